// round 7
// baseline (speedup 1.0000x reference)
#include <cuda_runtime.h>
#include <cuda_fp16.h>

#define HID 128
#define E_ 262144
#define N_ 32768
#define GEO_ 13
#define ROWS_MAX (E_ + 512)
#define GRID_G (ROWS_MAX / 128)

typedef unsigned long long u64;
typedef unsigned int u32;

// ---- dynamic smem layout ----
#define SA 136                     // padded row stride (elements); 272B rows, ldmatrix conflict-free
#define OFF_AHI 0                  // 128 x SA fp16 = 34816
#define OFF_ALO 34816
#define OFF_BHI 69632              // B_hi only
#define OFF_SSB 104448
#define OFF_SSC 104960
#define OFF_SSH 105472
#define SMEM_NEED 105984           // x2 CTAs -> occupancy 2

// ---------------- scratch (device globals; no allocation) ----------------
__device__ float g_hA[(size_t)ROWS_MAX * HID];
__device__ float g_hB[(size_t)ROWS_MAX * HID];
__device__ __half g_Wh[4 * 3 * 16384];    // layer weights fp16 [r*3+l][n][k]
__device__ __half g_W0h[4 * 3 * 16384];   // W0 k-chunks 0..2
__device__ __half g_W0gh[4 * 2048];       // W0 geo chunk [r][n][16]
__device__ int   g_perm[ROWS_MAX];
__device__ int   g_inv[E_];               // edge -> padded row
__device__ int   g_route[E_];
__device__ int   g_cnt[4];
__device__ int   g_cur[4];
__device__ int   g_bnd[5];
__device__ float g_cntf[4];
__device__ float g_stats[4][4][HID][2];
__device__ float g_st[4][4][HID][2];
// node bucketing
__device__ int   g_ncnt[N_];
__device__ int   g_ncur[N_];
__device__ int   g_noff[N_];
__device__ int   g_nbkt[E_];

// ---------------- helpers ----------------
__device__ __forceinline__ u32 smem_u32(const void* p){
  u32 a; asm("{ .reg .u64 t; cvta.to.shared.u64 t, %1; cvt.u32.u64 %0, t; }" : "=r"(a) : "l"(p));
  return a;
}
__device__ __forceinline__ void split_store4(char* bp, u32 offH, u32 offL, float4 v){
  __half2 h01 = __floats2half2_rn(v.x, v.y);
  __half2 h23 = __floats2half2_rn(v.z, v.w);
  float2 f01 = __half22float2(h01);
  float2 f23 = __half22float2(h23);
  __half2 l01 = __floats2half2_rn(v.x - f01.x, v.y - f01.y);
  __half2 l23 = __floats2half2_rn(v.z - f23.x, v.w - f23.y);
  *(uint2*)(bp + offH) = make_uint2(*(u32*)&h01, *(u32*)&h23);
  *(uint2*)(bp + offL) = make_uint2(*(u32*)&l01, *(u32*)&l23);
}
__device__ __forceinline__ void ldm4(u32& r0, u32& r1, u32& r2, u32& r3, u32 addr){
  asm volatile("ldmatrix.sync.aligned.m8n8.x4.shared.b16 {%0,%1,%2,%3}, [%4];"
               : "=r"(r0), "=r"(r1), "=r"(r2), "=r"(r3) : "r"(addr));
}
__device__ __forceinline__ void mma16816(float* d, const u32* a, u32 b0, u32 b1){
  asm volatile("mma.sync.aligned.m16n8k16.row.col.f32.f16.f16.f32 "
               "{%0,%1,%2,%3}, {%4,%5,%6,%7}, {%8,%9}, {%0,%1,%2,%3};"
               : "+f"(d[0]), "+f"(d[1]), "+f"(d[2]), "+f"(d[3])
               : "r"(a[0]), "r"(a[1]), "r"(a[2]), "r"(a[3]), "r"(b0), "r"(b1));
}

// ---------------- L1: setup (zero counters, perm=-1, route+counts) ----------------
__global__ void k_setup(const int* __restrict__ eij, const int* __restrict__ ejk,
                        const int* __restrict__ nei_ptr, const int* __restrict__ ei){
  int idx = blockIdx.x * 256 + threadIdx.x;
  if (idx < ROWS_MAX) g_perm[idx] = -1;
  if (idx < 4 * 4 * HID * 2) ((float*)g_stats)[idx] = 0.f;
  if (idx < 4) { g_cnt[idx] = 0; g_cur[idx] = 0; }
  if (idx < N_) { g_ncnt[idx] = 0; g_ncur[idx] = 0; }
  if (idx < E_){
    int nei = nei_ptr[0];
    int r = ((eij[idx] < nei) ? 0 : 2) | ((ejk[idx] < nei) ? 0 : 1);
    g_route[idx] = r;
    int lane = threadIdx.x & 31;
    #pragma unroll
    for (int rr = 0; rr < 4; rr++){
      unsigned m = __ballot_sync(0xFFFFFFFFu, r == rr);
      if (r == rr && lane == (__ffs(m) - 1)) atomicAdd(&g_cnt[rr], __popc(m));
    }
    atomicAdd(&g_ncnt[ei[idx]], 1);
  }
}

// ---------------- L2: route offsets + node prefix sum (1 block, 1024 thr) ----------
__global__ void k_offsets2(){
  __shared__ int part[1024];
  int t = threadIdx.x;
  if (t == 0){
    int b = 0;
    #pragma unroll
    for (int r = 0; r < 4; r++){
      g_bnd[r] = b;
      int c = g_cnt[r];
      b += ((c + 127) / 128) * 128;
      g_cntf[r] = (c > 0) ? (float)c : 1.0f;
    }
    g_bnd[4] = b;
  }
  int base = t * 32;
  int loc[32], s = 0;
  #pragma unroll
  for (int j = 0; j < 32; j++){ loc[j] = s; s += g_ncnt[base + j]; }
  part[t] = s;
  __syncthreads();
  for (int off = 1; off < 1024; off <<= 1){
    int v = (t >= off) ? part[t - off] : 0;
    __syncthreads();
    part[t] += v;
    __syncthreads();
  }
  int excl = part[t] - s;
  #pragma unroll
  for (int j = 0; j < 32; j++) g_noff[base + j] = excl + loc[j];
}

// ---------------- L3: permutation + node buckets + weight prep ----------------
__global__ void k_permprep(const int* __restrict__ ei,
                           const float* __restrict__ W0, const float* __restrict__ W){
  int bid = blockIdx.x, tid = threadIdx.x;
  if (bid < 1024){
    int e = bid * 256 + tid;
    int r = g_route[e];
    int lane = tid & 31;
    #pragma unroll
    for (int rr = 0; rr < 4; rr++){
      unsigned m = __ballot_sync(0xFFFFFFFFu, r == rr);
      if (r == rr){
        int leader = __ffs(m) - 1;
        int base = 0;
        if (lane == leader) base = atomicAdd(&g_cur[rr], __popc(m));
        base = __shfl_sync(m, base, leader);
        unsigned lt = (lane == 0) ? 0u : (0xFFFFFFFFu >> (32 - lane));
        int pos = g_bnd[rr] + base + __popc(m & lt);
        g_perm[pos] = e;
        g_inv[e] = pos;
      }
    }
    int i = ei[e];
    int slot = g_noff[i] + atomicAdd(&g_ncur[i], 1);
    g_nbkt[slot] = e;
  } else {
    int idx = (bid - 1024) * 256 + tid;
    const int NL = 4 * 3 * 16384;
    if (idx < NL){
      int rl = idx / 16384, rem = idx & 16383;
      int n = rem >> 7, k = rem & 127;
      g_Wh[idx] = __float2half_rn(W[((size_t)(rl * 128 + n)) * 128 + k]);
    } else if (idx < 2 * NL){
      int t2 = idx - NL;
      int rc = t2 / 16384, rem = t2 & 16383;
      int r = rc / 3, c = rc % 3;
      int n = rem >> 7, k = rem & 127;
      g_W0h[t2] = __float2half_rn(W0[((size_t)(r * 128 + n)) * 397 + c * 128 + k]);
    } else if (idx < 2 * NL + 4 * 2048){
      int t2 = idx - 2 * NL;
      int r = t2 / 2048, rem = t2 & 2047;
      int n = rem >> 4, k = rem & 15;
      int ko = 384 + k;
      float v = (ko < 397) ? W0[((size_t)(r * 128 + n)) * 397 + ko] : 0.f;
      g_W0gh[t2] = __float2half_rn(v);
    }
  }
}

// ---------------- HMMA mainloop: low register pressure (b-frags 4 live) ----------
__device__ __forceinline__ void mma_chunk(u32 sb, int mw, int nw, int lane, int nk,
                                          float acc[2][8][4]){
  for (int ks = 0; ks < nk; ks++){
    int k0 = ks * 16;
    u32 ah[2][4], al[2][4];
    #pragma unroll
    for (int im = 0; im < 2; im++){
      int row = mw + im * 16 + (lane & 15);
      int col = k0 + ((lane >> 4) << 3);
      u32 off = (u32)(row * SA + col) * 2;
      ldm4(ah[im][0], ah[im][1], ah[im][2], ah[im][3], sb + OFF_AHI + off);
      ldm4(al[im][0], al[im][1], al[im][2], al[im][3], sb + OFF_ALO + off);
    }
    int brow = nw + ((lane >> 4) << 3) + (lane & 7);
    int bcol = k0 + (((lane >> 3) & 1) << 3);
    #pragma unroll
    for (int g = 0; g < 4; g++){
      u32 b0, b1, b2, b3;
      ldm4(b0, b1, b2, b3, sb + OFF_BHI + (u32)((brow + g * 16) * SA + bcol) * 2);
      mma16816(acc[0][2*g],     ah[0], b0, b1);
      mma16816(acc[1][2*g],     ah[1], b0, b1);
      mma16816(acc[0][2*g],     al[0], b0, b1);
      mma16816(acc[1][2*g],     al[1], b0, b1);
      mma16816(acc[0][2*g + 1], ah[0], b2, b3);
      mma16816(acc[1][2*g + 1], ah[1], b2, b3);
      mma16816(acc[0][2*g + 1], al[0], b2, b3);
      mma16816(acc[1][2*g + 1], al[1], b2, b3);
    }
  }
}

// ---------------- epilogue: bias + store + fused BN stats ----------------
__device__ __forceinline__ void epilogue_mma(float acc[2][8][4], char* bp,
                                             float* __restrict__ hout,
                                             int m0, int mw, int nw, int lane,
                                             int r, int layer, int nval){
  int gid = lane >> 2, tig = lane & 3;
  const float* ssb = (const float*)(bp + OFF_SSB);
  float sum[8][2], sq[8][2];
  #pragma unroll
  for (int in = 0; in < 8; in++){ sum[in][0] = sum[in][1] = sq[in][0] = sq[in][1] = 0.f; }
  #pragma unroll
  for (int im = 0; im < 2; im++){
    int lr0 = mw + im * 16 + gid;
    bool v0 = lr0 < nval, v1 = (lr0 + 8) < nval;
    #pragma unroll
    for (int in = 0; in < 8; in++){
      float* d = acc[im][in];
      int col = nw + in * 8 + tig * 2;
      float b0 = ssb[col], b1 = ssb[col + 1];
      float e0 = d[0] + b0, e1 = d[1] + b1, e2 = d[2] + b0, e3 = d[3] + b1;
      *(float2*)&hout[(size_t)(m0 + lr0) * HID + col]     = make_float2(e0, e1);
      *(float2*)&hout[(size_t)(m0 + lr0 + 8) * HID + col] = make_float2(e2, e3);
      float m0v = v0 ? e0 : 0.f, m1v = v0 ? e1 : 0.f;
      float m2v = v1 ? e2 : 0.f, m3v = v1 ? e3 : 0.f;
      sum[in][0] += m0v + m2v; sum[in][1] += m1v + m3v;
      sq[in][0]  += m0v * m0v + m2v * m2v;
      sq[in][1]  += m1v * m1v + m3v * m3v;
    }
  }
  #pragma unroll
  for (int off = 4; off <= 16; off <<= 1){
    #pragma unroll
    for (int in = 0; in < 8; in++){
      sum[in][0] += __shfl_xor_sync(0xFFFFFFFFu, sum[in][0], off);
      sum[in][1] += __shfl_xor_sync(0xFFFFFFFFu, sum[in][1], off);
      sq[in][0]  += __shfl_xor_sync(0xFFFFFFFFu, sq[in][0], off);
      sq[in][1]  += __shfl_xor_sync(0xFFFFFFFFu, sq[in][1], off);
    }
  }
  if (gid == 0){
    #pragma unroll
    for (int in = 0; in < 8; in++){
      int col = nw + in * 8 + tig * 2;
      atomicAdd(&g_stats[layer][r][col][0], sum[in][0]);
      atomicAdd(&g_stats[layer][r][col][1], sq[in][0]);
      atomicAdd(&g_stats[layer][r][col + 1][0], sum[in][1]);
      atomicAdd(&g_stats[layer][r][col + 1][1], sq[in][1]);
    }
  }
}

// ---------------- L4 (PROFILED): GEMM layer 0 (gather, K = 3*128 + 16) ----------
__global__ __launch_bounds__(256, 2)
void k_gemm0(const float* __restrict__ nf, const float* __restrict__ geo,
             const int* __restrict__ ei, const float* __restrict__ b0){
  extern __shared__ char bp[];
  __shared__ int sE[128], sN0[128], sN1[128], sN2[128];
  u32 sb = smem_u32(bp);

  int m0 = blockIdx.x << 7;
  if (m0 >= g_bnd[4]) return;
  int r = 0;
  #pragma unroll
  for (int q = 1; q < 4; q++) if (m0 >= g_bnd[q]) r = q;

  int tid = threadIdx.x, wid = tid >> 5, lane = tid & 31;
  int mw = (wid & 3) * 32, nw = (wid >> 2) * 64;

  if (tid < 128){
    int e = g_perm[m0 + tid];
    sE[tid] = e;
    int a = 0, b_ = 0, c = 0;
    if (e >= 0){ a = ei[e]; b_ = ei[E_ + e]; c = ei[2 * E_ + e]; }
    sN0[tid] = a; sN1[tid] = b_; sN2[tid] = c;
    ((float*)(bp + OFF_SSB))[tid] = b0[r * HID + tid];
  }
  __syncthreads();

  float acc[2][8][4];
  #pragma unroll
  for (int im = 0; im < 2; im++)
    #pragma unroll
    for (int in = 0; in < 8; in++)
      #pragma unroll
      for (int t = 0; t < 4; t++) acc[im][in][t] = 0.f;

  for (int ch = 0; ch < 4; ch++){
    if (ch){ __syncthreads(); }
    if (ch < 3){
      const int* nodes = (ch == 0) ? sN0 : ((ch == 1) ? sN1 : sN2);
      #pragma unroll
      for (int j = 0; j < 16; j++){
        int f = j * 256 + tid;
        int row = f >> 5, c4 = (f & 31) << 2;
        float4 v = make_float4(0.f, 0.f, 0.f, 0.f);
        if (sE[row] >= 0) v = *(const float4*)&nf[(size_t)nodes[row] * HID + c4];
        u32 o = (u32)(row * SA + c4) * 2;
        split_store4(bp, OFF_AHI + o, OFF_ALO + o, v);
      }
      const float4* sh = (const float4*)(g_W0h + (r * 3 + ch) * 16384);
      for (int i = tid; i < 2048; i += 256){
        int row = i >> 4, seg = i & 15;
        *(float4*)(bp + OFF_BHI + (u32)(row * SA + seg * 8) * 2) = sh[i];
      }
    } else {
      #pragma unroll
      for (int j = 0; j < 2; j++){
        int f = j * 256 + tid;
        int row = f >> 2, c4 = (f & 3) << 2;
        int e = sE[row];
        float4 v;
        #pragma unroll
        for (int t = 0; t < 4; t++){
          int col = c4 + t;
          (&v.x)[t] = (e >= 0 && col < GEO_) ? geo[(size_t)e * GEO_ + col] : 0.f;
        }
        u32 o = (u32)(row * SA + c4) * 2;
        split_store4(bp, OFF_AHI + o, OFF_ALO + o, v);
      }
      {
        const float4* sh = (const float4*)(g_W0gh + r * 2048);
        int row = tid >> 1, seg = tid & 1;
        *(float4*)(bp + OFF_BHI + (u32)(row * SA + seg * 8) * 2) = sh[tid];
      }
    }
    __syncthreads();
    mma_chunk(sb, mw, nw, lane, (ch < 3) ? 8 : 1, acc);
  }

  int nv = g_bnd[r] + g_cnt[r] - m0;
  nv = (nv < 0) ? 0 : ((nv > 128) ? 128 : nv);
  epilogue_mma(acc, bp, g_hA, m0, mw, nw, lane, r, 0, nv);
}

// ---------------- GEMM layers 1..3 ----------------
template<int LI>
__global__ __launch_bounds__(256, 2)
void k_gemml(const float* __restrict__ bArr){
  const float* hin  = (LI & 1) ? g_hA : g_hB;
  float*       hout = (LI & 1) ? g_hB : g_hA;
  extern __shared__ char bp[];
  u32 sb = smem_u32(bp);

  int m0 = blockIdx.x << 7;
  if (m0 >= g_bnd[4]) return;
  int r = 0;
  #pragma unroll
  for (int q = 1; q < 4; q++) if (m0 >= g_bnd[q]) r = q;

  int tid = threadIdx.x, wid = tid >> 5, lane = tid & 31;
  int mw = (wid & 3) * 32, nw = (wid >> 2) * 64;

  if (tid < 128){
    ((float*)(bp + OFF_SSC))[tid] = g_st[LI - 1][r][tid][0];
    ((float*)(bp + OFF_SSH))[tid] = g_st[LI - 1][r][tid][1];
    ((float*)(bp + OFF_SSB))[tid] = bArr[(r * 3 + (LI - 1)) * HID + tid];
  }
  __syncthreads();

  const float* ssc = (const float*)(bp + OFF_SSC);
  const float* ssh = (const float*)(bp + OFF_SSH);
  #pragma unroll
  for (int j = 0; j < 16; j++){
    int f = j * 256 + tid;
    int row = f >> 5, c4 = (f & 31) << 2;
    float4 h = *(const float4*)&hin[(size_t)(m0 + row) * HID + c4];
    float4 sc = *(const float4*)&ssc[c4];
    float4 sh = *(const float4*)&ssh[c4];
    float4 a;
    a.x = fmaxf(fmaf(h.x, sc.x, sh.x), 0.f);
    a.y = fmaxf(fmaf(h.y, sc.y, sh.y), 0.f);
    a.z = fmaxf(fmaf(h.z, sc.z, sh.z), 0.f);
    a.w = fmaxf(fmaf(h.w, sc.w, sh.w), 0.f);
    u32 o = (u32)(row * SA + c4) * 2;
    split_store4(bp, OFF_AHI + o, OFF_ALO + o, a);
  }
  {
    const float4* shp = (const float4*)(g_Wh + (r * 3 + (LI - 1)) * 16384);
    for (int i = tid; i < 2048; i += 256){
      int row = i >> 4, seg = i & 15;
      *(float4*)(bp + OFF_BHI + (u32)(row * SA + seg * 8) * 2) = shp[i];
    }
  }
  __syncthreads();

  float acc[2][8][4];
  #pragma unroll
  for (int im = 0; im < 2; im++)
    #pragma unroll
    for (int in = 0; in < 8; in++)
      #pragma unroll
      for (int t = 0; t < 4; t++) acc[im][in][t] = 0.f;

  mma_chunk(sb, mw, nw, lane, 8, acc);

  int nv = g_bnd[r] + g_cnt[r] - m0;
  nv = (nv < 0) ? 0 : ((nv > 128) ? 128 : nv);
  epilogue_mma(acc, bp, hout, m0, mw, nw, lane, r, LI, nv);
}

// ---------------- BN finalize ----------------
__global__ void k_finalize(int layer, const float* __restrict__ gamma,
                           const float* __restrict__ beta){
  int t = threadIdx.x + blockIdx.x * blockDim.x;
  if (t >= 512) return;
  int r = t >> 7, c = t & 127;
  float cnt  = g_cntf[r];
  float mean = g_stats[layer][r][c][0] / cnt;
  float var  = fmaxf(g_stats[layer][r][c][1] / cnt - mean * mean, 0.f);
  float inv  = rsqrtf(var + 1e-5f);
  float s    = gamma[(r * 4 + layer) * HID + c] * inv;
  g_st[layer][r][c][0] = s;
  g_st[layer][r][c][1] = beta[(r * 4 + layer) * HID + c] - mean * s;
}

// ---------------- output: node-bucketed gather, no atomics ----------------
__global__ void k_out(const float* __restrict__ att, float* __restrict__ out){
  int n = blockIdx.x, col = threadIdx.x;
  int s = g_noff[n], cnt = g_ncnt[n];
  float acc = 0.f;
  for (int k = 0; k < cnt; k++){
    int e = g_nbkt[s + k];
    int row = g_inv[e];
    int r = g_route[e];
    float h = g_hB[(size_t)row * HID + col];
    float v = fmaxf(fmaf(h, g_st[3][r][col][0], g_st[3][r][col][1]), 0.f) * att[r];
    acc += v;
  }
  out[(size_t)n * HID + col] = acc;
}

// ---------------- launch ----------------
extern "C" void kernel_launch(void* const* d_in, const int* in_sizes, int n_in,
                              void* d_out, int out_size){
  const float* nf    = (const float*)d_in[0];
  const float* geo   = (const float*)d_in[1];
  const int*   ei    = (const int*)d_in[2];
  const int*   eij   = (const int*)d_in[3];
  const int*   ejk   = (const int*)d_in[4];
  const int*   nei   = (const int*)d_in[5];
  const float* att   = (const float*)d_in[6];
  const float* W0    = (const float*)d_in[7];
  const float* b0    = (const float*)d_in[8];
  const float* W     = (const float*)d_in[9];
  const float* b     = (const float*)d_in[10];
  const float* gamma = (const float*)d_in[11];
  const float* beta  = (const float*)d_in[12];
  float* out = (float*)d_out;

  cudaFuncSetAttribute(k_gemm0,    cudaFuncAttributeMaxDynamicSharedMemorySize, SMEM_NEED);
  cudaFuncSetAttribute(k_gemml<1>, cudaFuncAttributeMaxDynamicSharedMemorySize, SMEM_NEED);
  cudaFuncSetAttribute(k_gemml<2>, cudaFuncAttributeMaxDynamicSharedMemorySize, SMEM_NEED);
  cudaFuncSetAttribute(k_gemml<3>, cudaFuncAttributeMaxDynamicSharedMemorySize, SMEM_NEED);

  k_setup<<<ROWS_MAX / 256, 256>>>(eij, ejk, nei, ei);     // L1
  k_offsets2<<<1, 1024>>>();                               // L2
  k_permprep<<<1024 + 1568, 256>>>(ei, W0, W);             // L3
  k_gemm0<<<GRID_G, 256, SMEM_NEED>>>(nf, geo, ei, b0);    // L4 <- ncu window
  k_finalize<<<1, 512>>>(0, gamma, beta);
  k_gemml<1><<<GRID_G, 256, SMEM_NEED>>>(b);
  k_finalize<<<1, 512>>>(1, gamma, beta);
  k_gemml<2><<<GRID_G, 256, SMEM_NEED>>>(b);
  k_finalize<<<1, 512>>>(2, gamma, beta);
  k_gemml<3><<<GRID_G, 256, SMEM_NEED>>>(b);
  k_finalize<<<1, 512>>>(3, gamma, beta);
  k_out<<<N_, HID>>>(att, out);
}

// round 8
// speedup vs baseline: 1.0040x; 1.0040x over previous
#include <cuda_runtime.h>
#include <cuda_fp16.h>

#define HID 128
#define E_ 262144
#define N_ 32768
#define GEO_ 13
#define ROWS_MAX (E_ + 512)
#define GRID_G2 (ROWS_MAX / 64)

typedef unsigned long long u64;
typedef unsigned int u32;

// ---- dynamic smem layout (M-tile 64) ----
#define SA 136
#define OFF_AHI 0                  // 64 x SA fp16 = 17408
#define OFF_ALO 17408
#define OFF_BHI 34816              // 128 x SA fp16 = 34816
#define OFF_SSB 69632
#define OFF_SSC 70144
#define OFF_SSH 70656
#define SMEM_NEED 71168            // x3 CTAs = 213.5KB -> occupancy 3

// ---------------- scratch ----------------
__device__ float g_hA[(size_t)ROWS_MAX * HID];
__device__ float g_hB[(size_t)ROWS_MAX * HID];
__device__ __half g_Wh[4 * 3 * 16384];
__device__ __half g_W0h[4 * 3 * 16384];
__device__ __half g_W0gh[4 * 2048];
__device__ int   g_perm[ROWS_MAX];
__device__ int   g_inv[E_];
__device__ int   g_route[E_];
__device__ int   g_cnt[4];
__device__ int   g_cur[4];
__device__ int   g_bnd[5];
__device__ float g_cntf[4];
__device__ float g_stats[4][4][HID][2];
__device__ float g_st[4][4][HID][2];
__device__ int   g_ncnt[N_];
__device__ int   g_ncur[N_];
__device__ int   g_noff[N_];
__device__ int   g_nbkt[E_];

// ---------------- helpers ----------------
__device__ __forceinline__ u32 smem_u32(const void* p){
  u32 a; asm("{ .reg .u64 t; cvta.to.shared.u64 t, %1; cvt.u32.u64 %0, t; }" : "=r"(a) : "l"(p));
  return a;
}
#define CP_ASYNC16(dst, src) asm volatile("cp.async.ca.shared.global [%0], [%1], 16;" :: "r"(dst), "l"(src))
#define CP_COMMIT() asm volatile("cp.async.commit_group;" ::: "memory")
#define CP_WAIT0() asm volatile("cp.async.wait_group 0;" ::: "memory")

__device__ __forceinline__ void split_store4(char* bp, u32 offH, u32 offL, float4 v){
  __half2 h01 = __floats2half2_rn(v.x, v.y);
  __half2 h23 = __floats2half2_rn(v.z, v.w);
  float2 f01 = __half22float2(h01);
  float2 f23 = __half22float2(h23);
  __half2 l01 = __floats2half2_rn(v.x - f01.x, v.y - f01.y);
  __half2 l23 = __floats2half2_rn(v.z - f23.x, v.w - f23.y);
  *(uint2*)(bp + offH) = make_uint2(*(u32*)&h01, *(u32*)&h23);
  *(uint2*)(bp + offL) = make_uint2(*(u32*)&l01, *(u32*)&l23);
}
__device__ __forceinline__ void ldm4(u32& r0, u32& r1, u32& r2, u32& r3, u32 addr){
  asm volatile("ldmatrix.sync.aligned.m8n8.x4.shared.b16 {%0,%1,%2,%3}, [%4];"
               : "=r"(r0), "=r"(r1), "=r"(r2), "=r"(r3) : "r"(addr));
}
__device__ __forceinline__ void mma16816(float* d, const u32* a, u32 b0, u32 b1){
  asm volatile("mma.sync.aligned.m16n8k16.row.col.f32.f16.f16.f32 "
               "{%0,%1,%2,%3}, {%4,%5,%6,%7}, {%8,%9}, {%0,%1,%2,%3};"
               : "+f"(d[0]), "+f"(d[1]), "+f"(d[2]), "+f"(d[3])
               : "r"(a[0]), "r"(a[1]), "r"(a[2]), "r"(a[3]), "r"(b0), "r"(b1));
}

// ---------------- L1: setup ----------------
__global__ void k_setup(const int* __restrict__ eij, const int* __restrict__ ejk,
                        const int* __restrict__ nei_ptr, const int* __restrict__ ei){
  int idx = blockIdx.x * 256 + threadIdx.x;
  if (idx < ROWS_MAX) g_perm[idx] = -1;
  if (idx < 4 * 4 * HID * 2) ((float*)g_stats)[idx] = 0.f;
  if (idx < 4) { g_cnt[idx] = 0; g_cur[idx] = 0; }
  if (idx < N_) { g_ncnt[idx] = 0; g_ncur[idx] = 0; }
  if (idx < E_){
    int nei = nei_ptr[0];
    int r = ((eij[idx] < nei) ? 0 : 2) | ((ejk[idx] < nei) ? 0 : 1);
    g_route[idx] = r;
    int lane = threadIdx.x & 31;
    #pragma unroll
    for (int rr = 0; rr < 4; rr++){
      unsigned m = __ballot_sync(0xFFFFFFFFu, r == rr);
      if (r == rr && lane == (__ffs(m) - 1)) atomicAdd(&g_cnt[rr], __popc(m));
    }
    atomicAdd(&g_ncnt[ei[idx]], 1);
  }
}

// ---------------- L2: offsets + node prefix sum ----------------
__global__ void k_offsets2(){
  __shared__ int part[1024];
  int t = threadIdx.x;
  if (t == 0){
    int b = 0;
    #pragma unroll
    for (int r = 0; r < 4; r++){
      g_bnd[r] = b;
      int c = g_cnt[r];
      b += ((c + 127) / 128) * 128;
      g_cntf[r] = (c > 0) ? (float)c : 1.0f;
    }
    g_bnd[4] = b;
  }
  int base = t * 32;
  int loc[32], s = 0;
  #pragma unroll
  for (int j = 0; j < 32; j++){ loc[j] = s; s += g_ncnt[base + j]; }
  part[t] = s;
  __syncthreads();
  for (int off = 1; off < 1024; off <<= 1){
    int v = (t >= off) ? part[t - off] : 0;
    __syncthreads();
    part[t] += v;
    __syncthreads();
  }
  int excl = part[t] - s;
  #pragma unroll
  for (int j = 0; j < 32; j++) g_noff[base + j] = excl + loc[j];
}

// ---------------- L3: permutation + buckets + weight prep ----------------
__global__ void k_permprep(const int* __restrict__ ei,
                           const float* __restrict__ W0, const float* __restrict__ W){
  int bid = blockIdx.x, tid = threadIdx.x;
  if (bid < 1024){
    int e = bid * 256 + tid;
    int r = g_route[e];
    int lane = tid & 31;
    #pragma unroll
    for (int rr = 0; rr < 4; rr++){
      unsigned m = __ballot_sync(0xFFFFFFFFu, r == rr);
      if (r == rr){
        int leader = __ffs(m) - 1;
        int base = 0;
        if (lane == leader) base = atomicAdd(&g_cur[rr], __popc(m));
        base = __shfl_sync(m, base, leader);
        unsigned lt = (lane == 0) ? 0u : (0xFFFFFFFFu >> (32 - lane));
        int pos = g_bnd[rr] + base + __popc(m & lt);
        g_perm[pos] = e;
        g_inv[e] = pos;
      }
    }
    int i = ei[e];
    int slot = g_noff[i] + atomicAdd(&g_ncur[i], 1);
    g_nbkt[slot] = e;
  } else {
    int idx = (bid - 1024) * 256 + tid;
    const int NL = 4 * 3 * 16384;
    if (idx < NL){
      int rl = idx / 16384, rem = idx & 16383;
      int n = rem >> 7, k = rem & 127;
      g_Wh[idx] = __float2half_rn(W[((size_t)(rl * 128 + n)) * 128 + k]);
    } else if (idx < 2 * NL){
      int t2 = idx - NL;
      int rc = t2 / 16384, rem = t2 & 16383;
      int r = rc / 3, c = rc % 3;
      int n = rem >> 7, k = rem & 127;
      g_W0h[t2] = __float2half_rn(W0[((size_t)(r * 128 + n)) * 397 + c * 128 + k]);
    } else if (idx < 2 * NL + 4 * 2048){
      int t2 = idx - 2 * NL;
      int r = t2 / 2048, rem = t2 & 2047;
      int n = rem >> 4, k = rem & 15;
      int ko = 384 + k;
      float v = (ko < 397) ? W0[((size_t)(r * 128 + n)) * 397 + ko] : 0.f;
      g_W0gh[t2] = __float2half_rn(v);
    }
  }
}

// ---------------- HMMA mainloop (M=64 tile; warp 32Mx32N) ----------------
__device__ __forceinline__ void mma_chunk(u32 sb, int mw, int nw, int lane, int nk,
                                          float acc[2][4][4]){
  for (int ks = 0; ks < nk; ks++){
    int k0 = ks * 16;
    u32 ah[2][4], al[2][4];
    #pragma unroll
    for (int im = 0; im < 2; im++){
      int row = mw + im * 16 + (lane & 15);
      int col = k0 + ((lane >> 4) << 3);
      u32 off = (u32)(row * SA + col) * 2;
      ldm4(ah[im][0], ah[im][1], ah[im][2], ah[im][3], sb + OFF_AHI + off);
      ldm4(al[im][0], al[im][1], al[im][2], al[im][3], sb + OFF_ALO + off);
    }
    int brow = nw + ((lane >> 4) << 3) + (lane & 7);
    int bcol = k0 + (((lane >> 3) & 1) << 3);
    #pragma unroll
    for (int g = 0; g < 2; g++){
      u32 b0, b1, b2, b3;
      ldm4(b0, b1, b2, b3, sb + OFF_BHI + (u32)((brow + g * 16) * SA + bcol) * 2);
      mma16816(acc[0][2*g],     ah[0], b0, b1);
      mma16816(acc[1][2*g],     ah[1], b0, b1);
      mma16816(acc[0][2*g],     al[0], b0, b1);
      mma16816(acc[1][2*g],     al[1], b0, b1);
      mma16816(acc[0][2*g + 1], ah[0], b2, b3);
      mma16816(acc[1][2*g + 1], ah[1], b2, b3);
      mma16816(acc[0][2*g + 1], al[0], b2, b3);
      mma16816(acc[1][2*g + 1], al[1], b2, b3);
    }
  }
}

// ---------------- epilogue ----------------
__device__ __forceinline__ void epilogue_mma(float acc[2][4][4], char* bp,
                                             float* __restrict__ hout,
                                             int m0, int mw, int nw, int lane,
                                             int r, int layer, int nval){
  int gid = lane >> 2, tig = lane & 3;
  const float* ssb = (const float*)(bp + OFF_SSB);
  float sum[4][2], sq[4][2];
  #pragma unroll
  for (int in = 0; in < 4; in++){ sum[in][0] = sum[in][1] = sq[in][0] = sq[in][1] = 0.f; }
  #pragma unroll
  for (int im = 0; im < 2; im++){
    int lr0 = mw + im * 16 + gid;
    bool v0 = lr0 < nval, v1 = (lr0 + 8) < nval;
    #pragma unroll
    for (int in = 0; in < 4; in++){
      float* d = acc[im][in];
      int col = nw + in * 8 + tig * 2;
      float b0 = ssb[col], b1 = ssb[col + 1];
      float e0 = d[0] + b0, e1 = d[1] + b1, e2 = d[2] + b0, e3 = d[3] + b1;
      *(float2*)&hout[(size_t)(m0 + lr0) * HID + col]     = make_float2(e0, e1);
      *(float2*)&hout[(size_t)(m0 + lr0 + 8) * HID + col] = make_float2(e2, e3);
      float m0v = v0 ? e0 : 0.f, m1v = v0 ? e1 : 0.f;
      float m2v = v1 ? e2 : 0.f, m3v = v1 ? e3 : 0.f;
      sum[in][0] += m0v + m2v; sum[in][1] += m1v + m3v;
      sq[in][0]  += m0v * m0v + m2v * m2v;
      sq[in][1]  += m1v * m1v + m3v * m3v;
    }
  }
  #pragma unroll
  for (int off = 4; off <= 16; off <<= 1){
    #pragma unroll
    for (int in = 0; in < 4; in++){
      sum[in][0] += __shfl_xor_sync(0xFFFFFFFFu, sum[in][0], off);
      sum[in][1] += __shfl_xor_sync(0xFFFFFFFFu, sum[in][1], off);
      sq[in][0]  += __shfl_xor_sync(0xFFFFFFFFu, sq[in][0], off);
      sq[in][1]  += __shfl_xor_sync(0xFFFFFFFFu, sq[in][1], off);
    }
  }
  if (gid == 0){
    #pragma unroll
    for (int in = 0; in < 4; in++){
      int col = nw + in * 8 + tig * 2;
      atomicAdd(&g_stats[layer][r][col][0], sum[in][0]);
      atomicAdd(&g_stats[layer][r][col][1], sq[in][0]);
      atomicAdd(&g_stats[layer][r][col + 1][0], sum[in][1]);
      atomicAdd(&g_stats[layer][r][col + 1][1], sq[in][1]);
    }
  }
}

// ---------------- L4 (PROFILED): GEMM layer 0 ----------------
__global__ __launch_bounds__(256, 3)
void k_gemm0(const float* __restrict__ nf, const float* __restrict__ geo,
             const int* __restrict__ ei, const float* __restrict__ b0){
  extern __shared__ char bp[];
  __shared__ int sE[64], sN0[64], sN1[64], sN2[64];
  u32 sb = smem_u32(bp);

  int m0 = blockIdx.x << 6;
  if (m0 >= g_bnd[4]) return;
  int r = 0;
  #pragma unroll
  for (int q = 1; q < 4; q++) if (m0 >= g_bnd[q]) r = q;

  int tid = threadIdx.x, wid = tid >> 5, lane = tid & 31;
  int mw = (wid & 1) * 32, nw = (wid >> 1) * 32;

  if (tid < 64){
    int e = g_perm[m0 + tid];
    sE[tid] = e;
    int a = 0, b_ = 0, c = 0;
    if (e >= 0){ a = ei[e]; b_ = ei[E_ + e]; c = ei[2 * E_ + e]; }
    sN0[tid] = a; sN1[tid] = b_; sN2[tid] = c;
  }
  if (tid < 128) ((float*)(bp + OFF_SSB))[tid] = b0[r * HID + tid];
  __syncthreads();

  float acc[2][4][4];
  #pragma unroll
  for (int im = 0; im < 2; im++)
    #pragma unroll
    for (int in = 0; in < 4; in++)
      #pragma unroll
      for (int t = 0; t < 4; t++) acc[im][in][t] = 0.f;

  for (int ch = 0; ch < 4; ch++){
    if (ch){ __syncthreads(); }
    if (ch < 3){
      // B via cp.async (overlaps A gather below)
      const __half* wsrc = g_W0h + (r * 3 + ch) * 16384;
      #pragma unroll
      for (int j = 0; j < 8; j++){
        int i = j * 256 + tid;
        int row = i >> 4, seg = i & 15;
        CP_ASYNC16(sb + OFF_BHI + (u32)(row * SA + seg * 8) * 2, wsrc + row * 128 + seg * 8);
      }
      const int* nodes = (ch == 0) ? sN0 : ((ch == 1) ? sN1 : sN2);
      #pragma unroll
      for (int j = 0; j < 8; j++){
        int f = j * 256 + tid;
        int row = f >> 5, c4 = (f & 31) << 2;
        float4 v = make_float4(0.f, 0.f, 0.f, 0.f);
        if (sE[row] >= 0) v = *(const float4*)&nf[(size_t)nodes[row] * HID + c4];
        u32 o = (u32)(row * SA + c4) * 2;
        split_store4(bp, OFF_AHI + o, OFF_ALO + o, v);
      }
    } else {
      const __half* wsrc = g_W0gh + r * 2048;
      {
        int row = tid >> 1, seg = tid & 1;
        CP_ASYNC16(sb + OFF_BHI + (u32)(row * SA + seg * 8) * 2, wsrc + row * 16 + seg * 8);
      }
      {
        int row = tid >> 2, c4 = (tid & 3) << 2;
        int e = sE[row];
        float4 v;
        #pragma unroll
        for (int t = 0; t < 4; t++){
          int col = c4 + t;
          (&v.x)[t] = (e >= 0 && col < GEO_) ? geo[(size_t)e * GEO_ + col] : 0.f;
        }
        u32 o = (u32)(row * SA + c4) * 2;
        split_store4(bp, OFF_AHI + o, OFF_ALO + o, v);
      }
    }
    CP_COMMIT();
    CP_WAIT0();
    __syncthreads();
    mma_chunk(sb, mw, nw, lane, (ch < 3) ? 8 : 1, acc);
  }

  int nv = g_bnd[r] + g_cnt[r] - m0;
  nv = (nv < 0) ? 0 : ((nv > 64) ? 64 : nv);
  epilogue_mma(acc, bp, g_hA, m0, mw, nw, lane, r, 0, nv);
}

// ---------------- GEMM layers 1..3 ----------------
template<int LI>
__global__ __launch_bounds__(256, 3)
void k_gemml(const float* __restrict__ bArr){
  const float* hin  = (LI & 1) ? g_hA : g_hB;
  float*       hout = (LI & 1) ? g_hB : g_hA;
  extern __shared__ char bp[];
  u32 sb = smem_u32(bp);

  int m0 = blockIdx.x << 6;
  if (m0 >= g_bnd[4]) return;
  int r = 0;
  #pragma unroll
  for (int q = 1; q < 4; q++) if (m0 >= g_bnd[q]) r = q;

  int tid = threadIdx.x, wid = tid >> 5, lane = tid & 31;
  int mw = (wid & 1) * 32, nw = (wid >> 1) * 32;

  // B via cp.async first (overlaps everything below)
  {
    const __half* wsrc = g_Wh + (r * 3 + (LI - 1)) * 16384;
    #pragma unroll
    for (int j = 0; j < 8; j++){
      int i = j * 256 + tid;
      int row = i >> 4, seg = i & 15;
      CP_ASYNC16(sb + OFF_BHI + (u32)(row * SA + seg * 8) * 2, wsrc + row * 128 + seg * 8);
    }
    CP_COMMIT();
  }
  if (tid < 128){
    ((float*)(bp + OFF_SSC))[tid] = g_st[LI - 1][r][tid][0];
    ((float*)(bp + OFF_SSH))[tid] = g_st[LI - 1][r][tid][1];
    ((float*)(bp + OFF_SSB))[tid] = bArr[(r * 3 + (LI - 1)) * HID + tid];
  }
  __syncthreads();

  const float* ssc = (const float*)(bp + OFF_SSC);
  const float* ssh = (const float*)(bp + OFF_SSH);
  #pragma unroll
  for (int j = 0; j < 8; j++){
    int f = j * 256 + tid;
    int row = f >> 5, c4 = (f & 31) << 2;
    float4 h = *(const float4*)&hin[(size_t)(m0 + row) * HID + c4];
    float4 sc = *(const float4*)&ssc[c4];
    float4 sh = *(const float4*)&ssh[c4];
    float4 a;
    a.x = fmaxf(fmaf(h.x, sc.x, sh.x), 0.f);
    a.y = fmaxf(fmaf(h.y, sc.y, sh.y), 0.f);
    a.z = fmaxf(fmaf(h.z, sc.z, sh.z), 0.f);
    a.w = fmaxf(fmaf(h.w, sc.w, sh.w), 0.f);
    u32 o = (u32)(row * SA + c4) * 2;
    split_store4(bp, OFF_AHI + o, OFF_ALO + o, a);
  }
  CP_WAIT0();
  __syncthreads();

  float acc[2][4][4];
  #pragma unroll
  for (int im = 0; im < 2; im++)
    #pragma unroll
    for (int in = 0; in < 4; in++)
      #pragma unroll
      for (int t = 0; t < 4; t++) acc[im][in][t] = 0.f;

  mma_chunk(sb, mw, nw, lane, 8, acc);

  int nv = g_bnd[r] + g_cnt[r] - m0;
  nv = (nv < 0) ? 0 : ((nv > 64) ? 64 : nv);
  epilogue_mma(acc, bp, hout, m0, mw, nw, lane, r, LI, nv);
}

// ---------------- BN finalize ----------------
__global__ void k_finalize(int layer, const float* __restrict__ gamma,
                           const float* __restrict__ beta){
  int t = threadIdx.x + blockIdx.x * blockDim.x;
  if (t >= 512) return;
  int r = t >> 7, c = t & 127;
  float cnt  = g_cntf[r];
  float mean = g_stats[layer][r][c][0] / cnt;
  float var  = fmaxf(g_stats[layer][r][c][1] / cnt - mean * mean, 0.f);
  float inv  = rsqrtf(var + 1e-5f);
  float s    = gamma[(r * 4 + layer) * HID + c] * inv;
  g_st[layer][r][c][0] = s;
  g_st[layer][r][c][1] = beta[(r * 4 + layer) * HID + c] - mean * s;
}

// ---------------- output: node-bucketed gather ----------------
__global__ void k_out(const float* __restrict__ att, float* __restrict__ out){
  int n = blockIdx.x, col = threadIdx.x;
  int s = g_noff[n], cnt = g_ncnt[n];
  float acc = 0.f;
  for (int k = 0; k < cnt; k++){
    int e = g_nbkt[s + k];
    int row = g_inv[e];
    int r = g_route[e];
    float h = g_hB[(size_t)row * HID + col];
    float v = fmaxf(fmaf(h, g_st[3][r][col][0], g_st[3][r][col][1]), 0.f) * att[r];
    acc += v;
  }
  out[(size_t)n * HID + col] = acc;
}

// ---------------- launch ----------------
extern "C" void kernel_launch(void* const* d_in, const int* in_sizes, int n_in,
                              void* d_out, int out_size){
  const float* nf    = (const float*)d_in[0];
  const float* geo   = (const float*)d_in[1];
  const int*   ei    = (const int*)d_in[2];
  const int*   eij   = (const int*)d_in[3];
  const int*   ejk   = (const int*)d_in[4];
  const int*   nei   = (const int*)d_in[5];
  const float* att   = (const float*)d_in[6];
  const float* W0    = (const float*)d_in[7];
  const float* b0    = (const float*)d_in[8];
  const float* W     = (const float*)d_in[9];
  const float* b     = (const float*)d_in[10];
  const float* gamma = (const float*)d_in[11];
  const float* beta  = (const float*)d_in[12];
  float* out = (float*)d_out;

  cudaFuncSetAttribute(k_gemm0,    cudaFuncAttributeMaxDynamicSharedMemorySize, SMEM_NEED);
  cudaFuncSetAttribute(k_gemml<1>, cudaFuncAttributeMaxDynamicSharedMemorySize, SMEM_NEED);
  cudaFuncSetAttribute(k_gemml<2>, cudaFuncAttributeMaxDynamicSharedMemorySize, SMEM_NEED);
  cudaFuncSetAttribute(k_gemml<3>, cudaFuncAttributeMaxDynamicSharedMemorySize, SMEM_NEED);

  k_setup<<<ROWS_MAX / 256, 256>>>(eij, ejk, nei, ei);     // L1
  k_offsets2<<<1, 1024>>>();                               // L2
  k_permprep<<<1024 + 1568, 256>>>(ei, W0, W);             // L3
  k_gemm0<<<GRID_G2, 256, SMEM_NEED>>>(nf, geo, ei, b0);   // L4 <- ncu window
  k_finalize<<<1, 512>>>(0, gamma, beta);
  k_gemml<1><<<GRID_G2, 256, SMEM_NEED>>>(b);
  k_finalize<<<1, 512>>>(1, gamma, beta);
  k_gemml<2><<<GRID_G2, 256, SMEM_NEED>>>(b);
  k_finalize<<<1, 512>>>(2, gamma, beta);
  k_gemml<3><<<GRID_G2, 256, SMEM_NEED>>>(b);
  k_finalize<<<1, 512>>>(3, gamma, beta);
  k_out<<<N_, HID>>>(att, out);
}

// round 10
// speedup vs baseline: 1.0235x; 1.0194x over previous
#include <cuda_runtime.h>
#include <cuda_fp16.h>

#define HID 128
#define E_ 262144
#define N_ 32768
#define GEO_ 13
#define ROWS_MAX (E_ + 512)
#define GRID_G2 (ROWS_MAX / 64)
#define SETUP_BLKS 1026
#define WPREP_BLKS 1568
#define SETUP_GRID (SETUP_BLKS + WPREP_BLKS)

typedef unsigned long long u64;
typedef unsigned int u32;

// ---- dynamic smem layout (M-tile 64, single fp16) ----
#define SA 136
#define OFF_A 0                    // 64 x SA fp16 = 17408
#define OFF_B 17408                // 128 x SA fp16 = 34816
#define OFF_SSB 52224
#define OFF_SSC 52736
#define OFF_SSH 53248
#define SMEM_NEED 53760            // x3 CTAs -> occupancy 3

// ---------------- scratch ----------------
__device__ float g_hA[(size_t)ROWS_MAX * HID];
__device__ float g_hB[(size_t)ROWS_MAX * HID];
__device__ __half g_Wh[4 * 3 * 16384];
__device__ __half g_W0h[4 * 3 * 16384];
__device__ __half g_W0gh[4 * 2048];
__device__ int   g_perm[ROWS_MAX];
__device__ int   g_inv[E_];
__device__ int   g_route[E_];
__device__ int   g_cnt[4];
__device__ int   g_cur[4];
__device__ int   g_bnd[5];
__device__ float g_cntf[4];
__device__ float g_stats[4][4][HID][2];
__device__ float g_st[4][4][HID][2];
__device__ int   g_ncnt[N_];
__device__ int   g_ncur[N_];
__device__ int   g_noff[N_];
__device__ int   g_nbkt[E_];

// ---------------- helpers ----------------
__device__ __forceinline__ u32 smem_u32(const void* p){
  u32 a; asm("{ .reg .u64 t; cvta.to.shared.u64 t, %1; cvt.u32.u64 %0, t; }" : "=r"(a) : "l"(p));
  return a;
}
#define CP_ASYNC16(dst, src) asm volatile("cp.async.ca.shared.global [%0], [%1], 16;" :: "r"(dst), "l"(src))
#define CP_COMMIT() asm volatile("cp.async.commit_group;" ::: "memory")
#define CP_WAIT0() asm volatile("cp.async.wait_group 0;" ::: "memory")

__device__ __forceinline__ void store_a4(char* bp, u32 off, float4 v){
  __half2 h01 = __floats2half2_rn(v.x, v.y);
  __half2 h23 = __floats2half2_rn(v.z, v.w);
  *(uint2*)(bp + off) = make_uint2(*(u32*)&h01, *(u32*)&h23);
}
__device__ __forceinline__ void ldm4(u32& r0, u32& r1, u32& r2, u32& r3, u32 addr){
  asm volatile("ldmatrix.sync.aligned.m8n8.x4.shared.b16 {%0,%1,%2,%3}, [%4];"
               : "=r"(r0), "=r"(r1), "=r"(r2), "=r"(r3) : "r"(addr));
}
__device__ __forceinline__ void mma16816(float* d, const u32* a, u32 b0, u32 b1){
  asm volatile("mma.sync.aligned.m16n8k16.row.col.f32.f16.f16.f32 "
               "{%0,%1,%2,%3}, {%4,%5,%6,%7}, {%8,%9}, {%0,%1,%2,%3};"
               : "+f"(d[0]), "+f"(d[1]), "+f"(d[2]), "+f"(d[3])
               : "r"(a[0]), "r"(a[1]), "r"(a[2]), "r"(a[3]), "r"(b0), "r"(b1));
}

// ---------------- L1: setup + weight prep ----------------
__global__ void k_setup(const int* __restrict__ eij, const int* __restrict__ ejk,
                        const int* __restrict__ nei_ptr, const int* __restrict__ ei,
                        const float* __restrict__ W0, const float* __restrict__ W){
  int bid = blockIdx.x, tid = threadIdx.x;
  if (bid < SETUP_BLKS){
    int idx = bid * 256 + tid;
    if (idx < ROWS_MAX) g_perm[idx] = -1;
    if (idx < 4096) ((float*)g_stats)[idx] = 0.f;
    if (idx < 4){ g_cnt[idx] = 0; g_cur[idx] = 0; }
    if (idx < N_){ g_ncnt[idx] = 0; g_ncur[idx] = 0; }
    if (idx < E_){
      int nei = nei_ptr[0];
      int r = ((eij[idx] < nei) ? 0 : 2) | ((ejk[idx] < nei) ? 0 : 1);
      g_route[idx] = r;
      int lane = tid & 31;
      #pragma unroll
      for (int rr = 0; rr < 4; rr++){
        unsigned m = __ballot_sync(0xFFFFFFFFu, r == rr);
        if (r == rr && lane == (__ffs(m) - 1)) atomicAdd(&g_cnt[rr], __popc(m));
      }
      atomicAdd(&g_ncnt[ei[idx]], 1);
    }
  } else {
    int idx = (bid - SETUP_BLKS) * 256 + tid;
    const int NL = 4 * 3 * 16384;
    if (idx < NL){
      int rl = idx / 16384, rem = idx & 16383;
      int n = rem >> 7, k = rem & 127;
      g_Wh[idx] = __float2half_rn(W[((size_t)(rl * 128 + n)) * 128 + k]);
    } else if (idx < 2 * NL){
      int t2 = idx - NL;
      int rc = t2 / 16384, rem = t2 & 16383;
      int r = rc / 3, c = rc % 3;
      int n = rem >> 7, k = rem & 127;
      g_W0h[t2] = __float2half_rn(W0[((size_t)(r * 128 + n)) * 397 + c * 128 + k]);
    } else {
      int t2 = idx - 2 * NL;
      int r = t2 / 2048, rem = t2 & 2047;
      int n = rem >> 4, k = rem & 15;
      int ko = 384 + k;
      float v = (ko < 397) ? W0[((size_t)(r * 128 + n)) * 397 + ko] : 0.f;
      g_W0gh[t2] = __float2half_rn(v);
    }
  }
}

// ---------------- L2: route offsets + node prefix sum ----------------
__global__ void k_offsets2(){
  __shared__ int part[1024];
  int t = threadIdx.x;
  if (t == 0){
    int b = 0;
    #pragma unroll
    for (int r = 0; r < 4; r++){
      g_bnd[r] = b;
      int c = g_cnt[r];
      b += ((c + 127) / 128) * 128;
      g_cntf[r] = (c > 0) ? (float)c : 1.0f;
    }
    g_bnd[4] = b;
  }
  int base = t * 32;
  int loc[32], s = 0;
  #pragma unroll
  for (int j = 0; j < 32; j++){ loc[j] = s; s += g_ncnt[base + j]; }
  part[t] = s;
  __syncthreads();
  for (int off = 1; off < 1024; off <<= 1){
    int v = (t >= off) ? part[t - off] : 0;
    __syncthreads();
    part[t] += v;
    __syncthreads();
  }
  int excl = part[t] - s;
  #pragma unroll
  for (int j = 0; j < 32; j++) g_noff[base + j] = excl + loc[j];
}

// ---------------- L3: permutation + node buckets ----------------
__global__ void k_permprep(const int* __restrict__ ei){
  int e = blockIdx.x * 256 + threadIdx.x;
  int r = g_route[e];
  int lane = threadIdx.x & 31;
  #pragma unroll
  for (int rr = 0; rr < 4; rr++){
    unsigned m = __ballot_sync(0xFFFFFFFFu, r == rr);
    if (r == rr){
      int leader = __ffs(m) - 1;
      int base = 0;
      if (lane == leader) base = atomicAdd(&g_cur[rr], __popc(m));
      base = __shfl_sync(m, base, leader);
      unsigned lt = (lane == 0) ? 0u : (0xFFFFFFFFu >> (32 - lane));
      int pos = g_bnd[rr] + base + __popc(m & lt);
      g_perm[pos] = e;
      g_inv[e] = pos;
    }
  }
  int i = ei[e];
  int slot = g_noff[i] + atomicAdd(&g_ncur[i], 1);
  g_nbkt[slot] = e;
}

// ---------------- fragment loads ----------------
__device__ __forceinline__ void loadA(u32 sb, int mw, int lane, int k0, u32 a[2][4]){
  #pragma unroll
  for (int im = 0; im < 2; im++){
    int row = mw + im * 16 + (lane & 15);
    int col = k0 + ((lane >> 4) << 3);
    ldm4(a[im][0], a[im][1], a[im][2], a[im][3], sb + OFF_A + (u32)(row * SA + col) * 2);
  }
}
__device__ __forceinline__ void loadB(u32 sb, int nw, int lane, int k0, u32 b[4][2]){
  int brow = nw + ((lane >> 4) << 3) + (lane & 7);
  int bcol = k0 + (((lane >> 3) & 1) << 3);
  #pragma unroll
  for (int g = 0; g < 2; g++){
    ldm4(b[2*g][0], b[2*g][1], b[2*g+1][0], b[2*g+1][1],
         sb + OFF_B + (u32)((brow + g * 16) * SA + bcol) * 2);
  }
}

// ---------------- pipelined mainloop (A double-buffered) ----------------
template<int NK>
__device__ __forceinline__ void mma_chunk(u32 sb, int mw, int nw, int lane, float acc[2][4][4]){
  u32 a[2][2][4];
  loadA(sb, mw, lane, 0, a[0]);
  #pragma unroll
  for (int ks = 0; ks < NK; ks++){
    int cur = ks & 1;
    u32 b[4][2];
    loadB(sb, nw, lane, ks * 16, b);
    if (ks + 1 < NK) loadA(sb, mw, lane, (ks + 1) * 16, a[cur ^ 1]);
    #pragma unroll
    for (int im = 0; im < 2; im++)
      #pragma unroll
      for (int in = 0; in < 4; in++)
        mma16816(acc[im][in], a[cur][im], b[in][0], b[in][1]);
  }
}

// ---------------- epilogue: bias + store + fused BN stats ----------------
__device__ __forceinline__ void epilogue_mma(float acc[2][4][4], char* bp,
                                             float* __restrict__ hout,
                                             int m0, int mw, int nw, int lane,
                                             int r, int layer, int nval){
  int gid = lane >> 2, tig = lane & 3;
  const float* ssb = (const float*)(bp + OFF_SSB);
  float sum[4][2], sq[4][2];
  #pragma unroll
  for (int in = 0; in < 4; in++){ sum[in][0] = sum[in][1] = sq[in][0] = sq[in][1] = 0.f; }
  #pragma unroll
  for (int im = 0; im < 2; im++){
    int lr0 = mw + im * 16 + gid;
    bool v0 = lr0 < nval, v1 = (lr0 + 8) < nval;
    #pragma unroll
    for (int in = 0; in < 4; in++){
      float* d = acc[im][in];
      int col = nw + in * 8 + tig * 2;
      float b0 = ssb[col], b1 = ssb[col + 1];
      float e0 = d[0] + b0, e1 = d[1] + b1, e2 = d[2] + b0, e3 = d[3] + b1;
      *(float2*)&hout[(size_t)(m0 + lr0) * HID + col]     = make_float2(e0, e1);
      *(float2*)&hout[(size_t)(m0 + lr0 + 8) * HID + col] = make_float2(e2, e3);
      float m0v = v0 ? e0 : 0.f, m1v = v0 ? e1 : 0.f;
      float m2v = v1 ? e2 : 0.f, m3v = v1 ? e3 : 0.f;
      sum[in][0] += m0v + m2v; sum[in][1] += m1v + m3v;
      sq[in][0]  += m0v * m0v + m2v * m2v;
      sq[in][1]  += m1v * m1v + m3v * m3v;
    }
  }
  #pragma unroll
  for (int off = 4; off <= 16; off <<= 1){
    #pragma unroll
    for (int in = 0; in < 4; in++){
      sum[in][0] += __shfl_xor_sync(0xFFFFFFFFu, sum[in][0], off);
      sum[in][1] += __shfl_xor_sync(0xFFFFFFFFu, sum[in][1], off);
      sq[in][0]  += __shfl_xor_sync(0xFFFFFFFFu, sq[in][0], off);
      sq[in][1]  += __shfl_xor_sync(0xFFFFFFFFu, sq[in][1], off);
    }
  }
  if (gid == 0){
    #pragma unroll
    for (int in = 0; in < 4; in++){
      int col = nw + in * 8 + tig * 2;
      atomicAdd(&g_stats[layer][r][col][0], sum[in][0]);
      atomicAdd(&g_stats[layer][r][col][1], sq[in][0]);
      atomicAdd(&g_stats[layer][r][col + 1][0], sum[in][1]);
      atomicAdd(&g_stats[layer][r][col + 1][1], sq[in][1]);
    }
  }
}

// ---------------- L4: GEMM layer 0 (gather, K = 3*128 + 16) ----------------
__global__ __launch_bounds__(256, 3)
void k_gemm0(const float* __restrict__ nf, const float* __restrict__ geo,
             const int* __restrict__ ei, const float* __restrict__ b0){
  extern __shared__ char bp[];
  __shared__ int sE[64], sN0[64], sN1[64], sN2[64];
  u32 sb = smem_u32(bp);
  int m0 = blockIdx.x << 6;
  if (m0 >= g_bnd[4]) return;
  int r = 0;
  #pragma unroll
  for (int q = 1; q < 4; q++) if (m0 >= g_bnd[q]) r = q;
  int tid = threadIdx.x, wid = tid >> 5, lane = tid & 31;
  int mw = (wid & 1) * 32, nw = (wid >> 1) * 32;

  if (tid < 64){
    int e = g_perm[m0 + tid];
    sE[tid] = e;
    int a = 0, b_ = 0, c = 0;
    if (e >= 0){ a = ei[e]; b_ = ei[E_ + e]; c = ei[2 * E_ + e]; }
    sN0[tid] = a; sN1[tid] = b_; sN2[tid] = c;
  }
  if (tid < 128) ((float*)(bp + OFF_SSB))[tid] = b0[r * HID + tid];
  __syncthreads();

  float acc[2][4][4];
  #pragma unroll
  for (int im = 0; im < 2; im++)
    #pragma unroll
    for (int in = 0; in < 4; in++)
      #pragma unroll
      for (int t = 0; t < 4; t++) acc[im][in][t] = 0.f;

  for (int ch = 0; ch < 4; ch++){
    if (ch){ __syncthreads(); }
    if (ch < 3){
      const __half* wsrc = g_W0h + (r * 3 + ch) * 16384;
      #pragma unroll
      for (int j = 0; j < 8; j++){
        int i = j * 256 + tid;
        int row = i >> 4, seg = i & 15;
        CP_ASYNC16(sb + OFF_B + (u32)(row * SA + seg * 8) * 2, wsrc + row * 128 + seg * 8);
      }
      const int* nodes = (ch == 0) ? sN0 : ((ch == 1) ? sN1 : sN2);
      #pragma unroll
      for (int j = 0; j < 8; j++){
        int f = j * 256 + tid;
        int row = f >> 5, c4 = (f & 31) << 2;
        float4 v = make_float4(0.f, 0.f, 0.f, 0.f);
        if (sE[row] >= 0) v = *(const float4*)&nf[(size_t)nodes[row] * HID + c4];
        store_a4(bp, OFF_A + (u32)(row * SA + c4) * 2, v);
      }
    } else {
      const __half* wsrc = g_W0gh + r * 2048;
      {
        int row = tid >> 1, seg = tid & 1;
        CP_ASYNC16(sb + OFF_B + (u32)(row * SA + seg * 8) * 2, wsrc + row * 16 + seg * 8);
      }
      {
        int row = tid >> 2, c4 = (tid & 3) << 2;
        int e = sE[row];
        float4 v;
        #pragma unroll
        for (int t = 0; t < 4; t++){
          int col = c4 + t;
          (&v.x)[t] = (e >= 0 && col < GEO_) ? geo[(size_t)e * GEO_ + col] : 0.f;
        }
        store_a4(bp, OFF_A + (u32)(row * SA + c4) * 2, v);
      }
    }
    CP_COMMIT();
    CP_WAIT0();
    __syncthreads();
    if (ch < 3) mma_chunk<8>(sb, mw, nw, lane, acc);
    else        mma_chunk<1>(sb, mw, nw, lane, acc);
  }

  int nv = g_bnd[r] + g_cnt[r] - m0;
  nv = (nv < 0) ? 0 : ((nv > 64) ? 64 : nv);
  epilogue_mma(acc, bp, g_hA, m0, mw, nw, lane, r, 0, nv);
}

// ---------------- GEMM layers 1..3 ----------------
template<int LI>
__global__ __launch_bounds__(256, 3)
void k_gemml(const float* __restrict__ bArr){
  const float* hin  = (LI & 1) ? g_hA : g_hB;
  float*       hout = (LI & 1) ? g_hB : g_hA;
  extern __shared__ char bp[];
  u32 sb = smem_u32(bp);
  int m0 = blockIdx.x << 6;
  if (m0 >= g_bnd[4]) return;
  int r = 0;
  #pragma unroll
  for (int q = 1; q < 4; q++) if (m0 >= g_bnd[q]) r = q;
  int tid = threadIdx.x, wid = tid >> 5, lane = tid & 31;
  int mw = (wid & 1) * 32, nw = (wid >> 1) * 32;

  {
    const __half* wsrc = g_Wh + (r * 3 + (LI - 1)) * 16384;
    #pragma unroll
    for (int j = 0; j < 8; j++){
      int i = j * 256 + tid;
      int row = i >> 4, seg = i & 15;
      CP_ASYNC16(sb + OFF_B + (u32)(row * SA + seg * 8) * 2, wsrc + row * 128 + seg * 8);
    }
    CP_COMMIT();
  }
  if (tid < 128){
    ((float*)(bp + OFF_SSC))[tid] = g_st[LI - 1][r][tid][0];
    ((float*)(bp + OFF_SSH))[tid] = g_st[LI - 1][r][tid][1];
    ((float*)(bp + OFF_SSB))[tid] = bArr[(r * 3 + (LI - 1)) * HID + tid];
  }
  __syncthreads();

  const float* ssc = (const float*)(bp + OFF_SSC);
  const float* ssh = (const float*)(bp + OFF_SSH);
  #pragma unroll
  for (int j = 0; j < 8; j++){
    int f = j * 256 + tid;
    int row = f >> 5, c4 = (f & 31) << 2;
    float4 h = *(const float4*)&hin[(size_t)(m0 + row) * HID + c4];
    float4 sc = *(const float4*)&ssc[c4];
    float4 sh = *(const float4*)&ssh[c4];
    float4 a;
    a.x = fmaxf(fmaf(h.x, sc.x, sh.x), 0.f);
    a.y = fmaxf(fmaf(h.y, sc.y, sh.y), 0.f);
    a.z = fmaxf(fmaf(h.z, sc.z, sh.z), 0.f);
    a.w = fmaxf(fmaf(h.w, sc.w, sh.w), 0.f);
    store_a4(bp, OFF_A + (u32)(row * SA + c4) * 2, a);
  }
  CP_WAIT0();
  __syncthreads();

  float acc[2][4][4];
  #pragma unroll
  for (int im = 0; im < 2; im++)
    #pragma unroll
    for (int in = 0; in < 4; in++)
      #pragma unroll
      for (int t = 0; t < 4; t++) acc[im][in][t] = 0.f;

  mma_chunk<8>(sb, mw, nw, lane, acc);

  int nv = g_bnd[r] + g_cnt[r] - m0;
  nv = (nv < 0) ? 0 : ((nv > 64) ? 64 : nv);
  epilogue_mma(acc, bp, hout, m0, mw, nw, lane, r, LI, nv);
}

// ---------------- BN finalize ----------------
__global__ void k_finalize(int layer, const float* __restrict__ gamma,
                           const float* __restrict__ beta){
  int t = threadIdx.x + blockIdx.x * blockDim.x;
  if (t >= 512) return;
  int r = t >> 7, c = t & 127;
  float cnt  = g_cntf[r];
  float mean = g_stats[layer][r][c][0] / cnt;
  float var  = fmaxf(g_stats[layer][r][c][1] / cnt - mean * mean, 0.f);
  float inv  = rsqrtf(var + 1e-5f);
  float s    = gamma[(r * 4 + layer) * HID + c] * inv;
  g_st[layer][r][c][0] = s;
  g_st[layer][r][c][1] = beta[(r * 4 + layer) * HID + c] - mean * s;
}

// ---------------- output: node-bucketed gather ----------------
__global__ void k_out(const float* __restrict__ att, float* __restrict__ out){
  int n = blockIdx.x, col = threadIdx.x;
  int s = g_noff[n], cnt = g_ncnt[n];
  float acc = 0.f;
  for (int k = 0; k < cnt; k++){
    int e = g_nbkt[s + k];
    int row = g_inv[e];
    int r = g_route[e];
    float h = g_hB[(size_t)row * HID + col];
    acc += fmaxf(fmaf(h, g_st[3][r][col][0], g_st[3][r][col][1]), 0.f) * att[r];
  }
  out[(size_t)n * HID + col] = acc;
}

// ---------------- launch ----------------
extern "C" void kernel_launch(void* const* d_in, const int* in_sizes, int n_in,
                              void* d_out, int out_size){
  const float* nf    = (const float*)d_in[0];
  const float* geo   = (const float*)d_in[1];
  const int*   ei    = (const int*)d_in[2];
  const int*   eij   = (const int*)d_in[3];
  const int*   ejk   = (const int*)d_in[4];
  const int*   nei   = (const int*)d_in[5];
  const float* att   = (const float*)d_in[6];
  const float* W0    = (const float*)d_in[7];
  const float* b0    = (const float*)d_in[8];
  const float* W     = (const float*)d_in[9];
  const float* b     = (const float*)d_in[10];
  const float* gamma = (const float*)d_in[11];
  const float* beta  = (const float*)d_in[12];
  float* out = (float*)d_out;

  cudaFuncSetAttribute(k_gemm0,    cudaFuncAttributeMaxDynamicSharedMemorySize, SMEM_NEED);
  cudaFuncSetAttribute(k_gemml<1>, cudaFuncAttributeMaxDynamicSharedMemorySize, SMEM_NEED);
  cudaFuncSetAttribute(k_gemml<2>, cudaFuncAttributeMaxDynamicSharedMemorySize, SMEM_NEED);
  cudaFuncSetAttribute(k_gemml<3>, cudaFuncAttributeMaxDynamicSharedMemorySize, SMEM_NEED);

  k_setup<<<SETUP_GRID, 256>>>(eij, ejk, nei, ei, W0, W);   // L1
  k_offsets2<<<1, 1024>>>();                                 // L2
  k_permprep<<<E_ / 256, 256>>>(ei);                         // L3
  k_gemm0<<<GRID_G2, 256, SMEM_NEED>>>(nf, geo, ei, b0);     // L4 <- ncu window
  k_finalize<<<1, 512>>>(0, gamma, beta);
  k_gemml<1><<<GRID_G2, 256, SMEM_NEED>>>(b);
  k_finalize<<<1, 512>>>(1, gamma, beta);
  k_gemml<2><<<GRID_G2, 256, SMEM_NEED>>>(b);
  k_finalize<<<1, 512>>>(2, gamma, beta);
  k_gemml<3><<<GRID_G2, 256, SMEM_NEED>>>(b);
  k_finalize<<<1, 512>>>(3, gamma, beta);
  k_out<<<N_, HID>>>(att, out);
}

// round 11
// speedup vs baseline: 1.0759x; 1.0512x over previous
#include <cuda_runtime.h>
#include <cuda_fp16.h>

#define HID 128
#define E_ 262144
#define N_ 32768
#define GEO_ 13
#define ROWS_MAX (E_ + 512)
#define GRID_G2 (ROWS_MAX / 64)
#define SETUP_BLKS 1026
#define WPREP_BLKS 1568
#define SETUP_GRID (SETUP_BLKS + WPREP_BLKS)

typedef unsigned long long u64;
typedef unsigned int u32;

// ---- dynamic smem layout (M-tile 64, single fp16) ----
#define SA 136
#define OFF_A 0                    // 64 x SA fp16 = 17408
#define OFF_B 17408                // 128 x SA fp16 = 34816
#define OFF_SSB 52224
#define OFF_SSC 52736
#define OFF_SSH 53248
#define SMEM_NEED 53760            // x3 CTAs -> occupancy 3

// ---------------- scratch ----------------
__device__ __half g_hA16[(size_t)ROWS_MAX * HID];
__device__ __half g_hB16[(size_t)ROWS_MAX * HID];
__device__ __half g_Wh[4 * 3 * 16384];
__device__ __half g_W0h[4 * 3 * 16384];
__device__ __half g_W0gh[4 * 2048];
__device__ int   g_perm[ROWS_MAX];
__device__ u32   g_invr[E_];              // edge -> row | (route<<20)
__device__ int   g_route[E_];
__device__ int   g_cnt[4];
__device__ int   g_cur[4];
__device__ int   g_bnd[5];
__device__ float g_cntf[4];
__device__ float g_stats[4][4][HID][2];
__device__ float g_st[4][4][HID][2];
__device__ int   g_ncnt[N_];
__device__ int   g_ncur[N_];
__device__ int   g_noff[N_];
__device__ int   g_nbkt[E_];

// ---------------- helpers ----------------
__device__ __forceinline__ u32 smem_u32(const void* p){
  u32 a; asm("{ .reg .u64 t; cvta.to.shared.u64 t, %1; cvt.u32.u64 %0, t; }" : "=r"(a) : "l"(p));
  return a;
}
#define CP_ASYNC16(dst, src) asm volatile("cp.async.ca.shared.global [%0], [%1], 16;" :: "r"(dst), "l"(src))
#define CP_COMMIT() asm volatile("cp.async.commit_group;" ::: "memory")
#define CP_WAIT0() asm volatile("cp.async.wait_group 0;" ::: "memory")

__device__ __forceinline__ void store_a4(char* bp, u32 off, float4 v){
  __half2 h01 = __floats2half2_rn(v.x, v.y);
  __half2 h23 = __floats2half2_rn(v.z, v.w);
  *(uint2*)(bp + off) = make_uint2(*(u32*)&h01, *(u32*)&h23);
}
__device__ __forceinline__ void ldm4(u32& r0, u32& r1, u32& r2, u32& r3, u32 addr){
  asm volatile("ldmatrix.sync.aligned.m8n8.x4.shared.b16 {%0,%1,%2,%3}, [%4];"
               : "=r"(r0), "=r"(r1), "=r"(r2), "=r"(r3) : "r"(addr));
}
__device__ __forceinline__ void mma16816(float* d, const u32* a, u32 b0, u32 b1){
  asm volatile("mma.sync.aligned.m16n8k16.row.col.f32.f16.f16.f32 "
               "{%0,%1,%2,%3}, {%4,%5,%6,%7}, {%8,%9}, {%0,%1,%2,%3};"
               : "+f"(d[0]), "+f"(d[1]), "+f"(d[2]), "+f"(d[3])
               : "r"(a[0]), "r"(a[1]), "r"(a[2]), "r"(a[3]), "r"(b0), "r"(b1));
}

// ---------------- L1: setup + weight prep ----------------
__global__ void k_setup(const int* __restrict__ eij, const int* __restrict__ ejk,
                        const int* __restrict__ nei_ptr, const int* __restrict__ ei,
                        const float* __restrict__ W0, const float* __restrict__ W){
  int bid = blockIdx.x, tid = threadIdx.x;
  if (bid < SETUP_BLKS){
    int idx = bid * 256 + tid;
    if (idx < ROWS_MAX) g_perm[idx] = -1;
    if (idx < 4096) ((float*)g_stats)[idx] = 0.f;
    if (idx < 4){ g_cnt[idx] = 0; g_cur[idx] = 0; }
    if (idx < N_){ g_ncnt[idx] = 0; g_ncur[idx] = 0; }
    if (idx < E_){
      int nei = nei_ptr[0];
      int r = ((eij[idx] < nei) ? 0 : 2) | ((ejk[idx] < nei) ? 0 : 1);
      g_route[idx] = r;
      int lane = tid & 31;
      #pragma unroll
      for (int rr = 0; rr < 4; rr++){
        unsigned m = __ballot_sync(0xFFFFFFFFu, r == rr);
        if (r == rr && lane == (__ffs(m) - 1)) atomicAdd(&g_cnt[rr], __popc(m));
      }
      atomicAdd(&g_ncnt[ei[idx]], 1);
    }
  } else {
    int idx = (bid - SETUP_BLKS) * 256 + tid;
    const int NL = 4 * 3 * 16384;
    if (idx < NL){
      int rl = idx / 16384, rem = idx & 16383;
      int n = rem >> 7, k = rem & 127;
      g_Wh[idx] = __float2half_rn(W[((size_t)(rl * 128 + n)) * 128 + k]);
    } else if (idx < 2 * NL){
      int t2 = idx - NL;
      int rc = t2 / 16384, rem = t2 & 16383;
      int r = rc / 3, c = rc % 3;
      int n = rem >> 7, k = rem & 127;
      g_W0h[t2] = __float2half_rn(W0[((size_t)(r * 128 + n)) * 397 + c * 128 + k]);
    } else {
      int t2 = idx - 2 * NL;
      int r = t2 / 2048, rem = t2 & 2047;
      int n = rem >> 4, k = rem & 15;
      int ko = 384 + k;
      float v = (ko < 397) ? W0[((size_t)(r * 128 + n)) * 397 + ko] : 0.f;
      g_W0gh[t2] = __float2half_rn(v);
    }
  }
}

// ---------------- L2: route offsets + node prefix sum ----------------
__global__ void k_offsets2(){
  __shared__ int part[1024];
  int t = threadIdx.x;
  if (t == 0){
    int b = 0;
    #pragma unroll
    for (int r = 0; r < 4; r++){
      g_bnd[r] = b;
      int c = g_cnt[r];
      b += ((c + 127) / 128) * 128;
      g_cntf[r] = (c > 0) ? (float)c : 1.0f;
    }
    g_bnd[4] = b;
  }
  int base = t * 32;
  int loc[32], s = 0;
  #pragma unroll
  for (int j = 0; j < 32; j++){ loc[j] = s; s += g_ncnt[base + j]; }
  part[t] = s;
  __syncthreads();
  for (int off = 1; off < 1024; off <<= 1){
    int v = (t >= off) ? part[t - off] : 0;
    __syncthreads();
    part[t] += v;
    __syncthreads();
  }
  int excl = part[t] - s;
  #pragma unroll
  for (int j = 0; j < 32; j++) g_noff[base + j] = excl + loc[j];
}

// ---------------- L3: permutation + node buckets ----------------
__global__ void k_permprep(const int* __restrict__ ei){
  int e = blockIdx.x * 256 + threadIdx.x;
  int r = g_route[e];
  int lane = threadIdx.x & 31;
  #pragma unroll
  for (int rr = 0; rr < 4; rr++){
    unsigned m = __ballot_sync(0xFFFFFFFFu, r == rr);
    if (r == rr){
      int leader = __ffs(m) - 1;
      int base = 0;
      if (lane == leader) base = atomicAdd(&g_cur[rr], __popc(m));
      base = __shfl_sync(m, base, leader);
      unsigned lt = (lane == 0) ? 0u : (0xFFFFFFFFu >> (32 - lane));
      int pos = g_bnd[rr] + base + __popc(m & lt);
      g_perm[pos] = e;
      g_invr[e] = (u32)pos | ((u32)rr << 20);
    }
  }
  int i = ei[e];
  int slot = g_noff[i] + atomicAdd(&g_ncur[i], 1);
  g_nbkt[slot] = e;
}

// ---------------- fragment loads ----------------
__device__ __forceinline__ void loadA(u32 sb, int mw, int lane, int k0, u32 a[2][4]){
  #pragma unroll
  for (int im = 0; im < 2; im++){
    int row = mw + im * 16 + (lane & 15);
    int col = k0 + ((lane >> 4) << 3);
    ldm4(a[im][0], a[im][1], a[im][2], a[im][3], sb + OFF_A + (u32)(row * SA + col) * 2);
  }
}
__device__ __forceinline__ void loadB(u32 sb, int nw, int lane, int k0, u32 b[4][2]){
  int brow = nw + ((lane >> 4) << 3) + (lane & 7);
  int bcol = k0 + (((lane >> 3) & 1) << 3);
  #pragma unroll
  for (int g = 0; g < 2; g++){
    ldm4(b[2*g][0], b[2*g][1], b[2*g+1][0], b[2*g+1][1],
         sb + OFF_B + (u32)((brow + g * 16) * SA + bcol) * 2);
  }
}

// ---------------- pipelined mainloop (A double-buffered) ----------------
template<int NK>
__device__ __forceinline__ void mma_chunk(u32 sb, int mw, int nw, int lane, float acc[2][4][4]){
  u32 a[2][2][4];
  loadA(sb, mw, lane, 0, a[0]);
  #pragma unroll
  for (int ks = 0; ks < NK; ks++){
    int cur = ks & 1;
    u32 b[4][2];
    loadB(sb, nw, lane, ks * 16, b);
    if (ks + 1 < NK) loadA(sb, mw, lane, (ks + 1) * 16, a[cur ^ 1]);
    #pragma unroll
    for (int im = 0; im < 2; im++)
      #pragma unroll
      for (int in = 0; in < 4; in++)
        mma16816(acc[im][in], a[cur][im], b[in][0], b[in][1]);
  }
}

// ---------------- epilogue: bias + fp16 store + fused BN stats ----------------
__device__ __forceinline__ void epilogue_mma(float acc[2][4][4], char* bp,
                                             __half* __restrict__ hout,
                                             int m0, int mw, int nw, int lane,
                                             int r, int layer, int nval){
  int gid = lane >> 2, tig = lane & 3;
  const float* ssb = (const float*)(bp + OFF_SSB);
  float sum[4][2], sq[4][2];
  #pragma unroll
  for (int in = 0; in < 4; in++){ sum[in][0] = sum[in][1] = sq[in][0] = sq[in][1] = 0.f; }
  #pragma unroll
  for (int im = 0; im < 2; im++){
    int lr0 = mw + im * 16 + gid;
    bool v0 = lr0 < nval, v1 = (lr0 + 8) < nval;
    #pragma unroll
    for (int in = 0; in < 4; in++){
      float* d = acc[im][in];
      int col = nw + in * 8 + tig * 2;
      float b0 = ssb[col], b1 = ssb[col + 1];
      float e0 = d[0] + b0, e1 = d[1] + b1, e2 = d[2] + b0, e3 = d[3] + b1;
      __half2 p01 = __floats2half2_rn(e0, e1);
      __half2 p23 = __floats2half2_rn(e2, e3);
      *(u32*)&hout[(size_t)(m0 + lr0) * HID + col]     = *(u32*)&p01;
      *(u32*)&hout[(size_t)(m0 + lr0 + 8) * HID + col] = *(u32*)&p23;
      float m0v = v0 ? e0 : 0.f, m1v = v0 ? e1 : 0.f;
      float m2v = v1 ? e2 : 0.f, m3v = v1 ? e3 : 0.f;
      sum[in][0] += m0v + m2v; sum[in][1] += m1v + m3v;
      sq[in][0]  += m0v * m0v + m2v * m2v;
      sq[in][1]  += m1v * m1v + m3v * m3v;
    }
  }
  #pragma unroll
  for (int off = 4; off <= 16; off <<= 1){
    #pragma unroll
    for (int in = 0; in < 4; in++){
      sum[in][0] += __shfl_xor_sync(0xFFFFFFFFu, sum[in][0], off);
      sum[in][1] += __shfl_xor_sync(0xFFFFFFFFu, sum[in][1], off);
      sq[in][0]  += __shfl_xor_sync(0xFFFFFFFFu, sq[in][0], off);
      sq[in][1]  += __shfl_xor_sync(0xFFFFFFFFu, sq[in][1], off);
    }
  }
  if (gid == 0){
    #pragma unroll
    for (int in = 0; in < 4; in++){
      int col = nw + in * 8 + tig * 2;
      atomicAdd(&g_stats[layer][r][col][0], sum[in][0]);
      atomicAdd(&g_stats[layer][r][col][1], sq[in][0]);
      atomicAdd(&g_stats[layer][r][col + 1][0], sum[in][1]);
      atomicAdd(&g_stats[layer][r][col + 1][1], sq[in][1]);
    }
  }
}

// ---------------- L4 (PROFILED): GEMM layer 0 (gather, K = 3*128 + 16) ----------
__global__ __launch_bounds__(256, 3)
void k_gemm0(const float* __restrict__ nf, const float* __restrict__ geo,
             const int* __restrict__ ei, const float* __restrict__ b0){
  extern __shared__ char bp[];
  __shared__ int sE[64], sN0[64], sN1[64], sN2[64];
  u32 sb = smem_u32(bp);
  int m0 = blockIdx.x << 6;
  if (m0 >= g_bnd[4]) return;
  int r = 0;
  #pragma unroll
  for (int q = 1; q < 4; q++) if (m0 >= g_bnd[q]) r = q;
  int tid = threadIdx.x, wid = tid >> 5, lane = tid & 31;
  int mw = (wid & 1) * 32, nw = (wid >> 1) * 32;

  if (tid < 64){
    int e = g_perm[m0 + tid];
    sE[tid] = e;
    int a = 0, b_ = 0, c = 0;
    if (e >= 0){ a = ei[e]; b_ = ei[E_ + e]; c = ei[2 * E_ + e]; }
    sN0[tid] = a; sN1[tid] = b_; sN2[tid] = c;
  }
  if (tid < 128) ((float*)(bp + OFF_SSB))[tid] = b0[r * HID + tid];
  __syncthreads();

  float acc[2][4][4];
  #pragma unroll
  for (int im = 0; im < 2; im++)
    #pragma unroll
    for (int in = 0; in < 4; in++)
      #pragma unroll
      for (int t = 0; t < 4; t++) acc[im][in][t] = 0.f;

  for (int ch = 0; ch < 4; ch++){
    if (ch){ __syncthreads(); }
    if (ch < 3){
      const __half* wsrc = g_W0h + (r * 3 + ch) * 16384;
      #pragma unroll
      for (int j = 0; j < 8; j++){
        int i = j * 256 + tid;
        int row = i >> 4, seg = i & 15;
        CP_ASYNC16(sb + OFF_B + (u32)(row * SA + seg * 8) * 2, wsrc + row * 128 + seg * 8);
      }
      const int* nodes = (ch == 0) ? sN0 : ((ch == 1) ? sN1 : sN2);
      #pragma unroll
      for (int j = 0; j < 8; j++){
        int f = j * 256 + tid;
        int row = f >> 5, c4 = (f & 31) << 2;
        float4 v = make_float4(0.f, 0.f, 0.f, 0.f);
        if (sE[row] >= 0) v = *(const float4*)&nf[(size_t)nodes[row] * HID + c4];
        store_a4(bp, OFF_A + (u32)(row * SA + c4) * 2, v);
      }
    } else {
      const __half* wsrc = g_W0gh + r * 2048;
      {
        int row = tid >> 1, seg = tid & 1;
        CP_ASYNC16(sb + OFF_B + (u32)(row * SA + seg * 8) * 2, wsrc + row * 16 + seg * 8);
      }
      {
        int row = tid >> 2, c4 = (tid & 3) << 2;
        int e = sE[row];
        float4 v;
        #pragma unroll
        for (int t = 0; t < 4; t++){
          int col = c4 + t;
          (&v.x)[t] = (e >= 0 && col < GEO_) ? geo[(size_t)e * GEO_ + col] : 0.f;
        }
        store_a4(bp, OFF_A + (u32)(row * SA + c4) * 2, v);
      }
    }
    CP_COMMIT();
    CP_WAIT0();
    __syncthreads();
    if (ch < 3) mma_chunk<8>(sb, mw, nw, lane, acc);
    else        mma_chunk<1>(sb, mw, nw, lane, acc);
  }

  int nv = g_bnd[r] + g_cnt[r] - m0;
  nv = (nv < 0) ? 0 : ((nv > 64) ? 64 : nv);
  epilogue_mma(acc, bp, g_hA16, m0, mw, nw, lane, r, 0, nv);
}

// ---------------- GEMM layers 1..3 (fp16 h in/out) ----------------
template<int LI>
__global__ __launch_bounds__(256, 3)
void k_gemml(const float* __restrict__ bArr){
  const __half* hin  = (LI & 1) ? g_hA16 : g_hB16;
  __half*       hout = (LI & 1) ? g_hB16 : g_hA16;
  extern __shared__ char bp[];
  u32 sb = smem_u32(bp);
  int m0 = blockIdx.x << 6;
  if (m0 >= g_bnd[4]) return;
  int r = 0;
  #pragma unroll
  for (int q = 1; q < 4; q++) if (m0 >= g_bnd[q]) r = q;
  int tid = threadIdx.x, wid = tid >> 5, lane = tid & 31;
  int mw = (wid & 1) * 32, nw = (wid >> 1) * 32;

  {
    const __half* wsrc = g_Wh + (r * 3 + (LI - 1)) * 16384;
    #pragma unroll
    for (int j = 0; j < 8; j++){
      int i = j * 256 + tid;
      int row = i >> 4, seg = i & 15;
      CP_ASYNC16(sb + OFF_B + (u32)(row * SA + seg * 8) * 2, wsrc + row * 128 + seg * 8);
    }
    CP_COMMIT();
  }
  if (tid < 128){
    ((float*)(bp + OFF_SSC))[tid] = g_st[LI - 1][r][tid][0];
    ((float*)(bp + OFF_SSH))[tid] = g_st[LI - 1][r][tid][1];
    ((float*)(bp + OFF_SSB))[tid] = bArr[(r * 3 + (LI - 1)) * HID + tid];
  }
  __syncthreads();

  const float* ssc = (const float*)(bp + OFF_SSC);
  const float* ssh = (const float*)(bp + OFF_SSH);
  #pragma unroll
  for (int j = 0; j < 8; j++){
    int f = j * 256 + tid;
    int row = f >> 5, c4 = (f & 31) << 2;
    uint2 hv = *(const uint2*)&hin[(size_t)(m0 + row) * HID + c4];
    float2 f01 = __half22float2(*(__half2*)&hv.x);
    float2 f23 = __half22float2(*(__half2*)&hv.y);
    float4 sc = *(const float4*)&ssc[c4];
    float4 sh = *(const float4*)&ssh[c4];
    float4 a;
    a.x = fmaxf(fmaf(f01.x, sc.x, sh.x), 0.f);
    a.y = fmaxf(fmaf(f01.y, sc.y, sh.y), 0.f);
    a.z = fmaxf(fmaf(f23.x, sc.z, sh.z), 0.f);
    a.w = fmaxf(fmaf(f23.y, sc.w, sh.w), 0.f);
    store_a4(bp, OFF_A + (u32)(row * SA + c4) * 2, a);
  }
  CP_WAIT0();
  __syncthreads();

  float acc[2][4][4];
  #pragma unroll
  for (int im = 0; im < 2; im++)
    #pragma unroll
    for (int in = 0; in < 4; in++)
      #pragma unroll
      for (int t = 0; t < 4; t++) acc[im][in][t] = 0.f;

  mma_chunk<8>(sb, mw, nw, lane, acc);

  int nv = g_bnd[r] + g_cnt[r] - m0;
  nv = (nv < 0) ? 0 : ((nv > 64) ? 64 : nv);
  epilogue_mma(acc, bp, hout, m0, mw, nw, lane, r, LI, nv);
}

// ---------------- BN finalize ----------------
__global__ void k_finalize(int layer, const float* __restrict__ gamma,
                           const float* __restrict__ beta){
  int t = threadIdx.x + blockIdx.x * blockDim.x;
  if (t >= 512) return;
  int r = t >> 7, c = t & 127;
  float cnt  = g_cntf[r];
  float mean = g_stats[layer][r][c][0] / cnt;
  float var  = fmaxf(g_stats[layer][r][c][1] / cnt - mean * mean, 0.f);
  float inv  = rsqrtf(var + 1e-5f);
  float s    = gamma[(r * 4 + layer) * HID + c] * inv;
  g_st[layer][r][c][0] = s;
  g_st[layer][r][c][1] = beta[(r * 4 + layer) * HID + c] - mean * s;
}

// ---------------- output: node-bucketed gather (fp16 h, preloaded tables) -------
__global__ void k_out(const float* __restrict__ att, float* __restrict__ out){
  int n = blockIdx.x, t = threadIdx.x;
  int col = t * 2;
  float s0[4], t0[4], s1[4], t1[4], aw[4];
  #pragma unroll
  for (int r = 0; r < 4; r++){
    s0[r] = g_st[3][r][col][0];     t0[r] = g_st[3][r][col][1];
    s1[r] = g_st[3][r][col + 1][0]; t1[r] = g_st[3][r][col + 1][1];
    aw[r] = att[r];
  }
  int s = g_noff[n], cnt = g_ncnt[n];
  float a0 = 0.f, a1 = 0.f;
  for (int k = 0; k < cnt; k++){
    int e = g_nbkt[s + k];
    u32 pr = g_invr[e];
    int row = pr & 0xFFFFF;
    int r = pr >> 20;
    u32 hv = *(const u32*)&g_hB16[(size_t)row * HID + col];
    float2 f = __half22float2(*(__half2*)&hv);
    a0 += fmaxf(fmaf(f.x, s0[r], t0[r]), 0.f) * aw[r];
    a1 += fmaxf(fmaf(f.y, s1[r], t1[r]), 0.f) * aw[r];
  }
  *(float2*)&out[(size_t)n * HID + col] = make_float2(a0, a1);
}

// ---------------- launch ----------------
extern "C" void kernel_launch(void* const* d_in, const int* in_sizes, int n_in,
                              void* d_out, int out_size){
  const float* nf    = (const float*)d_in[0];
  const float* geo   = (const float*)d_in[1];
  const int*   ei    = (const int*)d_in[2];
  const int*   eij   = (const int*)d_in[3];
  const int*   ejk   = (const int*)d_in[4];
  const int*   nei   = (const int*)d_in[5];
  const float* att   = (const float*)d_in[6];
  const float* W0    = (const float*)d_in[7];
  const float* b0    = (const float*)d_in[8];
  const float* W     = (const float*)d_in[9];
  const float* b     = (const float*)d_in[10];
  const float* gamma = (const float*)d_in[11];
  const float* beta  = (const float*)d_in[12];
  float* out = (float*)d_out;

  cudaFuncSetAttribute(k_gemm0,    cudaFuncAttributeMaxDynamicSharedMemorySize, SMEM_NEED);
  cudaFuncSetAttribute(k_gemml<1>, cudaFuncAttributeMaxDynamicSharedMemorySize, SMEM_NEED);
  cudaFuncSetAttribute(k_gemml<2>, cudaFuncAttributeMaxDynamicSharedMemorySize, SMEM_NEED);
  cudaFuncSetAttribute(k_gemml<3>, cudaFuncAttributeMaxDynamicSharedMemorySize, SMEM_NEED);

  k_setup<<<SETUP_GRID, 256>>>(eij, ejk, nei, ei, W0, W);   // L1
  k_offsets2<<<1, 1024>>>();                                 // L2
  k_permprep<<<E_ / 256, 256>>>(ei);                         // L3
  k_gemm0<<<GRID_G2, 256, SMEM_NEED>>>(nf, geo, ei, b0);     // L4 <- ncu window
  k_finalize<<<1, 512>>>(0, gamma, beta);
  k_gemml<1><<<GRID_G2, 256, SMEM_NEED>>>(b);
  k_finalize<<<1, 512>>>(1, gamma, beta);
  k_gemml<2><<<GRID_G2, 256, SMEM_NEED>>>(b);
  k_finalize<<<1, 512>>>(2, gamma, beta);
  k_gemml<3><<<GRID_G2, 256, SMEM_NEED>>>(b);
  k_finalize<<<1, 512>>>(3, gamma, beta);
  k_out<<<N_, 64>>>(att, out);
}

// round 12
// speedup vs baseline: 1.2428x; 1.1551x over previous
#include <cuda_runtime.h>
#include <cuda_fp16.h>

#define HID 128
#define E_ 262144
#define N_ 32768
#define GEO_ 13
#define ROWS_MAX (E_ + 512)
#define GRID_G2 (ROWS_MAX / 64)
#define SETUP_BLKS 1026
#define WPREP_BLKS 1568
#define NF16_BLKS 2048
#define GEO16_BLKS 1024
#define SETUP_GRID (SETUP_BLKS + WPREP_BLKS + NF16_BLKS + GEO16_BLKS)
#define LGRID 296

typedef unsigned long long u64;
typedef unsigned int u32;

// ---- dynamic smem: two stages of (A | B) ----
#define SA 136
#define OFF_A 0                    // 64 x SA fp16 = 17408
#define OFF_B 17408                // 128 x SA fp16 = 34816
#define STAGE 52224
#define SMEM_NEED (2 * STAGE)      // 104448; x2 CTAs/SM

// ---------------- scratch ----------------
__device__ __half g_hA16[(size_t)ROWS_MAX * HID];
__device__ __half g_hB16[(size_t)ROWS_MAX * HID];
__device__ __half g_nf16[(size_t)N_ * HID];
__device__ __half g_geo16[(size_t)E_ * 16];
__device__ __half g_Wh[4 * 3 * 16384];
__device__ __half g_W0h[4 * 3 * 16384];
__device__ __half g_W0gh[4 * 2048];
__device__ int   g_perm[ROWS_MAX];
__device__ u32   g_invr[E_];
__device__ int   g_route[E_];
__device__ int   g_cnt[4];
__device__ int   g_cur[4];
__device__ int   g_bnd[5];
__device__ float g_cntf[4];
__device__ float g_stats[4][4][HID][2];
__device__ float g_st[4][4][HID][2];
__device__ int   g_ncnt[N_];
__device__ int   g_ncur[N_];
__device__ int   g_noff[N_];
__device__ int   g_nbkt[E_];

// ---------------- helpers ----------------
__device__ __forceinline__ u32 smem_u32(const void* p){
  u32 a; asm("{ .reg .u64 t; cvta.to.shared.u64 t, %1; cvt.u32.u64 %0, t; }" : "=r"(a) : "l"(p));
  return a;
}
#define CP_ASYNC16(dst, src) asm volatile("cp.async.ca.shared.global [%0], [%1], 16;" :: "r"(dst), "l"(src))
#define CP_COMMIT() asm volatile("cp.async.commit_group;" ::: "memory")
#define CP_WAIT0() asm volatile("cp.async.wait_group 0;" ::: "memory")

__device__ __forceinline__ void ldm4(u32& r0, u32& r1, u32& r2, u32& r3, u32 addr){
  asm volatile("ldmatrix.sync.aligned.m8n8.x4.shared.b16 {%0,%1,%2,%3}, [%4];"
               : "=r"(r0), "=r"(r1), "=r"(r2), "=r"(r3) : "r"(addr));
}
__device__ __forceinline__ void mma16816(float* d, const u32* a, u32 b0, u32 b1){
  asm volatile("mma.sync.aligned.m16n8k16.row.col.f32.f16.f16.f32 "
               "{%0,%1,%2,%3}, {%4,%5,%6,%7}, {%8,%9}, {%0,%1,%2,%3};"
               : "+f"(d[0]), "+f"(d[1]), "+f"(d[2]), "+f"(d[3])
               : "r"(a[0]), "r"(a[1]), "r"(a[2]), "r"(a[3]), "r"(b0), "r"(b1));
}

// ---------------- L1: setup + weight prep + nf16/geo16 convert ----------------
__global__ void k_setup(const int* __restrict__ eij, const int* __restrict__ ejk,
                        const int* __restrict__ nei_ptr, const int* __restrict__ ei,
                        const float* __restrict__ W0, const float* __restrict__ W,
                        const float* __restrict__ nf, const float* __restrict__ geo){
  int bid = blockIdx.x, tid = threadIdx.x;
  if (bid < SETUP_BLKS){
    int idx = bid * 256 + tid;
    if (idx < ROWS_MAX) g_perm[idx] = -1;
    if (idx < 4096) ((float*)g_stats)[idx] = 0.f;
    if (idx < 4){ g_cnt[idx] = 0; g_cur[idx] = 0; }
    if (idx < N_){ g_ncnt[idx] = 0; g_ncur[idx] = 0; }
    if (idx < E_){
      int nei = nei_ptr[0];
      int r = ((eij[idx] < nei) ? 0 : 2) | ((ejk[idx] < nei) ? 0 : 1);
      g_route[idx] = r;
      int lane = tid & 31;
      #pragma unroll
      for (int rr = 0; rr < 4; rr++){
        unsigned m = __ballot_sync(0xFFFFFFFFu, r == rr);
        if (r == rr && lane == (__ffs(m) - 1)) atomicAdd(&g_cnt[rr], __popc(m));
      }
      atomicAdd(&g_ncnt[ei[idx]], 1);
    }
  } else if (bid < SETUP_BLKS + WPREP_BLKS){
    int idx = (bid - SETUP_BLKS) * 256 + tid;
    const int NL = 4 * 3 * 16384;
    if (idx < NL){
      int rl = idx / 16384, rem = idx & 16383;
      int n = rem >> 7, k = rem & 127;
      g_Wh[idx] = __float2half_rn(W[((size_t)(rl * 128 + n)) * 128 + k]);
    } else if (idx < 2 * NL){
      int t2 = idx - NL;
      int rc = t2 / 16384, rem = t2 & 16383;
      int r = rc / 3, c = rc % 3;
      int n = rem >> 7, k = rem & 127;
      g_W0h[t2] = __float2half_rn(W0[((size_t)(r * 128 + n)) * 397 + c * 128 + k]);
    } else {
      int t2 = idx - 2 * NL;
      int r = t2 / 2048, rem = t2 & 2047;
      int n = rem >> 4, k = rem & 15;
      int ko = 384 + k;
      float v = (ko < 397) ? W0[((size_t)(r * 128 + n)) * 397 + ko] : 0.f;
      g_W0gh[t2] = __float2half_rn(v);
    }
  } else if (bid < SETUP_BLKS + WPREP_BLKS + NF16_BLKS){
    int idx = (bid - SETUP_BLKS - WPREP_BLKS) * 256 + tid;
    size_t base = (size_t)idx * 8;
    float4 v0 = *(const float4*)&nf[base];
    float4 v1 = *(const float4*)&nf[base + 4];
    __half2 a = __floats2half2_rn(v0.x, v0.y);
    __half2 b = __floats2half2_rn(v0.z, v0.w);
    __half2 c = __floats2half2_rn(v1.x, v1.y);
    __half2 d = __floats2half2_rn(v1.z, v1.w);
    uint4 o; o.x = *(u32*)&a; o.y = *(u32*)&b; o.z = *(u32*)&c; o.w = *(u32*)&d;
    *(uint4*)&g_nf16[base] = o;
  } else {
    int e = (bid - SETUP_BLKS - WPREP_BLKS - NF16_BLKS) * 256 + tid;
    const float* gp = geo + (size_t)e * GEO_;
    __half h[16];
    #pragma unroll
    for (int c = 0; c < 16; c++) h[c] = (c < GEO_) ? __float2half_rn(gp[c]) : __float2half_rn(0.f);
    uint4* dst = (uint4*)&g_geo16[(size_t)e * 16];
    dst[0] = *(uint4*)&h[0];
    dst[1] = *(uint4*)&h[8];
  }
}

// ---------------- L2: route offsets + node prefix sum ----------------
__global__ void k_offsets2(){
  __shared__ int part[1024];
  int t = threadIdx.x;
  if (t == 0){
    int b = 0;
    #pragma unroll
    for (int r = 0; r < 4; r++){
      g_bnd[r] = b;
      int c = g_cnt[r];
      b += ((c + 127) / 128) * 128;
      g_cntf[r] = (c > 0) ? (float)c : 1.0f;
    }
    g_bnd[4] = b;
  }
  int base = t * 32;
  int loc[32], s = 0;
  #pragma unroll
  for (int j = 0; j < 32; j++){ loc[j] = s; s += g_ncnt[base + j]; }
  part[t] = s;
  __syncthreads();
  for (int off = 1; off < 1024; off <<= 1){
    int v = (t >= off) ? part[t - off] : 0;
    __syncthreads();
    part[t] += v;
    __syncthreads();
  }
  int excl = part[t] - s;
  #pragma unroll
  for (int j = 0; j < 32; j++) g_noff[base + j] = excl + loc[j];
}

// ---------------- L3: permutation + node buckets ----------------
__global__ void k_permprep(const int* __restrict__ ei){
  int e = blockIdx.x * 256 + threadIdx.x;
  int r = g_route[e];
  int lane = threadIdx.x & 31;
  #pragma unroll
  for (int rr = 0; rr < 4; rr++){
    unsigned m = __ballot_sync(0xFFFFFFFFu, r == rr);
    if (r == rr){
      int leader = __ffs(m) - 1;
      int base = 0;
      if (lane == leader) base = atomicAdd(&g_cur[rr], __popc(m));
      base = __shfl_sync(m, base, leader);
      unsigned lt = (lane == 0) ? 0u : (0xFFFFFFFFu >> (32 - lane));
      int pos = g_bnd[rr] + base + __popc(m & lt);
      g_perm[pos] = e;
      g_invr[e] = (u32)pos | ((u32)rr << 20);
    }
  }
  int i = ei[e];
  int slot = g_noff[i] + atomicAdd(&g_ncur[i], 1);
  g_nbkt[slot] = e;
}

// ---------------- cp.async prefetchers ----------------
__device__ __forceinline__ void prefetch_B(u32 base, const __half* wsrc, int tid){
  #pragma unroll
  for (int j = 0; j < 8; j++){
    int i = j * 256 + tid;
    int row = i >> 4, seg = i & 15;
    CP_ASYNC16(base + OFF_B + (u32)(row * SA + seg * 8) * 2, wsrc + row * 128 + seg * 8);
  }
}
__device__ __forceinline__ void prefetch_Ah(u32 base, const __half* hsrc, int tid){
  #pragma unroll
  for (int j = 0; j < 4; j++){
    int i = j * 256 + tid;
    int row = i >> 4, seg = i & 15;
    CP_ASYNC16(base + OFF_A + (u32)(row * SA + seg * 8) * 2, hsrc + (size_t)row * 128 + seg * 8);
  }
}
__device__ __forceinline__ void prefetch_Ag(u32 base, const int* sNc, int tid){
  #pragma unroll
  for (int j = 0; j < 4; j++){
    int i = j * 256 + tid;
    int row = i >> 4, seg = i & 15;
    int node = sNc[row];
    CP_ASYNC16(base + OFF_A + (u32)(row * SA + seg * 8) * 2, g_nf16 + (size_t)node * 128 + seg * 8);
  }
}

// ---------------- fragment loads / mainloop ----------------
__device__ __forceinline__ void loadA(u32 sbase, int mw, int lane, int k0, u32 a[2][4]){
  #pragma unroll
  for (int im = 0; im < 2; im++){
    int row = mw + im * 16 + (lane & 15);
    int col = k0 + ((lane >> 4) << 3);
    ldm4(a[im][0], a[im][1], a[im][2], a[im][3], sbase + OFF_A + (u32)(row * SA + col) * 2);
  }
}
__device__ __forceinline__ void loadB(u32 sbase, int nw, int lane, int k0, u32 b[4][2]){
  int brow = nw + ((lane >> 4) << 3) + (lane & 7);
  int bcol = k0 + (((lane >> 3) & 1) << 3);
  #pragma unroll
  for (int g = 0; g < 2; g++){
    ldm4(b[2*g][0], b[2*g][1], b[2*g+1][0], b[2*g+1][1],
         sbase + OFF_B + (u32)((brow + g * 16) * SA + bcol) * 2);
  }
}
template<int NK>
__device__ __forceinline__ void mma_chunk(u32 sbase, int mw, int nw, int lane, float acc[2][4][4]){
  u32 a[2][2][4];
  loadA(sbase, mw, lane, 0, a[0]);
  #pragma unroll
  for (int ks = 0; ks < NK; ks++){
    int cur = ks & 1;
    u32 b[4][2];
    loadB(sbase, nw, lane, ks * 16, b);
    if (ks + 1 < NK) loadA(sbase, mw, lane, (ks + 1) * 16, a[cur ^ 1]);
    #pragma unroll
    for (int im = 0; im < 2; im++)
      #pragma unroll
      for (int in = 0; in < 4; in++)
        mma16816(acc[im][in], a[cur][im], b[in][0], b[in][1]);
  }
}

// ---------------- epilogue: bias(global) + fp16 store + fused BN stats ----------
__device__ __forceinline__ void epilogue_mma(float acc[2][4][4], const float* __restrict__ biasp,
                                             __half* __restrict__ hout,
                                             int m0, int mw, int nw, int lane,
                                             int r, int layer, int nval){
  int gid = lane >> 2, tig = lane & 3;
  float sum[4][2], sq[4][2];
  #pragma unroll
  for (int in = 0; in < 4; in++){ sum[in][0] = sum[in][1] = sq[in][0] = sq[in][1] = 0.f; }
  #pragma unroll
  for (int im = 0; im < 2; im++){
    int lr0 = mw + im * 16 + gid;
    bool v0 = lr0 < nval, v1 = (lr0 + 8) < nval;
    #pragma unroll
    for (int in = 0; in < 4; in++){
      float* d = acc[im][in];
      int col = nw + in * 8 + tig * 2;
      float2 bv = *(const float2*)&biasp[col];
      float e0 = d[0] + bv.x, e1 = d[1] + bv.y, e2 = d[2] + bv.x, e3 = d[3] + bv.y;
      __half2 p01 = __floats2half2_rn(e0, e1);
      __half2 p23 = __floats2half2_rn(e2, e3);
      *(u32*)&hout[(size_t)(m0 + lr0) * HID + col]     = *(u32*)&p01;
      *(u32*)&hout[(size_t)(m0 + lr0 + 8) * HID + col] = *(u32*)&p23;
      float m0v = v0 ? e0 : 0.f, m1v = v0 ? e1 : 0.f;
      float m2v = v1 ? e2 : 0.f, m3v = v1 ? e3 : 0.f;
      sum[in][0] += m0v + m2v; sum[in][1] += m1v + m3v;
      sq[in][0]  += m0v * m0v + m2v * m2v;
      sq[in][1]  += m1v * m1v + m3v * m3v;
    }
  }
  #pragma unroll
  for (int off = 4; off <= 16; off <<= 1){
    #pragma unroll
    for (int in = 0; in < 4; in++){
      sum[in][0] += __shfl_xor_sync(0xFFFFFFFFu, sum[in][0], off);
      sum[in][1] += __shfl_xor_sync(0xFFFFFFFFu, sum[in][1], off);
      sq[in][0]  += __shfl_xor_sync(0xFFFFFFFFu, sq[in][0], off);
      sq[in][1]  += __shfl_xor_sync(0xFFFFFFFFu, sq[in][1], off);
    }
  }
  if (gid == 0){
    #pragma unroll
    for (int in = 0; in < 4; in++){
      int col = nw + in * 8 + tig * 2;
      atomicAdd(&g_stats[layer][r][col][0], sum[in][0]);
      atomicAdd(&g_stats[layer][r][col][1], sq[in][0]);
      atomicAdd(&g_stats[layer][r][col + 1][0], sum[in][1]);
      atomicAdd(&g_stats[layer][r][col + 1][1], sq[in][1]);
    }
  }
}

// ---------------- L4 (PROFILED): GEMM layer 0 — 2-stage chunk pipeline ----------
__global__ __launch_bounds__(256, 2)
void k_gemm0(const int* __restrict__ ei, const float* __restrict__ b0){
  extern __shared__ char bp[];
  __shared__ int sE[64], sN[3][64];
  u32 sb = smem_u32(bp);
  int m0 = blockIdx.x << 6;
  int bnd1 = g_bnd[1], bnd2 = g_bnd[2], bnd3 = g_bnd[3], bnd4 = g_bnd[4];
  if (m0 >= bnd4) return;
  int r = (m0 >= bnd1) + (m0 >= bnd2) + (m0 >= bnd3);
  int tid = threadIdx.x, wid = tid >> 5, lane = tid & 31;
  int mw = (wid & 1) * 32, nw = (wid >> 1) * 32;

  if (tid < 64){
    int e = g_perm[m0 + tid];
    int a = 0, b_ = 0, c = 0;
    if (e >= 0){ a = ei[e]; b_ = ei[E_ + e]; c = ei[2 * E_ + e]; }
    sN[0][tid] = a; sN[1][tid] = b_; sN[2][tid] = c;
    sE[tid] = (e < 0) ? 0 : e;
  }
  __syncthreads();

  float acc[2][4][4];
  #pragma unroll
  for (int im = 0; im < 2; im++)
    #pragma unroll
    for (int in = 0; in < 4; in++)
      #pragma unroll
      for (int t = 0; t < 4; t++) acc[im][in][t] = 0.f;

  // prefetch chunk 0
  prefetch_B(sb, g_W0h + (r * 3 + 0) * 16384, tid);
  prefetch_Ag(sb, sN[0], tid);
  CP_COMMIT();

  #pragma unroll
  for (int c = 0; c < 4; c++){
    CP_WAIT0();
    __syncthreads();
    u32 nbase = sb + ((c + 1) & 1) * STAGE;
    if (c < 2){
      prefetch_B(nbase, g_W0h + (r * 3 + c + 1) * 16384, tid);
      prefetch_Ag(nbase, sN[c + 1], tid);
    } else if (c == 2){
      // geo chunk: B = W0gh (128 rows x 16), A = geo16 (64 rows x 16)
      {
        int row = tid >> 1, seg = tid & 1;
        CP_ASYNC16(nbase + OFF_B + (u32)(row * SA + seg * 8) * 2,
                   g_W0gh + r * 2048 + row * 16 + seg * 8);
      }
      if (tid < 128){
        int row = tid >> 1, seg = tid & 1;
        int e = sE[row];
        CP_ASYNC16(nbase + OFF_A + (u32)(row * SA + seg * 8) * 2,
                   g_geo16 + (size_t)e * 16 + seg * 8);
      }
    }
    CP_COMMIT();
    u32 cbase = sb + (c & 1) * STAGE;
    if (c < 3) mma_chunk<8>(cbase, mw, nw, lane, acc);
    else       mma_chunk<1>(cbase, mw, nw, lane, acc);
  }

  int nv = g_bnd[r] + g_cnt[r] - m0;
  nv = (nv < 0) ? 0 : ((nv > 64) ? 64 : nv);
  epilogue_mma(acc, b0 + r * HID, g_hA16, m0, mw, nw, lane, r, 0, nv);
}

// ---------------- GEMM layers 1..3: persistent, cross-tile pipeline ------------
template<int LI>
__global__ __launch_bounds__(256, 2)
void k_gemml(const float* __restrict__ bArr){
  const __half* hin  = (LI & 1) ? g_hA16 : g_hB16;
  __half*       hout = (LI & 1) ? g_hB16 : g_hA16;
  extern __shared__ char bp[];
  u32 sb = smem_u32(bp);
  int tid = threadIdx.x, wid = tid >> 5, lane = tid & 31;
  int mw = (wid & 1) * 32, nw = (wid >> 1) * 32;
  int c4 = (tid & 31) << 2;
  int bnd1 = g_bnd[1], bnd2 = g_bnd[2], bnd3 = g_bnd[3], bnd4 = g_bnd[4];
  int ntiles = (bnd4 + 63) >> 6;
  int G = gridDim.x;
  const float* stb = &g_st[LI - 1][0][0][0];
  const __half* wb = g_Wh + (LI - 1) * 16384;

  int t = blockIdx.x;
  float4 pn, qn;
  if (t < ntiles){
    int m0 = t << 6;
    int r = (m0 >= bnd1) + (m0 >= bnd2) + (m0 >= bnd3);
    prefetch_B(sb, wb + r * 3 * 16384, tid);
    prefetch_Ah(sb, hin + (size_t)m0 * HID, tid);
    const float* s = stb + r * 256 + c4 * 2;
    pn = *(const float4*)s;
    qn = *(const float4*)(s + 4);
  }
  CP_COMMIT();

  int st = 0;
  for (; t < ntiles; t += G, st ^= 1){
    int m0 = t << 6;
    int r = (m0 >= bnd1) + (m0 >= bnd2) + (m0 >= bnd3);
    float4 p = pn, q = qn;
    CP_WAIT0();
    __syncthreads();
    // in-place BN+relu convert of A stage
    char* abase = bp + st * STAGE + OFF_A;
    #pragma unroll
    for (int j = 0; j < 8; j++){
      int row = j * 8 + (tid >> 5);
      char* ap = abase + (u32)(row * SA + c4) * 2;
      uint2 hv = *(uint2*)ap;
      float2 f01 = __half22float2(*(__half2*)&hv.x);
      float2 f23 = __half22float2(*(__half2*)&hv.y);
      __half2 a01 = __floats2half2_rn(fmaxf(fmaf(f01.x, p.x, p.y), 0.f),
                                      fmaxf(fmaf(f01.y, p.z, p.w), 0.f));
      __half2 a23 = __floats2half2_rn(fmaxf(fmaf(f23.x, q.x, q.y), 0.f),
                                      fmaxf(fmaf(f23.y, q.z, q.w), 0.f));
      *(uint2*)ap = make_uint2(*(u32*)&a01, *(u32*)&a23);
    }
    __syncthreads();
    int tn = t + G;
    if (tn < ntiles){
      int mn = tn << 6;
      int rn = (mn >= bnd1) + (mn >= bnd2) + (mn >= bnd3);
      u32 nbase = sb + (st ^ 1) * STAGE;
      prefetch_B(nbase, wb + rn * 3 * 16384, tid);
      prefetch_Ah(nbase, hin + (size_t)mn * HID, tid);
      const float* s = stb + rn * 256 + c4 * 2;
      pn = *(const float4*)s;
      qn = *(const float4*)(s + 4);
    }
    CP_COMMIT();

    float acc[2][4][4];
    #pragma unroll
    for (int im = 0; im < 2; im++)
      #pragma unroll
      for (int in = 0; in < 4; in++)
        #pragma unroll
        for (int tt = 0; tt < 4; tt++) acc[im][in][tt] = 0.f;

    mma_chunk<8>(sb + st * STAGE, mw, nw, lane, acc);

    int nv = g_bnd[r] + g_cnt[r] - m0;
    nv = (nv < 0) ? 0 : ((nv > 64) ? 64 : nv);
    epilogue_mma(acc, bArr + (r * 3 + (LI - 1)) * HID, hout, m0, mw, nw, lane, r, LI, nv);
  }
}

// ---------------- BN finalize ----------------
__global__ void k_finalize(int layer, const float* __restrict__ gamma,
                           const float* __restrict__ beta){
  int t = threadIdx.x + blockIdx.x * blockDim.x;
  if (t >= 512) return;
  int r = t >> 7, c = t & 127;
  float cnt  = g_cntf[r];
  float mean = g_stats[layer][r][c][0] / cnt;
  float var  = fmaxf(g_stats[layer][r][c][1] / cnt - mean * mean, 0.f);
  float inv  = rsqrtf(var + 1e-5f);
  float s    = gamma[(r * 4 + layer) * HID + c] * inv;
  g_st[layer][r][c][0] = s;
  g_st[layer][r][c][1] = beta[(r * 4 + layer) * HID + c] - mean * s;
}

// ---------------- output: node-bucketed gather ----------------
__global__ void k_out(const float* __restrict__ att, float* __restrict__ out){
  int n = blockIdx.x, t = threadIdx.x;
  int col = t * 2;
  float s0[4], t0[4], s1[4], t1[4], aw[4];
  #pragma unroll
  for (int r = 0; r < 4; r++){
    s0[r] = g_st[3][r][col][0];     t0[r] = g_st[3][r][col][1];
    s1[r] = g_st[3][r][col + 1][0]; t1[r] = g_st[3][r][col + 1][1];
    aw[r] = att[r];
  }
  int s = g_noff[n], cnt = g_ncnt[n];
  float a0 = 0.f, a1 = 0.f;
  for (int k = 0; k < cnt; k++){
    int e = g_nbkt[s + k];
    u32 pr = g_invr[e];
    int row = pr & 0xFFFFF;
    int r = pr >> 20;
    u32 hv = *(const u32*)&g_hB16[(size_t)row * HID + col];
    float2 f = __half22float2(*(__half2*)&hv);
    a0 += fmaxf(fmaf(f.x, s0[r], t0[r]), 0.f) * aw[r];
    a1 += fmaxf(fmaf(f.y, s1[r], t1[r]), 0.f) * aw[r];
  }
  *(float2*)&out[(size_t)n * HID + col] = make_float2(a0, a1);
}

// ---------------- launch ----------------
extern "C" void kernel_launch(void* const* d_in, const int* in_sizes, int n_in,
                              void* d_out, int out_size){
  const float* nf    = (const float*)d_in[0];
  const float* geo   = (const float*)d_in[1];
  const int*   ei    = (const int*)d_in[2];
  const int*   eij   = (const int*)d_in[3];
  const int*   ejk   = (const int*)d_in[4];
  const int*   nei   = (const int*)d_in[5];
  const float* att   = (const float*)d_in[6];
  const float* W0    = (const float*)d_in[7];
  const float* b0    = (const float*)d_in[8];
  const float* W     = (const float*)d_in[9];
  const float* b     = (const float*)d_in[10];
  const float* gamma = (const float*)d_in[11];
  const float* beta  = (const float*)d_in[12];
  float* out = (float*)d_out;

  cudaFuncSetAttribute(k_gemm0,    cudaFuncAttributeMaxDynamicSharedMemorySize, SMEM_NEED);
  cudaFuncSetAttribute(k_gemml<1>, cudaFuncAttributeMaxDynamicSharedMemorySize, SMEM_NEED);
  cudaFuncSetAttribute(k_gemml<2>, cudaFuncAttributeMaxDynamicSharedMemorySize, SMEM_NEED);
  cudaFuncSetAttribute(k_gemml<3>, cudaFuncAttributeMaxDynamicSharedMemorySize, SMEM_NEED);

  k_setup<<<SETUP_GRID, 256>>>(eij, ejk, nei, ei, W0, W, nf, geo);  // L1
  k_offsets2<<<1, 1024>>>();                                         // L2
  k_permprep<<<E_ / 256, 256>>>(ei);                                 // L3
  k_gemm0<<<GRID_G2, 256, SMEM_NEED>>>(ei, b0);                      // L4 <- ncu window
  k_finalize<<<1, 512>>>(0, gamma, beta);
  k_gemml<1><<<LGRID, 256, SMEM_NEED>>>(b);
  k_finalize<<<1, 512>>>(1, gamma, beta);
  k_gemml<2><<<LGRID, 256, SMEM_NEED>>>(b);
  k_finalize<<<1, 512>>>(2, gamma, beta);
  k_gemml<3><<<LGRID, 256, SMEM_NEED>>>(b);
  k_finalize<<<1, 512>>>(3, gamma, beta);
  k_out<<<N_, 64>>>(att, out);
}

// round 13
// speedup vs baseline: 1.2529x; 1.0081x over previous
#include <cuda_runtime.h>
#include <cuda_fp16.h>

#define HID 128
#define E_ 262144
#define N_ 32768
#define GEO_ 13
#define ROWS_MAX (E_ + 512)
#define SETUP_BLKS 1026
#define WPREP_BLKS 1568
#define NF16_BLKS 2048
#define GEO16_BLKS 1024
#define SETUP_GRID (SETUP_BLKS + WPREP_BLKS + NF16_BLKS + GEO16_BLKS)
#define G0GRID 148
#define LGRID 296

typedef unsigned long long u64;
typedef unsigned int u32;

#define SA 136
#define A_CH 17408                  // 64 x SA fp16
#define B_CH 34816                  // 128 x SA fp16
// gemm0 smem: B0..B2 | Bgeo | A stages (3 chunks + geo each)
#define G0_OFF_B 0
#define G0_OFF_BG (3 * B_CH)        // 104448
#define G0_OFF_A (G0_OFF_BG + 4096) // 108544
#define G0_ASTRIDE (3 * A_CH + 2048)// 54272
#define G0_SMEM (G0_OFF_A + 2 * G0_ASTRIDE)  // 217088
// layer smem: B | A stages
#define L_OFF_B 0
#define L_OFF_A B_CH
#define L_SMEM (B_CH + 2 * A_CH)    // 69632

// ---------------- scratch ----------------
__device__ __half g_hA16[(size_t)ROWS_MAX * HID];
__device__ __half g_hB16[(size_t)ROWS_MAX * HID];
__device__ __half g_nf16[(size_t)N_ * HID];
__device__ __half g_geo16[(size_t)E_ * 16];
__device__ __half g_Wh[4 * 3 * 16384];
__device__ __half g_W0h[4 * 3 * 16384];
__device__ __half g_W0gh[4 * 2048];
__device__ int   g_perm[ROWS_MAX];
__device__ u32   g_invr[E_];
__device__ int   g_route[E_];
__device__ int   g_cnt[4];
__device__ int   g_cur[4];
__device__ int   g_bnd[5];
__device__ float g_cntf[4];
__device__ float g_stats[4][4][HID][2];
__device__ int   g_ncnt[N_];
__device__ int   g_ncur[N_];
__device__ int   g_noff[N_];
__device__ int   g_nbkt[E_];

// ---------------- helpers ----------------
__device__ __forceinline__ u32 smem_u32(const void* p){
  u32 a; asm("{ .reg .u64 t; cvta.to.shared.u64 t, %1; cvt.u32.u64 %0, t; }" : "=r"(a) : "l"(p));
  return a;
}
#define CP_ASYNC16(dst, src) asm volatile("cp.async.ca.shared.global [%0], [%1], 16;" :: "r"(dst), "l"(src))
#define CP_COMMIT() asm volatile("cp.async.commit_group;" ::: "memory")
#define CP_WAIT0() asm volatile("cp.async.wait_group 0;" ::: "memory")

__device__ __forceinline__ void ldm4(u32& r0, u32& r1, u32& r2, u32& r3, u32 addr){
  asm volatile("ldmatrix.sync.aligned.m8n8.x4.shared.b16 {%0,%1,%2,%3}, [%4];"
               : "=r"(r0), "=r"(r1), "=r"(r2), "=r"(r3) : "r"(addr));
}
__device__ __forceinline__ void mma16816(float* d, const u32* a, u32 b0, u32 b1){
  asm volatile("mma.sync.aligned.m16n8k16.row.col.f32.f16.f16.f32 "
               "{%0,%1,%2,%3}, {%4,%5,%6,%7}, {%8,%9}, {%0,%1,%2,%3};"
               : "+f"(d[0]), "+f"(d[1]), "+f"(d[2]), "+f"(d[3])
               : "r"(a[0]), "r"(a[1]), "r"(a[2]), "r"(a[3]), "r"(b0), "r"(b1));
}

// ---------------- L1: setup + weight prep + fp16 conversions ----------------
__global__ void k_setup(const int* __restrict__ eij, const int* __restrict__ ejk,
                        const int* __restrict__ nei_ptr, const int* __restrict__ ei,
                        const float* __restrict__ W0, const float* __restrict__ W,
                        const float* __restrict__ nf, const float* __restrict__ geo){
  int bid = blockIdx.x, tid = threadIdx.x;
  if (bid < SETUP_BLKS){
    int idx = bid * 256 + tid;
    if (idx < ROWS_MAX) g_perm[idx] = -1;
    if (idx < 4096) ((float*)g_stats)[idx] = 0.f;
    if (idx < 4){ g_cnt[idx] = 0; g_cur[idx] = 0; }
    if (idx < N_){ g_ncnt[idx] = 0; g_ncur[idx] = 0; }
    if (idx < E_){
      int nei = nei_ptr[0];
      int r = ((eij[idx] < nei) ? 0 : 2) | ((ejk[idx] < nei) ? 0 : 1);
      g_route[idx] = r;
      int lane = tid & 31;
      #pragma unroll
      for (int rr = 0; rr < 4; rr++){
        unsigned m = __ballot_sync(0xFFFFFFFFu, r == rr);
        if (r == rr && lane == (__ffs(m) - 1)) atomicAdd(&g_cnt[rr], __popc(m));
      }
      atomicAdd(&g_ncnt[ei[idx]], 1);
    }
  } else if (bid < SETUP_BLKS + WPREP_BLKS){
    int idx = (bid - SETUP_BLKS) * 256 + tid;
    const int NL = 4 * 3 * 16384;
    if (idx < NL){
      int rl = idx / 16384, rem = idx & 16383;
      int n = rem >> 7, k = rem & 127;
      g_Wh[idx] = __float2half_rn(W[((size_t)(rl * 128 + n)) * 128 + k]);
    } else if (idx < 2 * NL){
      int t2 = idx - NL;
      int rc = t2 / 16384, rem = t2 & 16383;
      int r = rc / 3, c = rc % 3;
      int n = rem >> 7, k = rem & 127;
      g_W0h[t2] = __float2half_rn(W0[((size_t)(r * 128 + n)) * 397 + c * 128 + k]);
    } else {
      int t2 = idx - 2 * NL;
      int r = t2 / 2048, rem = t2 & 2047;
      int n = rem >> 4, k = rem & 15;
      int ko = 384 + k;
      float v = (ko < 397) ? W0[((size_t)(r * 128 + n)) * 397 + ko] : 0.f;
      g_W0gh[t2] = __float2half_rn(v);
    }
  } else if (bid < SETUP_BLKS + WPREP_BLKS + NF16_BLKS){
    int idx = (bid - SETUP_BLKS - WPREP_BLKS) * 256 + tid;
    size_t base = (size_t)idx * 8;
    float4 v0 = *(const float4*)&nf[base];
    float4 v1 = *(const float4*)&nf[base + 4];
    __half2 a = __floats2half2_rn(v0.x, v0.y);
    __half2 b = __floats2half2_rn(v0.z, v0.w);
    __half2 c = __floats2half2_rn(v1.x, v1.y);
    __half2 d = __floats2half2_rn(v1.z, v1.w);
    uint4 o; o.x = *(u32*)&a; o.y = *(u32*)&b; o.z = *(u32*)&c; o.w = *(u32*)&d;
    *(uint4*)&g_nf16[base] = o;
  } else {
    int e = (bid - SETUP_BLKS - WPREP_BLKS - NF16_BLKS) * 256 + tid;
    const float* gp = geo + (size_t)e * GEO_;
    __half h[16];
    #pragma unroll
    for (int c = 0; c < 16; c++) h[c] = (c < GEO_) ? __float2half_rn(gp[c]) : __float2half_rn(0.f);
    uint4* dst = (uint4*)&g_geo16[(size_t)e * 16];
    dst[0] = *(uint4*)&h[0];
    dst[1] = *(uint4*)&h[8];
  }
}

// ---------------- L2: route offsets + node prefix sum ----------------
__global__ void k_offsets2(){
  __shared__ int part[1024];
  int t = threadIdx.x;
  if (t == 0){
    int b = 0;
    #pragma unroll
    for (int r = 0; r < 4; r++){
      g_bnd[r] = b;
      int c = g_cnt[r];
      b += ((c + 127) / 128) * 128;
      g_cntf[r] = (c > 0) ? (float)c : 1.0f;
    }
    g_bnd[4] = b;
  }
  int base = t * 32;
  int loc[32], s = 0;
  #pragma unroll
  for (int j = 0; j < 32; j++){ loc[j] = s; s += g_ncnt[base + j]; }
  part[t] = s;
  __syncthreads();
  for (int off = 1; off < 1024; off <<= 1){
    int v = (t >= off) ? part[t - off] : 0;
    __syncthreads();
    part[t] += v;
    __syncthreads();
  }
  int excl = part[t] - s;
  #pragma unroll
  for (int j = 0; j < 32; j++) g_noff[base + j] = excl + loc[j];
}

// ---------------- L3: permutation + node buckets ----------------
__global__ void k_permprep(const int* __restrict__ ei){
  int e = blockIdx.x * 256 + threadIdx.x;
  int r = g_route[e];
  int lane = threadIdx.x & 31;
  #pragma unroll
  for (int rr = 0; rr < 4; rr++){
    unsigned m = __ballot_sync(0xFFFFFFFFu, r == rr);
    if (r == rr){
      int leader = __ffs(m) - 1;
      int base = 0;
      if (lane == leader) base = atomicAdd(&g_cur[rr], __popc(m));
      base = __shfl_sync(m, base, leader);
      unsigned lt = (lane == 0) ? 0u : (0xFFFFFFFFu >> (32 - lane));
      int pos = g_bnd[rr] + base + __popc(m & lt);
      g_perm[pos] = e;
      g_invr[e] = (u32)pos | ((u32)rr << 20);
    }
  }
  int i = ei[e];
  int slot = g_noff[i] + atomicAdd(&g_ncur[i], 1);
  g_nbkt[slot] = e;
}

// ---------------- fragment loads (stride-templated) ----------------
template<int AS>
__device__ __forceinline__ void loadA(u32 abase, int mw, int lane, int k0, u32 a[2][4]){
  #pragma unroll
  for (int im = 0; im < 2; im++){
    int row = mw + im * 16 + (lane & 15);
    int col = k0 + ((lane >> 4) << 3);
    ldm4(a[im][0], a[im][1], a[im][2], a[im][3], abase + (u32)(row * AS + col) * 2);
  }
}
template<int BS>
__device__ __forceinline__ void loadB(u32 bbase, int nw, int lane, int k0, u32 b[4][2]){
  int brow = nw + ((lane >> 4) << 3) + (lane & 7);
  int bcol = k0 + (((lane >> 3) & 1) << 3);
  #pragma unroll
  for (int g = 0; g < 2; g++){
    ldm4(b[2*g][0], b[2*g][1], b[2*g+1][0], b[2*g+1][1],
         bbase + (u32)((brow + g * 16) * BS + bcol) * 2);
  }
}
template<int NK, int AS, int BS>
__device__ __forceinline__ void mma_chunk(u32 abase, u32 bbase, int mw, int nw, int lane,
                                          float acc[2][4][4]){
  u32 a[2][2][4];
  loadA<AS>(abase, mw, lane, 0, a[0]);
  #pragma unroll
  for (int ks = 0; ks < NK; ks++){
    int cur = ks & 1;
    u32 b[4][2];
    loadB<BS>(bbase, nw, lane, ks * 16, b);
    if (ks + 1 < NK) loadA<AS>(abase, mw, lane, (ks + 1) * 16, a[cur ^ 1]);
    #pragma unroll
    for (int im = 0; im < 2; im++)
      #pragma unroll
      for (int in = 0; in < 4; in++)
        mma16816(acc[im][in], a[cur][im], b[in][0], b[in][1]);
  }
}

// ---------------- epilogue: bias + fp16 store + fused BN stats ----------------
__device__ __forceinline__ void epilogue_mma(float acc[2][4][4], const float* __restrict__ biasp,
                                             __half* __restrict__ hout,
                                             int m0, int mw, int nw, int lane,
                                             int r, int layer, int nval){
  int gid = lane >> 2, tig = lane & 3;
  float sum[4][2], sq[4][2];
  #pragma unroll
  for (int in = 0; in < 4; in++){ sum[in][0] = sum[in][1] = sq[in][0] = sq[in][1] = 0.f; }
  #pragma unroll
  for (int im = 0; im < 2; im++){
    int lr0 = mw + im * 16 + gid;
    bool v0 = lr0 < nval, v1 = (lr0 + 8) < nval;
    #pragma unroll
    for (int in = 0; in < 4; in++){
      float* d = acc[im][in];
      int col = nw + in * 8 + tig * 2;
      float2 bv = *(const float2*)&biasp[col];
      float e0 = d[0] + bv.x, e1 = d[1] + bv.y, e2 = d[2] + bv.x, e3 = d[3] + bv.y;
      __half2 p01 = __floats2half2_rn(e0, e1);
      __half2 p23 = __floats2half2_rn(e2, e3);
      *(u32*)&hout[(size_t)(m0 + lr0) * HID + col]     = *(u32*)&p01;
      *(u32*)&hout[(size_t)(m0 + lr0 + 8) * HID + col] = *(u32*)&p23;
      float m0v = v0 ? e0 : 0.f, m1v = v0 ? e1 : 0.f;
      float m2v = v1 ? e2 : 0.f, m3v = v1 ? e3 : 0.f;
      sum[in][0] += m0v + m2v; sum[in][1] += m1v + m3v;
      sq[in][0]  += m0v * m0v + m2v * m2v;
      sq[in][1]  += m1v * m1v + m3v * m3v;
    }
  }
  #pragma unroll
  for (int off = 4; off <= 16; off <<= 1){
    #pragma unroll
    for (int in = 0; in < 4; in++){
      sum[in][0] += __shfl_xor_sync(0xFFFFFFFFu, sum[in][0], off);
      sum[in][1] += __shfl_xor_sync(0xFFFFFFFFu, sum[in][1], off);
      sq[in][0]  += __shfl_xor_sync(0xFFFFFFFFu, sq[in][0], off);
      sq[in][1]  += __shfl_xor_sync(0xFFFFFFFFu, sq[in][1], off);
    }
  }
  if (gid == 0){
    #pragma unroll
    for (int in = 0; in < 4; in++){
      int col = nw + in * 8 + tig * 2;
      atomicAdd(&g_stats[layer][r][col][0], sum[in][0]);
      atomicAdd(&g_stats[layer][r][col][1], sq[in][0]);
      atomicAdd(&g_stats[layer][r][col + 1][0], sum[in][1]);
      atomicAdd(&g_stats[layer][r][col + 1][1], sq[in][1]);
    }
  }
}

// ---------------- gemm0 prefetchers ----------------
__device__ __forceinline__ void g0_loadB(u32 sb, int r, int tid){
  #pragma unroll
  for (int c = 0; c < 3; c++){
    const __half* w = g_W0h + (r * 3 + c) * 16384;
    #pragma unroll
    for (int j = 0; j < 8; j++){
      int i = j * 256 + tid;
      int row = i >> 4, seg = i & 15;
      CP_ASYNC16(sb + G0_OFF_B + c * B_CH + (u32)(row * SA + seg * 8) * 2, w + row * 128 + seg * 8);
    }
  }
  {
    int row = tid >> 1, seg = tid & 1;
    CP_ASYNC16(sb + G0_OFF_BG + (u32)(row * 16 + seg * 8) * 2,
               g_W0gh + r * 2048 + row * 16 + seg * 8);
  }
}
__device__ __forceinline__ void g0_prefA(u32 abase, const int (*nodes)[64], const int* eids, int tid){
  #pragma unroll
  for (int c = 0; c < 3; c++){
    #pragma unroll
    for (int j = 0; j < 4; j++){
      int i = j * 256 + tid;
      int row = i >> 4, seg = i & 15;
      CP_ASYNC16(abase + c * A_CH + (u32)(row * SA + seg * 8) * 2,
                 g_nf16 + (size_t)nodes[c][row] * 128 + seg * 8);
    }
  }
  if (tid < 128){
    int row = tid >> 1, seg = tid & 1;
    CP_ASYNC16(abase + 3 * A_CH + (u32)(row * 16 + seg * 8) * 2,
               g_geo16 + (size_t)eids[row] * 16 + seg * 8);
  }
}

// ---------------- L4 (PROFILED): GEMM layer 0 — persistent, B-resident ----------
__global__ __launch_bounds__(256, 1)
void k_gemm0(const int* __restrict__ ei, const float* __restrict__ b0){
  extern __shared__ char bp[];
  __shared__ int sN[2][3][64];
  __shared__ int sE2[2][64];
  u32 sb = smem_u32(bp);
  int tid = threadIdx.x, wid = tid >> 5, lane = tid & 31;
  int mw = (wid & 1) * 32, nw = (wid >> 1) * 32;
  int bnd1 = g_bnd[1], bnd2 = g_bnd[2], bnd3 = g_bnd[3], bnd4 = g_bnd[4];
  int ntiles = bnd4 >> 6;
  int G = gridDim.x;
  int t = blockIdx.x;
  if (t >= ntiles) return;

  // load nodes(t) into buf0
  if (tid < 64){
    int e = g_perm[(t << 6) + tid];
    int ec = (e < 0) ? 0 : e;
    sN[0][0][tid] = (e < 0) ? 0 : ei[ec];
    sN[0][1][tid] = (e < 0) ? 0 : ei[E_ + ec];
    sN[0][2][tid] = (e < 0) ? 0 : ei[2 * E_ + ec];
    sE2[0][tid] = ec;
  }
  __syncthreads();
  int m00 = t << 6;
  int curR = (m00 >= bnd1) + (m00 >= bnd2) + (m00 >= bnd3);
  g0_loadB(sb, curR, tid);
  g0_prefA(sb + G0_OFF_A, sN[0], sE2[0], tid);
  CP_COMMIT();
  // load nodes(t+G) into buf1
  if (tid < 64 && t + G < ntiles){
    int e = g_perm[((t + G) << 6) + tid];
    int ec = (e < 0) ? 0 : e;
    sN[1][0][tid] = (e < 0) ? 0 : ei[ec];
    sN[1][1][tid] = (e < 0) ? 0 : ei[E_ + ec];
    sN[1][2][tid] = (e < 0) ? 0 : ei[2 * E_ + ec];
    sE2[1][tid] = ec;
  }

  int st = 0, p = 0;
  for (; t < ntiles; t += G, st ^= 1, p ^= 1){
    int m0 = t << 6;
    int r = curR;
    CP_WAIT0();
    __syncthreads();                       // stage st + B ready; node buf p^1 ready
    int tn = t + G;
    bool early = false;
    int rn = r;
    if (tn < ntiles){
      int mn = tn << 6;
      rn = (mn >= bnd1) + (mn >= bnd2) + (mn >= bnd3);
      if (rn == r){
        g0_prefA(sb + G0_OFF_A + (st ^ 1) * G0_ASTRIDE, sN[p ^ 1], sE2[p ^ 1], tid);
        CP_COMMIT();
        early = true;
      }
    }
    // mma: 3 resident chunks + geo
    float acc[2][4][4];
    #pragma unroll
    for (int im = 0; im < 2; im++)
      #pragma unroll
      for (int in = 0; in < 4; in++)
        #pragma unroll
        for (int tt = 0; tt < 4; tt++) acc[im][in][tt] = 0.f;
    u32 abase = sb + G0_OFF_A + st * G0_ASTRIDE;
    #pragma unroll
    for (int c = 0; c < 3; c++)
      mma_chunk<8, SA, SA>(abase + c * A_CH, sb + G0_OFF_B + c * B_CH, mw, nw, lane, acc);
    mma_chunk<1, 16, 16>(abase + 3 * A_CH, sb + G0_OFF_BG, mw, nw, lane, acc);

    int nv = g_bnd[r] + g_cnt[r] - m0;
    nv = (nv < 0) ? 0 : ((nv > 64) ? 64 : nv);
    epilogue_mma(acc, b0 + r * HID, g_hA16, m0, mw, nw, lane, r, 0, nv);

    // load nodes(t+2G) into buf p
    if (tid < 64 && t + 2 * G < ntiles){
      int e = g_perm[((t + 2 * G) << 6) + tid];
      int ec = (e < 0) ? 0 : e;
      sN[p][0][tid] = (e < 0) ? 0 : ei[ec];
      sN[p][1][tid] = (e < 0) ? 0 : ei[E_ + ec];
      sN[p][2][tid] = (e < 0) ? 0 : ei[2 * E_ + ec];
      sE2[p][tid] = ec;
    }
    if (!early && tn < ntiles){
      __syncthreads();                     // all warps done with B before reload
      curR = rn;
      g0_loadB(sb, curR, tid);
      g0_prefA(sb + G0_OFF_A + (st ^ 1) * G0_ASTRIDE, sN[p ^ 1], sE2[p ^ 1], tid);
      CP_COMMIT();
    }
  }
}

// ---------------- layers 1..3: persistent, B-resident, in-block finalize -------
template<int LI>
__global__ __launch_bounds__(256, 2)
void k_gemml(const float* __restrict__ bArr,
             const float* __restrict__ gamma, const float* __restrict__ beta){
  const __half* hin  = (LI & 1) ? g_hA16 : g_hB16;
  __half*       hout = (LI & 1) ? g_hB16 : g_hA16;
  extern __shared__ char bp[];
  __shared__ float2 sST[4][128];
  u32 sb = smem_u32(bp);
  int tid = threadIdx.x, wid = tid >> 5, lane = tid & 31;
  int mw = (wid & 1) * 32, nw = (wid >> 1) * 32;
  int c4 = (tid & 31) << 2;
  int bnd1 = g_bnd[1], bnd2 = g_bnd[2], bnd3 = g_bnd[3], bnd4 = g_bnd[4];
  int ntiles = bnd4 >> 6;
  int G = gridDim.x;
  const __half* wb = g_Wh + (LI - 1) * 16384;

  // in-block BN finalize for layer LI-1
  #pragma unroll
  for (int it = tid; it < 512; it += 256){
    int r = it >> 7, c = it & 127;
    float cnt  = g_cntf[r];
    float mean = g_stats[LI - 1][r][c][0] / cnt;
    float var  = fmaxf(g_stats[LI - 1][r][c][1] / cnt - mean * mean, 0.f);
    float inv  = rsqrtf(var + 1e-5f);
    float s    = gamma[(r * 4 + LI - 1) * HID + c] * inv;
    sST[r][c] = make_float2(s, beta[(r * 4 + LI - 1) * HID + c] - mean * s);
  }

  int t = blockIdx.x;
  if (t >= ntiles) return;
  int m00 = t << 6;
  int curR = (m00 >= bnd1) + (m00 >= bnd2) + (m00 >= bnd3);
  // B resident + first A
  {
    #pragma unroll
    for (int j = 0; j < 8; j++){
      int i = j * 256 + tid;
      int row = i >> 4, seg = i & 15;
      CP_ASYNC16(sb + L_OFF_B + (u32)(row * SA + seg * 8) * 2,
                 wb + curR * 3 * 16384 + row * 128 + seg * 8);
    }
    #pragma unroll
    for (int j = 0; j < 4; j++){
      int i = j * 256 + tid;
      int row = i >> 4, seg = i & 15;
      CP_ASYNC16(sb + L_OFF_A + (u32)(row * SA + seg * 8) * 2,
                 hin + (size_t)m00 * HID + (size_t)row * 128 + seg * 8);
    }
    CP_COMMIT();
  }

  int st = 0;
  for (; t < ntiles; t += G, st ^= 1){
    int m0 = t << 6;
    int r = curR;
    CP_WAIT0();
    __syncthreads();                       // covers sST too (first iteration)
    int tn = t + G;
    bool early = false;
    int rn = r;
    if (tn < ntiles){
      int mn = tn << 6;
      rn = (mn >= bnd1) + (mn >= bnd2) + (mn >= bnd3);
      if (rn == r){
        #pragma unroll
        for (int j = 0; j < 4; j++){
          int i = j * 256 + tid;
          int row = i >> 4, seg = i & 15;
          CP_ASYNC16(sb + L_OFF_A + (st ^ 1) * A_CH + (u32)(row * SA + seg * 8) * 2,
                     hin + (size_t)mn * HID + (size_t)row * 128 + seg * 8);
        }
        CP_COMMIT();
        early = true;
      }
    }
    // in-place BN+relu convert of A stage
    char* abase = bp + L_OFF_A + st * A_CH;
    #pragma unroll
    for (int j = 0; j < 8; j++){
      int row = j * 8 + (tid >> 5);
      char* ap = abase + (u32)(row * SA + c4) * 2;
      uint2 hv = *(uint2*)ap;
      float2 f01 = __half22float2(*(__half2*)&hv.x);
      float2 f23 = __half22float2(*(__half2*)&hv.y);
      float2 s0 = *(float2*)&sST[r][c4];
      float2 s1 = *(float2*)&sST[r][c4 + 1];
      float2 s2 = *(float2*)&sST[r][c4 + 2];
      float2 s3 = *(float2*)&sST[r][c4 + 3];
      __half2 a01 = __floats2half2_rn(fmaxf(fmaf(f01.x, s0.x, s0.y), 0.f),
                                      fmaxf(fmaf(f01.y, s1.x, s1.y), 0.f));
      __half2 a23 = __floats2half2_rn(fmaxf(fmaf(f23.x, s2.x, s2.y), 0.f),
                                      fmaxf(fmaf(f23.y, s3.x, s3.y), 0.f));
      *(uint2*)ap = make_uint2(*(u32*)&a01, *(u32*)&a23);
    }
    __syncthreads();                       // convert done before ldmatrix

    float acc[2][4][4];
    #pragma unroll
    for (int im = 0; im < 2; im++)
      #pragma unroll
      for (int in = 0; in < 4; in++)
        #pragma unroll
        for (int tt = 0; tt < 4; tt++) acc[im][in][tt] = 0.f;
    mma_chunk<8, SA, SA>(sb + L_OFF_A + st * A_CH, sb + L_OFF_B, mw, nw, lane, acc);

    int nv = g_bnd[r] + g_cnt[r] - m0;
    nv = (nv < 0) ? 0 : ((nv > 64) ? 64 : nv);
    epilogue_mma(acc, bArr + (r * 3 + (LI - 1)) * HID, hout, m0, mw, nw, lane, r, LI, nv);

    if (!early && tn < ntiles){
      __syncthreads();                     // mma done with B before reload
      curR = rn;
      int mn = tn << 6;
      #pragma unroll
      for (int j = 0; j < 8; j++){
        int i = j * 256 + tid;
        int row = i >> 4, seg = i & 15;
        CP_ASYNC16(sb + L_OFF_B + (u32)(row * SA + seg * 8) * 2,
                   wb + curR * 3 * 16384 + row * 128 + seg * 8);
      }
      #pragma unroll
      for (int j = 0; j < 4; j++){
        int i = j * 256 + tid;
        int row = i >> 4, seg = i & 15;
        CP_ASYNC16(sb + L_OFF_A + (st ^ 1) * A_CH + (u32)(row * SA + seg * 8) * 2,
                   hin + (size_t)mn * HID + (size_t)row * 128 + seg * 8);
      }
      CP_COMMIT();
    }
  }
}

// ---------------- output: node-bucketed gather, in-block finalize ----------------
__global__ void k_out(const float* __restrict__ att, const float* __restrict__ gamma,
                      const float* __restrict__ beta, float* __restrict__ out){
  int n = blockIdx.x, t = threadIdx.x;
  int col = t * 2;
  float s0[4], t0[4], s1[4], t1[4], aw[4];
  #pragma unroll
  for (int r = 0; r < 4; r++){
    float cnt = g_cntf[r];
    float mean0 = g_stats[3][r][col][0] / cnt;
    float var0  = fmaxf(g_stats[3][r][col][1] / cnt - mean0 * mean0, 0.f);
    float g0v = gamma[(r * 4 + 3) * HID + col];
    s0[r] = g0v * rsqrtf(var0 + 1e-5f);
    t0[r] = beta[(r * 4 + 3) * HID + col] - mean0 * s0[r];
    float mean1 = g_stats[3][r][col + 1][0] / cnt;
    float var1  = fmaxf(g_stats[3][r][col + 1][1] / cnt - mean1 * mean1, 0.f);
    float g1v = gamma[(r * 4 + 3) * HID + col + 1];
    s1[r] = g1v * rsqrtf(var1 + 1e-5f);
    t1[r] = beta[(r * 4 + 3) * HID + col + 1] - mean1 * s1[r];
    aw[r] = att[r];
  }
  int s = g_noff[n], cnt = g_ncnt[n];
  float a0 = 0.f, a1 = 0.f;
  for (int k = 0; k < cnt; k++){
    int e = g_nbkt[s + k];
    u32 pr = g_invr[e];
    int row = pr & 0xFFFFF;
    int r = pr >> 20;
    u32 hv = *(const u32*)&g_hB16[(size_t)row * HID + col];
    float2 f = __half22float2(*(__half2*)&hv);
    a0 += fmaxf(fmaf(f.x, s0[r], t0[r]), 0.f) * aw[r];
    a1 += fmaxf(fmaf(f.y, s1[r], t1[r]), 0.f) * aw[r];
  }
  *(float2*)&out[(size_t)n * HID + col] = make_float2(a0, a1);
}

// ---------------- launch ----------------
extern "C" void kernel_launch(void* const* d_in, const int* in_sizes, int n_in,
                              void* d_out, int out_size){
  const float* nf    = (const float*)d_in[0];
  const float* geo   = (const float*)d_in[1];
  const int*   ei    = (const int*)d_in[2];
  const int*   eij   = (const int*)d_in[3];
  const int*   ejk   = (const int*)d_in[4];
  const int*   nei   = (const int*)d_in[5];
  const float* att   = (const float*)d_in[6];
  const float* W0    = (const float*)d_in[7];
  const float* b0    = (const float*)d_in[8];
  const float* W     = (const float*)d_in[9];
  const float* b     = (const float*)d_in[10];
  const float* gamma = (const float*)d_in[11];
  const float* beta  = (const float*)d_in[12];
  float* out = (float*)d_out;

  cudaFuncSetAttribute(k_gemm0,    cudaFuncAttributeMaxDynamicSharedMemorySize, G0_SMEM);
  cudaFuncSetAttribute(k_gemml<1>, cudaFuncAttributeMaxDynamicSharedMemorySize, L_SMEM);
  cudaFuncSetAttribute(k_gemml<2>, cudaFuncAttributeMaxDynamicSharedMemorySize, L_SMEM);
  cudaFuncSetAttribute(k_gemml<3>, cudaFuncAttributeMaxDynamicSharedMemorySize, L_SMEM);

  k_setup<<<SETUP_GRID, 256>>>(eij, ejk, nei, ei, W0, W, nf, geo);  // L1
  k_offsets2<<<1, 1024>>>();                                         // L2
  k_permprep<<<E_ / 256, 256>>>(ei);                                 // L3
  k_gemm0<<<G0GRID, 256, G0_SMEM>>>(ei, b0);                         // L4 <- ncu window
  k_gemml<1><<<LGRID, 256, L_SMEM>>>(b, gamma, beta);                // L5
  k_gemml<2><<<LGRID, 256, L_SMEM>>>(b, gamma, beta);                // L6
  k_gemml<3><<<LGRID, 256, L_SMEM>>>(b, gamma, beta);                // L7
  k_out<<<N_, 64>>>(att, gamma, beta, out);                          // L8
}

// round 14
// speedup vs baseline: 1.2560x; 1.0025x over previous
#include <cuda_runtime.h>
#include <cuda_fp16.h>

#define HID 128
#define E_ 262144
#define N_ 32768
#define GEO_ 13
#define ROWS_MAX (E_ + 512)
#define SETUP_BLKS 1026
#define WPREP_BLKS 1568
#define NF16_BLKS 2048
#define GEO16_BLKS 1024
#define SETUP_GRID (SETUP_BLKS + WPREP_BLKS + NF16_BLKS + GEO16_BLKS)
#define G0GRID 148
#define LGRID 296

typedef unsigned long long u64;
typedef unsigned int u32;

#define SA 136
#define A_CH 17408                  // 64 x SA fp16
#define B_CH 34816                  // 128 x SA fp16
#define G0_OFF_B 0
#define G0_OFF_BG (3 * B_CH)
#define G0_OFF_A (G0_OFF_BG + 4096)
#define G0_ASTRIDE (3 * A_CH + 2048)
#define G0_SMEM (G0_OFF_A + 2 * G0_ASTRIDE)  // 217088
#define L_OFF_B 0
#define L_OFF_A B_CH
#define L_SMEM (B_CH + 2 * A_CH)    // 69632

// ---------------- scratch ----------------
__device__ __half g_hA16[(size_t)ROWS_MAX * HID];
__device__ __half g_hB16[(size_t)ROWS_MAX * HID];
__device__ __half g_nf16[(size_t)N_ * HID];
__device__ __half g_geo16[(size_t)E_ * 16];
__device__ __half g_Wh[4 * 3 * 16384];
__device__ __half g_W0h[4 * 3 * 16384];
__device__ __half g_W0gh[4 * 2048];
__device__ int   g_perm[ROWS_MAX];
__device__ int   g_route[E_];
__device__ int   g_cnt[4];
__device__ int   g_cur[4];
__device__ int   g_bnd[5];
__device__ float g_cntf[4];
__device__ float g_stats[4][4][HID][2];
__device__ int   g_ncnt[N_];
__device__ int   g_ncur[N_];
__device__ int   g_noff[N_];
__device__ u32   g_nbkt[E_];        // packed row | route<<20

// ---------------- helpers ----------------
__device__ __forceinline__ u32 smem_u32(const void* p){
  u32 a; asm("{ .reg .u64 t; cvta.to.shared.u64 t, %1; cvt.u32.u64 %0, t; }" : "=r"(a) : "l"(p));
  return a;
}
#define CP_ASYNC16(dst, src) asm volatile("cp.async.ca.shared.global [%0], [%1], 16;" :: "r"(dst), "l"(src))
#define CP_COMMIT() asm volatile("cp.async.commit_group;" ::: "memory")
#define CP_WAIT0() asm volatile("cp.async.wait_group 0;" ::: "memory")

__device__ __forceinline__ void ldm4(u32& r0, u32& r1, u32& r2, u32& r3, u32 addr){
  asm volatile("ldmatrix.sync.aligned.m8n8.x4.shared.b16 {%0,%1,%2,%3}, [%4];"
               : "=r"(r0), "=r"(r1), "=r"(r2), "=r"(r3) : "r"(addr));
}
__device__ __forceinline__ void mma16816(float* d, const u32* a, u32 b0, u32 b1){
  asm volatile("mma.sync.aligned.m16n8k16.row.col.f32.f16.f16.f32 "
               "{%0,%1,%2,%3}, {%4,%5,%6,%7}, {%8,%9}, {%0,%1,%2,%3};"
               : "+f"(d[0]), "+f"(d[1]), "+f"(d[2]), "+f"(d[3])
               : "r"(a[0]), "r"(a[1]), "r"(a[2]), "r"(a[3]), "r"(b0), "r"(b1));
}

// ---------------- L1: setup + weight prep + fp16 conversions ----------------
__global__ void k_setup(const int* __restrict__ eij, const int* __restrict__ ejk,
                        const int* __restrict__ nei_ptr, const int* __restrict__ ei,
                        const float* __restrict__ W0, const float* __restrict__ W,
                        const float* __restrict__ nf, const float* __restrict__ geo){
  int bid = blockIdx.x, tid = threadIdx.x;
  if (bid < SETUP_BLKS){
    int idx = bid * 256 + tid;
    if (idx < ROWS_MAX) g_perm[idx] = -1;
    if (idx < 4096) ((float*)g_stats)[idx] = 0.f;
    if (idx < 4){ g_cnt[idx] = 0; g_cur[idx] = 0; }
    if (idx < N_){ g_ncnt[idx] = 0; g_ncur[idx] = 0; }
    if (idx < E_){
      int nei = nei_ptr[0];
      int r = ((eij[idx] < nei) ? 0 : 2) | ((ejk[idx] < nei) ? 0 : 1);
      g_route[idx] = r;
      int lane = tid & 31;
      #pragma unroll
      for (int rr = 0; rr < 4; rr++){
        unsigned m = __ballot_sync(0xFFFFFFFFu, r == rr);
        if (r == rr && lane == (__ffs(m) - 1)) atomicAdd(&g_cnt[rr], __popc(m));
      }
      atomicAdd(&g_ncnt[ei[idx]], 1);
    }
  } else if (bid < SETUP_BLKS + WPREP_BLKS){
    int idx = (bid - SETUP_BLKS) * 256 + tid;
    const int NL = 4 * 3 * 16384;
    if (idx < NL){
      int rl = idx / 16384, rem = idx & 16383;
      int n = rem >> 7, k = rem & 127;
      g_Wh[idx] = __float2half_rn(W[((size_t)(rl * 128 + n)) * 128 + k]);
    } else if (idx < 2 * NL){
      int t2 = idx - NL;
      int rc = t2 / 16384, rem = t2 & 16383;
      int r = rc / 3, c = rc % 3;
      int n = rem >> 7, k = rem & 127;
      g_W0h[t2] = __float2half_rn(W0[((size_t)(r * 128 + n)) * 397 + c * 128 + k]);
    } else {
      int t2 = idx - 2 * NL;
      int r = t2 / 2048, rem = t2 & 2047;
      int n = rem >> 4, k = rem & 15;
      int ko = 384 + k;
      float v = (ko < 397) ? W0[((size_t)(r * 128 + n)) * 397 + ko] : 0.f;
      g_W0gh[t2] = __float2half_rn(v);
    }
  } else if (bid < SETUP_BLKS + WPREP_BLKS + NF16_BLKS){
    int idx = (bid - SETUP_BLKS - WPREP_BLKS) * 256 + tid;
    size_t base = (size_t)idx * 8;
    float4 v0 = *(const float4*)&nf[base];
    float4 v1 = *(const float4*)&nf[base + 4];
    __half2 a = __floats2half2_rn(v0.x, v0.y);
    __half2 b = __floats2half2_rn(v0.z, v0.w);
    __half2 c = __floats2half2_rn(v1.x, v1.y);
    __half2 d = __floats2half2_rn(v1.z, v1.w);
    uint4 o; o.x = *(u32*)&a; o.y = *(u32*)&b; o.z = *(u32*)&c; o.w = *(u32*)&d;
    *(uint4*)&g_nf16[base] = o;
  } else {
    int e = (bid - SETUP_BLKS - WPREP_BLKS - NF16_BLKS) * 256 + tid;
    const float* gp = geo + (size_t)e * GEO_;
    __half h[16];
    #pragma unroll
    for (int c = 0; c < 16; c++) h[c] = (c < GEO_) ? __float2half_rn(gp[c]) : __float2half_rn(0.f);
    uint4* dst = (uint4*)&g_geo16[(size_t)e * 16];
    dst[0] = *(uint4*)&h[0];
    dst[1] = *(uint4*)&h[8];
  }
}

// ---------------- L2: route offsets + node prefix sum ----------------
__global__ void k_offsets2(){
  __shared__ int part[1024];
  int t = threadIdx.x;
  if (t == 0){
    int b = 0;
    #pragma unroll
    for (int r = 0; r < 4; r++){
      g_bnd[r] = b;
      int c = g_cnt[r];
      b += ((c + 127) / 128) * 128;
      g_cntf[r] = (c > 0) ? (float)c : 1.0f;
    }
    g_bnd[4] = b;
  }
  int base = t * 32;
  int loc[32], s = 0;
  #pragma unroll
  for (int j = 0; j < 32; j++){ loc[j] = s; s += g_ncnt[base + j]; }
  part[t] = s;
  __syncthreads();
  for (int off = 1; off < 1024; off <<= 1){
    int v = (t >= off) ? part[t - off] : 0;
    __syncthreads();
    part[t] += v;
    __syncthreads();
  }
  int excl = part[t] - s;
  #pragma unroll
  for (int j = 0; j < 32; j++) g_noff[base + j] = excl + loc[j];
}

// ---------------- L3: permutation + packed node buckets ----------------
__global__ void k_permprep(const int* __restrict__ ei){
  int e = blockIdx.x * 256 + threadIdx.x;
  int r = g_route[e];
  int lane = threadIdx.x & 31;
  int pos = 0;
  #pragma unroll
  for (int rr = 0; rr < 4; rr++){
    unsigned m = __ballot_sync(0xFFFFFFFFu, r == rr);
    if (r == rr){
      int leader = __ffs(m) - 1;
      int base = 0;
      if (lane == leader) base = atomicAdd(&g_cur[rr], __popc(m));
      base = __shfl_sync(m, base, leader);
      unsigned lt = (lane == 0) ? 0u : (0xFFFFFFFFu >> (32 - lane));
      pos = g_bnd[rr] + base + __popc(m & lt);
      g_perm[pos] = e;
    }
  }
  int i = ei[e];
  int slot = g_noff[i] + atomicAdd(&g_ncur[i], 1);
  g_nbkt[slot] = (u32)pos | ((u32)r << 20);
}

// ---------------- fragment loads ----------------
template<int AS>
__device__ __forceinline__ void loadA(u32 abase, int mw, int lane, int k0, u32 a[2][4]){
  #pragma unroll
  for (int im = 0; im < 2; im++){
    int row = mw + im * 16 + (lane & 15);
    int col = k0 + ((lane >> 4) << 3);
    ldm4(a[im][0], a[im][1], a[im][2], a[im][3], abase + (u32)(row * AS + col) * 2);
  }
}
template<int BS>
__device__ __forceinline__ void loadB32(u32 bbase, int nw, int lane, int k0, u32 b[4][2]){
  int brow = nw + ((lane >> 4) << 3) + (lane & 7);
  int bcol = k0 + (((lane >> 3) & 1) << 3);
  #pragma unroll
  for (int g = 0; g < 2; g++){
    ldm4(b[2*g][0], b[2*g][1], b[2*g+1][0], b[2*g+1][1],
         bbase + (u32)((brow + g * 16) * BS + bcol) * 2);
  }
}
template<int BS>
__device__ __forceinline__ void loadB16(u32 bbase, int nw, int lane, int k0, u32 b[4]){
  int brow = nw + ((lane >> 4) << 3) + (lane & 7);
  int bcol = k0 + (((lane >> 3) & 1) << 3);
  ldm4(b[0], b[1], b[2], b[3], bbase + (u32)(brow * BS + bcol) * 2);
}

// layer mainloop (warp tile 32x32, A dbuf)
template<int NK>
__device__ __forceinline__ void mma_chunk4(u32 abase, u32 bbase, int mw, int nw, int lane,
                                           float acc[2][4][4]){
  u32 a[2][2][4];
  loadA<SA>(abase, mw, lane, 0, a[0]);
  #pragma unroll
  for (int ks = 0; ks < NK; ks++){
    int cur = ks & 1;
    u32 b[4][2];
    loadB32<SA>(bbase, nw, lane, ks * 16, b);
    if (ks + 1 < NK) loadA<SA>(abase, mw, lane, (ks + 1) * 16, a[cur ^ 1]);
    #pragma unroll
    for (int im = 0; im < 2; im++)
      #pragma unroll
      for (int in = 0; in < 4; in++)
        mma16816(acc[im][in], a[cur][im], b[in][0], b[in][1]);
  }
}
// gemm0 mainloop (warp tile 32x16, A+B dbuf)
template<int NK, int AS, int BS>
__device__ __forceinline__ void mma_chunk2(u32 abase, u32 bbase, int mw, int nw, int lane,
                                           float acc[2][2][4]){
  u32 a[2][2][4], b[2][4];
  loadA<AS>(abase, mw, lane, 0, a[0]);
  loadB16<BS>(bbase, nw, lane, 0, b[0]);
  #pragma unroll
  for (int ks = 0; ks < NK; ks++){
    int cur = ks & 1;
    if (ks + 1 < NK){
      loadA<AS>(abase, mw, lane, (ks + 1) * 16, a[cur ^ 1]);
      loadB16<BS>(bbase, nw, lane, (ks + 1) * 16, b[cur ^ 1]);
    }
    mma16816(acc[0][0], a[cur][0], b[cur][0], b[cur][1]);
    mma16816(acc[1][0], a[cur][1], b[cur][0], b[cur][1]);
    mma16816(acc[0][1], a[cur][0], b[cur][2], b[cur][3]);
    mma16816(acc[1][1], a[cur][1], b[cur][2], b[cur][3]);
  }
}

// ---------------- epilogue (templated on N-fragments per warp) ----------------
template<int IN>
__device__ __forceinline__ void epilogue_mma(float acc[2][IN][4], const float* __restrict__ biasp,
                                             __half* __restrict__ hout,
                                             int m0, int mw, int nw, int lane,
                                             int r, int layer, int nval){
  int gid = lane >> 2, tig = lane & 3;
  float sum[IN][2], sq[IN][2];
  #pragma unroll
  for (int in = 0; in < IN; in++){ sum[in][0] = sum[in][1] = sq[in][0] = sq[in][1] = 0.f; }
  #pragma unroll
  for (int im = 0; im < 2; im++){
    int lr0 = mw + im * 16 + gid;
    bool v0 = lr0 < nval, v1 = (lr0 + 8) < nval;
    #pragma unroll
    for (int in = 0; in < IN; in++){
      float* d = acc[im][in];
      int col = nw + in * 8 + tig * 2;
      float2 bv = *(const float2*)&biasp[col];
      float e0 = d[0] + bv.x, e1 = d[1] + bv.y, e2 = d[2] + bv.x, e3 = d[3] + bv.y;
      __half2 p01 = __floats2half2_rn(e0, e1);
      __half2 p23 = __floats2half2_rn(e2, e3);
      *(u32*)&hout[(size_t)(m0 + lr0) * HID + col]     = *(u32*)&p01;
      *(u32*)&hout[(size_t)(m0 + lr0 + 8) * HID + col] = *(u32*)&p23;
      float m0v = v0 ? e0 : 0.f, m1v = v0 ? e1 : 0.f;
      float m2v = v1 ? e2 : 0.f, m3v = v1 ? e3 : 0.f;
      sum[in][0] += m0v + m2v; sum[in][1] += m1v + m3v;
      sq[in][0]  += m0v * m0v + m2v * m2v;
      sq[in][1]  += m1v * m1v + m3v * m3v;
    }
  }
  #pragma unroll
  for (int off = 4; off <= 16; off <<= 1){
    #pragma unroll
    for (int in = 0; in < IN; in++){
      sum[in][0] += __shfl_xor_sync(0xFFFFFFFFu, sum[in][0], off);
      sum[in][1] += __shfl_xor_sync(0xFFFFFFFFu, sum[in][1], off);
      sq[in][0]  += __shfl_xor_sync(0xFFFFFFFFu, sq[in][0], off);
      sq[in][1]  += __shfl_xor_sync(0xFFFFFFFFu, sq[in][1], off);
    }
  }
  if (gid == 0){
    #pragma unroll
    for (int in = 0; in < IN; in++){
      int col = nw + in * 8 + tig * 2;
      atomicAdd(&g_stats[layer][r][col][0], sum[in][0]);
      atomicAdd(&g_stats[layer][r][col][1], sq[in][0]);
      atomicAdd(&g_stats[layer][r][col + 1][0], sum[in][1]);
      atomicAdd(&g_stats[layer][r][col + 1][1], sq[in][1]);
    }
  }
}

// ---------------- gemm0 prefetchers (512 threads) ----------------
__device__ __forceinline__ void g0_loadB(u32 sb, int r, int tid){
  #pragma unroll
  for (int c = 0; c < 3; c++){
    const __half* w = g_W0h + (r * 3 + c) * 16384;
    #pragma unroll
    for (int j = 0; j < 4; j++){
      int i = j * 512 + tid;
      int row = i >> 4, seg = i & 15;
      CP_ASYNC16(sb + G0_OFF_B + c * B_CH + (u32)(row * SA + seg * 8) * 2, w + row * 128 + seg * 8);
    }
  }
  if (tid < 256){
    int row = tid >> 1, seg = tid & 1;
    CP_ASYNC16(sb + G0_OFF_BG + (u32)(row * 16 + seg * 8) * 2,
               g_W0gh + r * 2048 + row * 16 + seg * 8);
  }
}
__device__ __forceinline__ void g0_prefA(u32 abase, const int (*nodes)[64], const int* eids, int tid){
  #pragma unroll
  for (int c = 0; c < 3; c++){
    #pragma unroll
    for (int j = 0; j < 2; j++){
      int i = j * 512 + tid;
      int row = i >> 4, seg = i & 15;
      CP_ASYNC16(abase + c * A_CH + (u32)(row * SA + seg * 8) * 2,
                 g_nf16 + (size_t)nodes[c][row] * 128 + seg * 8);
    }
  }
  if (tid < 128){
    int row = tid >> 1, seg = tid & 1;
    CP_ASYNC16(abase + 3 * A_CH + (u32)(row * 16 + seg * 8) * 2,
               g_geo16 + (size_t)eids[row] * 16 + seg * 8);
  }
}

// ---------------- L4 (PROFILED): GEMM0 — persistent, 512 thr, full dbuf --------
__global__ __launch_bounds__(512, 1)
void k_gemm0(const int* __restrict__ ei, const float* __restrict__ b0){
  extern __shared__ char bp[];
  __shared__ int sN[2][3][64];
  __shared__ int sE2[2][64];
  u32 sb = smem_u32(bp);
  int tid = threadIdx.x, wid = tid >> 5, lane = tid & 31;
  int mw = (wid & 1) * 32, nw = (wid >> 1) * 16;
  int bnd1 = g_bnd[1], bnd2 = g_bnd[2], bnd3 = g_bnd[3], bnd4 = g_bnd[4];
  int ntiles = bnd4 >> 6;
  int G = gridDim.x;
  int t = blockIdx.x;
  if (t >= ntiles) return;

  if (tid < 64){
    int e = g_perm[(t << 6) + tid];
    int ec = (e < 0) ? 0 : e;
    sN[0][0][tid] = (e < 0) ? 0 : ei[ec];
    sN[0][1][tid] = (e < 0) ? 0 : ei[E_ + ec];
    sN[0][2][tid] = (e < 0) ? 0 : ei[2 * E_ + ec];
    sE2[0][tid] = ec;
  }
  __syncthreads();
  int m00 = t << 6;
  int curR = (m00 >= bnd1) + (m00 >= bnd2) + (m00 >= bnd3);
  g0_loadB(sb, curR, tid);
  g0_prefA(sb + G0_OFF_A, sN[0], sE2[0], tid);
  CP_COMMIT();
  if (tid < 64 && t + G < ntiles){
    int e = g_perm[((t + G) << 6) + tid];
    int ec = (e < 0) ? 0 : e;
    sN[1][0][tid] = (e < 0) ? 0 : ei[ec];
    sN[1][1][tid] = (e < 0) ? 0 : ei[E_ + ec];
    sN[1][2][tid] = (e < 0) ? 0 : ei[2 * E_ + ec];
    sE2[1][tid] = ec;
  }

  int st = 0, p = 0;
  for (; t < ntiles; t += G, st ^= 1, p ^= 1){
    int m0 = t << 6;
    int r = curR;
    CP_WAIT0();
    __syncthreads();
    int tn = t + G;
    bool early = false;
    int rn = r;
    if (tn < ntiles){
      int mn = tn << 6;
      rn = (mn >= bnd1) + (mn >= bnd2) + (mn >= bnd3);
      if (rn == r){
        g0_prefA(sb + G0_OFF_A + (st ^ 1) * G0_ASTRIDE, sN[p ^ 1], sE2[p ^ 1], tid);
        CP_COMMIT();
        early = true;
      }
    }
    float acc[2][2][4];
    #pragma unroll
    for (int im = 0; im < 2; im++)
      #pragma unroll
      for (int in = 0; in < 2; in++)
        #pragma unroll
        for (int tt = 0; tt < 4; tt++) acc[im][in][tt] = 0.f;
    u32 abase = sb + G0_OFF_A + st * G0_ASTRIDE;
    #pragma unroll
    for (int c = 0; c < 3; c++)
      mma_chunk2<8, SA, SA>(abase + c * A_CH, sb + G0_OFF_B + c * B_CH, mw, nw, lane, acc);
    mma_chunk2<1, 16, 16>(abase + 3 * A_CH, sb + G0_OFF_BG, mw, nw, lane, acc);

    int nv = g_bnd[r] + g_cnt[r] - m0;
    nv = (nv < 0) ? 0 : ((nv > 64) ? 64 : nv);
    epilogue_mma<2>(acc, b0 + r * HID, g_hA16, m0, mw, nw, lane, r, 0, nv);

    if (tid < 64 && t + 2 * G < ntiles){
      int e = g_perm[((t + 2 * G) << 6) + tid];
      int ec = (e < 0) ? 0 : e;
      sN[p][0][tid] = (e < 0) ? 0 : ei[ec];
      sN[p][1][tid] = (e < 0) ? 0 : ei[E_ + ec];
      sN[p][2][tid] = (e < 0) ? 0 : ei[2 * E_ + ec];
      sE2[p][tid] = ec;
    }
    if (!early && tn < ntiles){
      __syncthreads();
      curR = rn;
      g0_loadB(sb, curR, tid);
      g0_prefA(sb + G0_OFF_A + (st ^ 1) * G0_ASTRIDE, sN[p ^ 1], sE2[p ^ 1], tid);
      CP_COMMIT();
    }
  }
}

// ---------------- layers 1..3: persistent, B-resident, occ 3 ----------------
template<int LI>
__global__ __launch_bounds__(256, 3)
void k_gemml(const float* __restrict__ bArr,
             const float* __restrict__ gamma, const float* __restrict__ beta){
  const __half* hin  = (LI & 1) ? g_hA16 : g_hB16;
  __half*       hout = (LI & 1) ? g_hB16 : g_hA16;
  extern __shared__ char bp[];
  __shared__ float2 sST[4][128];
  u32 sb = smem_u32(bp);
  int tid = threadIdx.x, wid = tid >> 5, lane = tid & 31;
  int mw = (wid & 1) * 32, nw = (wid >> 1) * 32;
  int c4 = (tid & 31) << 2;
  int bnd1 = g_bnd[1], bnd2 = g_bnd[2], bnd3 = g_bnd[3], bnd4 = g_bnd[4];
  int ntiles = bnd4 >> 6;
  int G = gridDim.x;
  const __half* wb = g_Wh + (LI - 1) * 16384;

  #pragma unroll
  for (int it = tid; it < 512; it += 256){
    int r = it >> 7, c = it & 127;
    float cnt  = g_cntf[r];
    float mean = g_stats[LI - 1][r][c][0] / cnt;
    float var  = fmaxf(g_stats[LI - 1][r][c][1] / cnt - mean * mean, 0.f);
    float inv  = rsqrtf(var + 1e-5f);
    float s    = gamma[(r * 4 + LI - 1) * HID + c] * inv;
    sST[r][c] = make_float2(s, beta[(r * 4 + LI - 1) * HID + c] - mean * s);
  }

  int t = blockIdx.x;
  if (t >= ntiles) return;
  int m00 = t << 6;
  int curR = (m00 >= bnd1) + (m00 >= bnd2) + (m00 >= bnd3);
  {
    #pragma unroll
    for (int j = 0; j < 8; j++){
      int i = j * 256 + tid;
      int row = i >> 4, seg = i & 15;
      CP_ASYNC16(sb + L_OFF_B + (u32)(row * SA + seg * 8) * 2,
                 wb + curR * 3 * 16384 + row * 128 + seg * 8);
    }
    #pragma unroll
    for (int j = 0; j < 4; j++){
      int i = j * 256 + tid;
      int row = i >> 4, seg = i & 15;
      CP_ASYNC16(sb + L_OFF_A + (u32)(row * SA + seg * 8) * 2,
                 hin + (size_t)m00 * HID + (size_t)row * 128 + seg * 8);
    }
    CP_COMMIT();
  }

  int st = 0;
  for (; t < ntiles; t += G, st ^= 1){
    int m0 = t << 6;
    int r = curR;
    CP_WAIT0();
    __syncthreads();
    int tn = t + G;
    bool early = false;
    int rn = r;
    if (tn < ntiles){
      int mn = tn << 6;
      rn = (mn >= bnd1) + (mn >= bnd2) + (mn >= bnd3);
      if (rn == r){
        #pragma unroll
        for (int j = 0; j < 4; j++){
          int i = j * 256 + tid;
          int row = i >> 4, seg = i & 15;
          CP_ASYNC16(sb + L_OFF_A + (st ^ 1) * A_CH + (u32)(row * SA + seg * 8) * 2,
                     hin + (size_t)mn * HID + (size_t)row * 128 + seg * 8);
        }
        CP_COMMIT();
        early = true;
      }
    }
    char* abase = bp + L_OFF_A + st * A_CH;
    #pragma unroll
    for (int j = 0; j < 8; j++){
      int row = j * 8 + (tid >> 5);
      char* ap = abase + (u32)(row * SA + c4) * 2;
      uint2 hv = *(uint2*)ap;
      float2 f01 = __half22float2(*(__half2*)&hv.x);
      float2 f23 = __half22float2(*(__half2*)&hv.y);
      float2 s0 = *(float2*)&sST[r][c4];
      float2 s1 = *(float2*)&sST[r][c4 + 1];
      float2 s2 = *(float2*)&sST[r][c4 + 2];
      float2 s3 = *(float2*)&sST[r][c4 + 3];
      __half2 a01 = __floats2half2_rn(fmaxf(fmaf(f01.x, s0.x, s0.y), 0.f),
                                      fmaxf(fmaf(f01.y, s1.x, s1.y), 0.f));
      __half2 a23 = __floats2half2_rn(fmaxf(fmaf(f23.x, s2.x, s2.y), 0.f),
                                      fmaxf(fmaf(f23.y, s3.x, s3.y), 0.f));
      *(uint2*)ap = make_uint2(*(u32*)&a01, *(u32*)&a23);
    }
    __syncthreads();

    float acc[2][4][4];
    #pragma unroll
    for (int im = 0; im < 2; im++)
      #pragma unroll
      for (int in = 0; in < 4; in++)
        #pragma unroll
        for (int tt = 0; tt < 4; tt++) acc[im][in][tt] = 0.f;
    mma_chunk4<8>(sb + L_OFF_A + st * A_CH, sb + L_OFF_B, mw, nw, lane, acc);

    int nv = g_bnd[r] + g_cnt[r] - m0;
    nv = (nv < 0) ? 0 : ((nv > 64) ? 64 : nv);
    epilogue_mma<4>(acc, bArr + (r * 3 + (LI - 1)) * HID, hout, m0, mw, nw, lane, r, LI, nv);

    if (!early && tn < ntiles){
      __syncthreads();
      curR = rn;
      int mn = tn << 6;
      #pragma unroll
      for (int j = 0; j < 8; j++){
        int i = j * 256 + tid;
        int row = i >> 4, seg = i & 15;
        CP_ASYNC16(sb + L_OFF_B + (u32)(row * SA + seg * 8) * 2,
                   wb + curR * 3 * 16384 + row * 128 + seg * 8);
      }
      #pragma unroll
      for (int j = 0; j < 4; j++){
        int i = j * 256 + tid;
        int row = i >> 4, seg = i & 15;
        CP_ASYNC16(sb + L_OFF_A + (st ^ 1) * A_CH + (u32)(row * SA + seg * 8) * 2,
                   hin + (size_t)mn * HID + (size_t)row * 128 + seg * 8);
      }
      CP_COMMIT();
    }
  }
}

// ---------------- output: packed buckets, 2-wide MLP ----------------
__global__ void k_out(const float* __restrict__ att, const float* __restrict__ gamma,
                      const float* __restrict__ beta, float* __restrict__ out){
  int n = blockIdx.x, t = threadIdx.x;
  int col = t * 2;
  float s0[4], t0[4], s1[4], t1[4], aw[4];
  #pragma unroll
  for (int r = 0; r < 4; r++){
    float cnt = g_cntf[r];
    float mean0 = g_stats[3][r][col][0] / cnt;
    float var0  = fmaxf(g_stats[3][r][col][1] / cnt - mean0 * mean0, 0.f);
    s0[r] = gamma[(r * 4 + 3) * HID + col] * rsqrtf(var0 + 1e-5f);
    t0[r] = beta[(r * 4 + 3) * HID + col] - mean0 * s0[r];
    float mean1 = g_stats[3][r][col + 1][0] / cnt;
    float var1  = fmaxf(g_stats[3][r][col + 1][1] / cnt - mean1 * mean1, 0.f);
    s1[r] = gamma[(r * 4 + 3) * HID + col + 1] * rsqrtf(var1 + 1e-5f);
    t1[r] = beta[(r * 4 + 3) * HID + col + 1] - mean1 * s1[r];
    aw[r] = att[r];
  }
  int s = g_noff[n], cnt = g_ncnt[n];
  float a0 = 0.f, a1 = 0.f;
  int k = 0;
  for (; k + 1 < cnt; k += 2){
    u32 p0 = g_nbkt[s + k], p1 = g_nbkt[s + k + 1];
    int r0 = p0 >> 20, r1 = p1 >> 20;
    u32 h0 = *(const u32*)&g_hB16[(size_t)(p0 & 0xFFFFF) * HID + col];
    u32 h1 = *(const u32*)&g_hB16[(size_t)(p1 & 0xFFFFF) * HID + col];
    float2 f0 = __half22float2(*(__half2*)&h0);
    float2 f1 = __half22float2(*(__half2*)&h1);
    a0 += fmaxf(fmaf(f0.x, s0[r0], t0[r0]), 0.f) * aw[r0];
    a1 += fmaxf(fmaf(f0.y, s1[r0], t1[r0]), 0.f) * aw[r0];
    a0 += fmaxf(fmaf(f1.x, s0[r1], t0[r1]), 0.f) * aw[r1];
    a1 += fmaxf(fmaf(f1.y, s1[r1], t1[r1]), 0.f) * aw[r1];
  }
  if (k < cnt){
    u32 p0 = g_nbkt[s + k];
    int r0 = p0 >> 20;
    u32 h0 = *(const u32*)&g_hB16[(size_t)(p0 & 0xFFFFF) * HID + col];
    float2 f0 = __half22float2(*(__half2*)&h0);
    a0 += fmaxf(fmaf(f0.x, s0[r0], t0[r0]), 0.f) * aw[r0];
    a1 += fmaxf(fmaf(f0.y, s1[r0], t1[r0]), 0.f) * aw[r0];
  }
  *(float2*)&out[(size_t)n * HID + col] = make_float2(a0, a1);
}

// ---------------- launch ----------------
extern "C" void kernel_launch(void* const* d_in, const int* in_sizes, int n_in,
                              void* d_out, int out_size){
  const float* nf    = (const float*)d_in[0];
  const float* geo   = (const float*)d_in[1];
  const int*   ei    = (const int*)d_in[2];
  const int*   eij   = (const int*)d_in[3];
  const int*   ejk   = (const int*)d_in[4];
  const int*   nei   = (const int*)d_in[5];
  const float* att   = (const float*)d_in[6];
  const float* W0    = (const float*)d_in[7];
  const float* b0    = (const float*)d_in[8];
  const float* W     = (const float*)d_in[9];
  const float* b     = (const float*)d_in[10];
  const float* gamma = (const float*)d_in[11];
  const float* beta  = (const float*)d_in[12];
  float* out = (float*)d_out;

  cudaFuncSetAttribute(k_gemm0,    cudaFuncAttributeMaxDynamicSharedMemorySize, G0_SMEM);
  cudaFuncSetAttribute(k_gemml<1>, cudaFuncAttributeMaxDynamicSharedMemorySize, L_SMEM);
  cudaFuncSetAttribute(k_gemml<2>, cudaFuncAttributeMaxDynamicSharedMemorySize, L_SMEM);
  cudaFuncSetAttribute(k_gemml<3>, cudaFuncAttributeMaxDynamicSharedMemorySize, L_SMEM);

  k_setup<<<SETUP_GRID, 256>>>(eij, ejk, nei, ei, W0, W, nf, geo);  // L1
  k_offsets2<<<1, 1024>>>();                                         // L2
  k_permprep<<<E_ / 256, 256>>>(ei);                                 // L3
  k_gemm0<<<G0GRID, 512, G0_SMEM>>>(ei, b0);                         // L4 <- ncu window
  k_gemml<1><<<LGRID, 256, L_SMEM>>>(b, gamma, beta);                // L5
  k_gemml<2><<<LGRID, 256, L_SMEM>>>(b, gamma, beta);                // L6
  k_gemml<3><<<LGRID, 256, L_SMEM>>>(b, gamma, beta);                // L7
  k_out<<<N_, 64>>>(att, gamma, beta, out);                          // L8
}

// round 15
// speedup vs baseline: 1.7874x; 1.4231x over previous
#include <cuda_runtime.h>
#include <cuda_fp16.h>

#define HID 128
#define E_ 262144
#define N_ 32768
#define GEO_ 13
#define ROWS_MAX (E_ + 512)
#define SETUP_BLKS 1026
#define WPREP_BLKS 1568
#define NF16_BLKS 2048
#define GEO16_BLKS 1024
#define SETUP_GRID (SETUP_BLKS + WPREP_BLKS + NF16_BLKS + GEO16_BLKS)
#define G0GRID 148
#define LGRID 296

typedef unsigned long long u64;
typedef unsigned int u32;

#define SA 136
#define A_CH 34816                  // 128 x SA fp16
#define B_CH 34816
#define G0_OFF_B 0
#define G0_OFF_BG (3 * B_CH)
#define G0_OFF_A (G0_OFF_BG + 4096)
#define G0_SMEM (G0_OFF_A + 2 * A_CH)  // 178176
#define L_OFF_B 0
#define L_OFF_A B_CH
#define L_SMEM (B_CH + 2 * A_CH)    // 104448, x2 CTAs

// ---------------- scratch ----------------
__device__ __half g_hA16[(size_t)ROWS_MAX * HID];
__device__ __half g_hB16[(size_t)ROWS_MAX * HID];
__device__ __half g_nf16[(size_t)N_ * HID];
__device__ __half g_geo16[(size_t)E_ * 16];
__device__ __half g_Wh[4 * 3 * 16384];
__device__ __half g_W0h[4 * 3 * 16384];
__device__ __half g_W0gh[4 * 2048];
__device__ int   g_perm[ROWS_MAX];
__device__ int   g_route[E_];
__device__ int   g_cnt[4];
__device__ int   g_cur[4];
__device__ int   g_bnd[5];
__device__ float g_cntf[4];
__device__ float g_stats[4][4][HID][2];
__device__ int   g_ncnt[N_];
__device__ int   g_ncur[N_];
__device__ int   g_noff[N_];
__device__ u32   g_nbkt[E_];

// ---------------- helpers ----------------
__device__ __forceinline__ u32 smem_u32(const void* p){
  u32 a; asm("{ .reg .u64 t; cvta.to.shared.u64 t, %1; cvt.u32.u64 %0, t; }" : "=r"(a) : "l"(p));
  return a;
}
#define CP_ASYNC16(dst, src) asm volatile("cp.async.ca.shared.global [%0], [%1], 16;" :: "r"(dst), "l"(src))
#define CP_COMMIT() asm volatile("cp.async.commit_group;" ::: "memory")
#define CP_WAIT0() asm volatile("cp.async.wait_group 0;" ::: "memory")

__device__ __forceinline__ void ldm4(u32& r0, u32& r1, u32& r2, u32& r3, u32 addr){
  asm volatile("ldmatrix.sync.aligned.m8n8.x4.shared.b16 {%0,%1,%2,%3}, [%4];"
               : "=r"(r0), "=r"(r1), "=r"(r2), "=r"(r3) : "r"(addr));
}
__device__ __forceinline__ void mma16816(float* d, const u32* a, u32 b0, u32 b1){
  asm volatile("mma.sync.aligned.m16n8k16.row.col.f32.f16.f16.f32 "
               "{%0,%1,%2,%3}, {%4,%5,%6,%7}, {%8,%9}, {%0,%1,%2,%3};"
               : "+f"(d[0]), "+f"(d[1]), "+f"(d[2]), "+f"(d[3])
               : "r"(a[0]), "r"(a[1]), "r"(a[2]), "r"(a[3]), "r"(b0), "r"(b1));
}

// ---------------- L1: setup + weight prep + fp16 conversions ----------------
__global__ void k_setup(const int* __restrict__ eij, const int* __restrict__ ejk,
                        const int* __restrict__ nei_ptr, const int* __restrict__ ei,
                        const float* __restrict__ W0, const float* __restrict__ W,
                        const float* __restrict__ nf, const float* __restrict__ geo){
  int bid = blockIdx.x, tid = threadIdx.x;
  if (bid < SETUP_BLKS){
    int idx = bid * 256 + tid;
    if (idx < ROWS_MAX) g_perm[idx] = -1;
    if (idx < 4096) ((float*)g_stats)[idx] = 0.f;
    if (idx < 4){ g_cnt[idx] = 0; g_cur[idx] = 0; }
    if (idx < N_){ g_ncnt[idx] = 0; g_ncur[idx] = 0; }
    if (idx < E_){
      int nei = nei_ptr[0];
      int r = ((eij[idx] < nei) ? 0 : 2) | ((ejk[idx] < nei) ? 0 : 1);
      g_route[idx] = r;
      int lane = tid & 31;
      #pragma unroll
      for (int rr = 0; rr < 4; rr++){
        unsigned m = __ballot_sync(0xFFFFFFFFu, r == rr);
        if (r == rr && lane == (__ffs(m) - 1)) atomicAdd(&g_cnt[rr], __popc(m));
      }
      atomicAdd(&g_ncnt[ei[idx]], 1);
    }
  } else if (bid < SETUP_BLKS + WPREP_BLKS){
    int idx = (bid - SETUP_BLKS) * 256 + tid;
    const int NL = 4 * 3 * 16384;
    if (idx < NL){
      int rl = idx / 16384, rem = idx & 16383;
      int n = rem >> 7, k = rem & 127;
      g_Wh[idx] = __float2half_rn(W[((size_t)(rl * 128 + n)) * 128 + k]);
    } else if (idx < 2 * NL){
      int t2 = idx - NL;
      int rc = t2 / 16384, rem = t2 & 16383;
      int r = rc / 3, c = rc % 3;
      int n = rem >> 7, k = rem & 127;
      g_W0h[t2] = __float2half_rn(W0[((size_t)(r * 128 + n)) * 397 + c * 128 + k]);
    } else {
      int t2 = idx - 2 * NL;
      int r = t2 / 2048, rem = t2 & 2047;
      int n = rem >> 4, k = rem & 15;
      int ko = 384 + k;
      float v = (ko < 397) ? W0[((size_t)(r * 128 + n)) * 397 + ko] : 0.f;
      g_W0gh[t2] = __float2half_rn(v);
    }
  } else if (bid < SETUP_BLKS + WPREP_BLKS + NF16_BLKS){
    int idx = (bid - SETUP_BLKS - WPREP_BLKS) * 256 + tid;
    size_t base = (size_t)idx * 8;
    float4 v0 = *(const float4*)&nf[base];
    float4 v1 = *(const float4*)&nf[base + 4];
    __half2 a = __floats2half2_rn(v0.x, v0.y);
    __half2 b = __floats2half2_rn(v0.z, v0.w);
    __half2 c = __floats2half2_rn(v1.x, v1.y);
    __half2 d = __floats2half2_rn(v1.z, v1.w);
    uint4 o; o.x = *(u32*)&a; o.y = *(u32*)&b; o.z = *(u32*)&c; o.w = *(u32*)&d;
    *(uint4*)&g_nf16[base] = o;
  } else {
    int e = (bid - SETUP_BLKS - WPREP_BLKS - NF16_BLKS) * 256 + tid;
    const float* gp = geo + (size_t)e * GEO_;
    __half h[16];
    #pragma unroll
    for (int c = 0; c < 16; c++) h[c] = (c < GEO_) ? __float2half_rn(gp[c]) : __float2half_rn(0.f);
    uint4* dst = (uint4*)&g_geo16[(size_t)e * 16];
    dst[0] = *(uint4*)&h[0];
    dst[1] = *(uint4*)&h[8];
  }
}

// ---------------- L2: route offsets + node prefix sum ----------------
__global__ void k_offsets2(){
  __shared__ int part[1024];
  int t = threadIdx.x;
  if (t == 0){
    int b = 0;
    #pragma unroll
    for (int r = 0; r < 4; r++){
      g_bnd[r] = b;
      int c = g_cnt[r];
      b += ((c + 127) / 128) * 128;
      g_cntf[r] = (c > 0) ? (float)c : 1.0f;
    }
    g_bnd[4] = b;
  }
  int base = t * 32;
  int loc[32], s = 0;
  #pragma unroll
  for (int j = 0; j < 32; j++){ loc[j] = s; s += g_ncnt[base + j]; }
  part[t] = s;
  __syncthreads();
  for (int off = 1; off < 1024; off <<= 1){
    int v = (t >= off) ? part[t - off] : 0;
    __syncthreads();
    part[t] += v;
    __syncthreads();
  }
  int excl = part[t] - s;
  #pragma unroll
  for (int j = 0; j < 32; j++) g_noff[base + j] = excl + loc[j];
}

// ---------------- L3: permutation + packed node buckets ----------------
__global__ void k_permprep(const int* __restrict__ ei){
  int e = blockIdx.x * 256 + threadIdx.x;
  int r = g_route[e];
  int lane = threadIdx.x & 31;
  int pos = 0;
  #pragma unroll
  for (int rr = 0; rr < 4; rr++){
    unsigned m = __ballot_sync(0xFFFFFFFFu, r == rr);
    if (r == rr){
      int leader = __ffs(m) - 1;
      int base = 0;
      if (lane == leader) base = atomicAdd(&g_cur[rr], __popc(m));
      base = __shfl_sync(m, base, leader);
      unsigned lt = (lane == 0) ? 0u : (0xFFFFFFFFu >> (32 - lane));
      pos = g_bnd[rr] + base + __popc(m & lt);
      g_perm[pos] = e;
    }
  }
  int i = ei[e];
  int slot = g_noff[i] + atomicAdd(&g_ncur[i], 1);
  g_nbkt[slot] = (u32)pos | ((u32)r << 20);
}

// ---------------- fragment loads / mainloop ----------------
template<int IM, int AS>
__device__ __forceinline__ void loadAx(u32 abase, int mw, int lane, int k0, u32 a[IM][4]){
  #pragma unroll
  for (int im = 0; im < IM; im++){
    int row = mw + im * 16 + (lane & 15);
    int col = k0 + ((lane >> 4) << 3);
    ldm4(a[im][0], a[im][1], a[im][2], a[im][3], abase + (u32)(row * AS + col) * 2);
  }
}
template<int BS>
__device__ __forceinline__ void loadB32(u32 bbase, int nw, int lane, int k0, u32 b[4][2]){
  int brow = nw + ((lane >> 4) << 3) + (lane & 7);
  int bcol = k0 + (((lane >> 3) & 1) << 3);
  #pragma unroll
  for (int g = 0; g < 2; g++){
    ldm4(b[2*g][0], b[2*g][1], b[2*g+1][0], b[2*g+1][1],
         bbase + (u32)((brow + g * 16) * BS + bcol) * 2);
  }
}
template<int NK, int IM, int AS, int BS>
__device__ __forceinline__ void mma_loop(u32 abase, u32 bbase, int mw, int nw, int lane,
                                         float acc[IM][4][4]){
  u32 a[2][IM][4];
  loadAx<IM, AS>(abase, mw, lane, 0, a[0]);
  #pragma unroll
  for (int ks = 0; ks < NK; ks++){
    int cur = ks & 1;
    u32 b[4][2];
    loadB32<BS>(bbase, nw, lane, ks * 16, b);
    if (ks + 1 < NK) loadAx<IM, AS>(abase, mw, lane, (ks + 1) * 16, a[cur ^ 1]);
    #pragma unroll
    for (int im = 0; im < IM; im++)
      #pragma unroll
      for (int in = 0; in < 4; in++)
        mma16816(acc[im][in], a[cur][im], b[in][0], b[in][1]);
  }
}

// ---------------- epilogue ----------------
template<int IM>
__device__ __forceinline__ void epilogue_mma(float acc[IM][4][4], const float* __restrict__ biasp,
                                             __half* __restrict__ hout,
                                             int m0, int mw, int nw, int lane,
                                             int r, int layer, int nval){
  int gid = lane >> 2, tig = lane & 3;
  float sum[4][2], sq[4][2];
  #pragma unroll
  for (int in = 0; in < 4; in++){ sum[in][0] = sum[in][1] = sq[in][0] = sq[in][1] = 0.f; }
  #pragma unroll
  for (int im = 0; im < IM; im++){
    int lr0 = mw + im * 16 + gid;
    bool v0 = lr0 < nval, v1 = (lr0 + 8) < nval;
    #pragma unroll
    for (int in = 0; in < 4; in++){
      float* d = acc[im][in];
      int col = nw + in * 8 + tig * 2;
      float2 bv = *(const float2*)&biasp[col];
      float e0 = d[0] + bv.x, e1 = d[1] + bv.y, e2 = d[2] + bv.x, e3 = d[3] + bv.y;
      __half2 p01 = __floats2half2_rn(e0, e1);
      __half2 p23 = __floats2half2_rn(e2, e3);
      *(u32*)&hout[(size_t)(m0 + lr0) * HID + col]     = *(u32*)&p01;
      *(u32*)&hout[(size_t)(m0 + lr0 + 8) * HID + col] = *(u32*)&p23;
      float m0v = v0 ? e0 : 0.f, m1v = v0 ? e1 : 0.f;
      float m2v = v1 ? e2 : 0.f, m3v = v1 ? e3 : 0.f;
      sum[in][0] += m0v + m2v; sum[in][1] += m1v + m3v;
      sq[in][0]  += m0v * m0v + m2v * m2v;
      sq[in][1]  += m1v * m1v + m3v * m3v;
    }
  }
  #pragma unroll
  for (int off = 4; off <= 16; off <<= 1){
    #pragma unroll
    for (int in = 0; in < 4; in++){
      sum[in][0] += __shfl_xor_sync(0xFFFFFFFFu, sum[in][0], off);
      sum[in][1] += __shfl_xor_sync(0xFFFFFFFFu, sum[in][1], off);
      sq[in][0]  += __shfl_xor_sync(0xFFFFFFFFu, sq[in][0], off);
      sq[in][1]  += __shfl_xor_sync(0xFFFFFFFFu, sq[in][1], off);
    }
  }
  if (gid == 0){
    #pragma unroll
    for (int in = 0; in < 4; in++){
      int col = nw + in * 8 + tig * 2;
      atomicAdd(&g_stats[layer][r][col][0], sum[in][0]);
      atomicAdd(&g_stats[layer][r][col][1], sq[in][0]);
      atomicAdd(&g_stats[layer][r][col + 1][0], sum[in][1]);
      atomicAdd(&g_stats[layer][r][col + 1][1], sq[in][1]);
    }
  }
}

// ---------------- gemm0 prefetchers (512 threads, 128-row tiles) ----------------
__device__ __forceinline__ void g0_loadB(u32 sb, int r, int tid){
  #pragma unroll
  for (int c = 0; c < 3; c++){
    const __half* w = g_W0h + (r * 3 + c) * 16384;
    #pragma unroll
    for (int j = 0; j < 4; j++){
      int i = j * 512 + tid;
      int row = i >> 4, seg = i & 15;
      CP_ASYNC16(sb + G0_OFF_B + c * B_CH + (u32)(row * SA + seg * 8) * 2, w + row * 128 + seg * 8);
    }
  }
}
__device__ __forceinline__ void g0_loadBG(u32 sb, int r, int tid){
  if (tid < 256){
    int row = tid >> 1, seg = tid & 1;
    CP_ASYNC16(sb + G0_OFF_BG + (u32)(row * 16 + seg * 8) * 2,
               g_W0gh + r * 2048 + row * 16 + seg * 8);
  }
}
__device__ __forceinline__ void g0_prefA(u32 abase, const int* nodes, int tid){
  #pragma unroll
  for (int j = 0; j < 4; j++){
    int i = j * 512 + tid;
    int row = i >> 4, seg = i & 15;
    CP_ASYNC16(abase + (u32)(row * SA + seg * 8) * 2,
               g_nf16 + (size_t)nodes[row] * 128 + seg * 8);
  }
}
__device__ __forceinline__ void g0_prefG(u32 abase, const int* eids, int tid){
  if (tid < 256){
    int row = tid >> 1, seg = tid & 1;
    CP_ASYNC16(abase + (u32)(row * 16 + seg * 8) * 2,
               g_geo16 + (size_t)eids[row] * 16 + seg * 8);
  }
}

// ---------------- L4 (PROFILED): GEMM0 — 128-row tiles, chunk pipeline ----------
__global__ __launch_bounds__(512, 1)
void k_gemm0(const int* __restrict__ ei, const float* __restrict__ b0){
  extern __shared__ char bp[];
  __shared__ int sN[2][3][128];
  __shared__ int sE2[2][128];
  u32 sb = smem_u32(bp);
  int tid = threadIdx.x, wid = tid >> 5, lane = tid & 31;
  int mw = (wid & 3) * 32, nw = (wid >> 2) * 32;
  int bnd1 = g_bnd[1], bnd2 = g_bnd[2], bnd3 = g_bnd[3], bnd4 = g_bnd[4];
  int ntiles = bnd4 >> 7;
  int G = gridDim.x;
  int t = blockIdx.x;
  if (t >= ntiles) return;

  if (tid < 128){
    int e = g_perm[(t << 7) + tid];
    int ec = (e < 0) ? 0 : e;
    sN[0][0][tid] = ei[ec];
    sN[0][1][tid] = ei[E_ + ec];
    sN[0][2][tid] = ei[2 * E_ + ec];
    sE2[0][tid] = ec;
  }
  __syncthreads();
  int m00 = t << 7;
  int curR = (m00 >= bnd1) + (m00 >= bnd2) + (m00 >= bnd3);
  g0_loadB(sb, curR, tid);
  g0_loadBG(sb, curR, tid);
  g0_prefA(sb + G0_OFF_A, sN[0][0], tid);
  CP_COMMIT();
  if (tid < 128 && t + G < ntiles){
    int e = g_perm[((t + G) << 7) + tid];
    int ec = (e < 0) ? 0 : e;
    sN[1][0][tid] = ei[ec];
    sN[1][1][tid] = ei[E_ + ec];
    sN[1][2][tid] = ei[2 * E_ + ec];
    sE2[1][tid] = ec;
  }

  bool bgReload = false;
  int p = 0;
  for (; t < ntiles; t += G, p ^= 1){
    int m0 = t << 7;
    int r = curR;
    int tn = t + G;
    float acc[2][4][4];
    #pragma unroll
    for (int im = 0; im < 2; im++)
      #pragma unroll
      for (int in = 0; in < 4; in++)
        #pragma unroll
        for (int z = 0; z < 4; z++) acc[im][in][z] = 0.f;

    #pragma unroll
    for (int c = 0; c < 4; c++){
      CP_WAIT0();
      __syncthreads();
      u32 nst = sb + G0_OFF_A + (u32)(((c + 1) & 1) * A_CH);
      if (c == 0){
        if (bgReload){ g0_loadBG(sb, r, tid); bgReload = false; }
        g0_prefA(nst, sN[p][1], tid);
      } else if (c == 1){
        g0_prefA(nst, sN[p][2], tid);
      } else if (c == 2){
        g0_prefG(nst, sE2[p], tid);
      } else {
        if (tn < ntiles){
          int mn = tn << 7;
          int rn = (mn >= bnd1) + (mn >= bnd2) + (mn >= bnd3);
          g0_prefA(nst, sN[p ^ 1][0], tid);
          if (rn != r){ g0_loadB(sb, rn, tid); bgReload = true; }
          curR = rn;
        }
      }
      CP_COMMIT();
      u32 abase = sb + G0_OFF_A + (u32)((c & 1) * A_CH);
      if (c < 3) mma_loop<8, 2, SA, SA>(abase, sb + G0_OFF_B + (u32)(c * B_CH), mw, nw, lane, acc);
      else       mma_loop<1, 2, 16, 16>(abase, sb + G0_OFF_BG, mw, nw, lane, acc);
    }

    int nv = g_bnd[r] + g_cnt[r] - m0;
    nv = (nv < 0) ? 0 : ((nv > 128) ? 128 : nv);
    epilogue_mma<2>(acc, b0 + r * HID, g_hA16, m0, mw, nw, lane, r, 0, nv);

    if (tid < 128 && t + 2 * G < ntiles){
      int e = g_perm[((t + 2 * G) << 7) + tid];
      int ec = (e < 0) ? 0 : e;
      sN[p][0][tid] = ei[ec];
      sN[p][1][tid] = ei[E_ + ec];
      sN[p][2][tid] = ei[2 * E_ + ec];
      sE2[p][tid] = ec;
    }
  }
}

// ---------------- layers 1..3: 128-row tiles, persistent, B-resident ----------
template<int LI>
__global__ __launch_bounds__(256, 2)
void k_gemml(const float* __restrict__ bArr,
             const float* __restrict__ gamma, const float* __restrict__ beta){
  const __half* hin  = (LI & 1) ? g_hA16 : g_hB16;
  __half*       hout = (LI & 1) ? g_hB16 : g_hA16;
  extern __shared__ char bp[];
  __shared__ float2 sST[4][128];
  u32 sb = smem_u32(bp);
  int tid = threadIdx.x, wid = tid >> 5, lane = tid & 31;
  int mw = (wid & 1) * 64, nw = (wid >> 1) * 32;
  int c4 = (tid & 31) << 2;
  int bnd1 = g_bnd[1], bnd2 = g_bnd[2], bnd3 = g_bnd[3], bnd4 = g_bnd[4];
  int ntiles = bnd4 >> 7;
  int G = gridDim.x;
  const __half* wb = g_Wh + (LI - 1) * 16384;

  #pragma unroll
  for (int it = tid; it < 512; it += 256){
    int r = it >> 7, c = it & 127;
    float cnt  = g_cntf[r];
    float mean = g_stats[LI - 1][r][c][0] / cnt;
    float var  = fmaxf(g_stats[LI - 1][r][c][1] / cnt - mean * mean, 0.f);
    float inv  = rsqrtf(var + 1e-5f);
    float s    = gamma[(r * 4 + LI - 1) * HID + c] * inv;
    sST[r][c] = make_float2(s, beta[(r * 4 + LI - 1) * HID + c] - mean * s);
  }

  int t = blockIdx.x;
  if (t >= ntiles) return;
  int m00 = t << 7;
  int curR = (m00 >= bnd1) + (m00 >= bnd2) + (m00 >= bnd3);
  {
    #pragma unroll
    for (int j = 0; j < 8; j++){
      int i = j * 256 + tid;
      int row = i >> 4, seg = i & 15;
      CP_ASYNC16(sb + L_OFF_B + (u32)(row * SA + seg * 8) * 2,
                 wb + curR * 3 * 16384 + row * 128 + seg * 8);
    }
    #pragma unroll
    for (int j = 0; j < 8; j++){
      int i = j * 256 + tid;
      int row = i >> 4, seg = i & 15;
      CP_ASYNC16(sb + L_OFF_A + (u32)(row * SA + seg * 8) * 2,
                 hin + (size_t)m00 * HID + (size_t)row * 128 + seg * 8);
    }
    CP_COMMIT();
  }

  int st = 0;
  for (; t < ntiles; t += G, st ^= 1){
    int m0 = t << 7;
    int r = curR;
    CP_WAIT0();
    __syncthreads();
    int tn = t + G;
    bool early = false;
    int rn = r;
    if (tn < ntiles){
      int mn = tn << 7;
      rn = (mn >= bnd1) + (mn >= bnd2) + (mn >= bnd3);
      if (rn == r){
        #pragma unroll
        for (int j = 0; j < 8; j++){
          int i = j * 256 + tid;
          int row = i >> 4, seg = i & 15;
          CP_ASYNC16(sb + L_OFF_A + (st ^ 1) * A_CH + (u32)(row * SA + seg * 8) * 2,
                     hin + (size_t)mn * HID + (size_t)row * 128 + seg * 8);
        }
        CP_COMMIT();
        early = true;
      }
    }
    char* abase = bp + L_OFF_A + st * A_CH;
    #pragma unroll
    for (int j = 0; j < 16; j++){
      int row = j * 8 + (tid >> 5);
      char* ap = abase + (u32)(row * SA + c4) * 2;
      uint2 hv = *(uint2*)ap;
      float2 f01 = __half22float2(*(__half2*)&hv.x);
      float2 f23 = __half22float2(*(__half2*)&hv.y);
      float2 s0 = sST[r][c4];
      float2 s1 = sST[r][c4 + 1];
      float2 s2 = sST[r][c4 + 2];
      float2 s3 = sST[r][c4 + 3];
      __half2 a01 = __floats2half2_rn(fmaxf(fmaf(f01.x, s0.x, s0.y), 0.f),
                                      fmaxf(fmaf(f01.y, s1.x, s1.y), 0.f));
      __half2 a23 = __floats2half2_rn(fmaxf(fmaf(f23.x, s2.x, s2.y), 0.f),
                                      fmaxf(fmaf(f23.y, s3.x, s3.y), 0.f));
      *(uint2*)ap = make_uint2(*(u32*)&a01, *(u32*)&a23);
    }
    __syncthreads();

    float acc[4][4][4];
    #pragma unroll
    for (int im = 0; im < 4; im++)
      #pragma unroll
      for (int in = 0; in < 4; in++)
        #pragma unroll
        for (int z = 0; z < 4; z++) acc[im][in][z] = 0.f;
    mma_loop<8, 4, SA, SA>(sb + L_OFF_A + st * A_CH, sb + L_OFF_B, mw, nw, lane, acc);

    int nv = g_bnd[r] + g_cnt[r] - m0;
    nv = (nv < 0) ? 0 : ((nv > 128) ? 128 : nv);
    epilogue_mma<4>(acc, bArr + (r * 3 + (LI - 1)) * HID, hout, m0, mw, nw, lane, r, LI, nv);

    if (!early && tn < ntiles){
      __syncthreads();
      curR = rn;
      int mn = tn << 7;
      #pragma unroll
      for (int j = 0; j < 8; j++){
        int i = j * 256 + tid;
        int row = i >> 4, seg = i & 15;
        CP_ASYNC16(sb + L_OFF_B + (u32)(row * SA + seg * 8) * 2,
                   wb + curR * 3 * 16384 + row * 128 + seg * 8);
      }
      #pragma unroll
      for (int j = 0; j < 8; j++){
        int i = j * 256 + tid;
        int row = i >> 4, seg = i & 15;
        CP_ASYNC16(sb + L_OFF_A + (st ^ 1) * A_CH + (u32)(row * SA + seg * 8) * 2,
                   hin + (size_t)mn * HID + (size_t)row * 128 + seg * 8);
      }
      CP_COMMIT();
    }
  }
}

// ---------------- output: packed buckets ----------------
__global__ void k_out(const float* __restrict__ att, const float* __restrict__ gamma,
                      const float* __restrict__ beta, float* __restrict__ out){
  int n = blockIdx.x, t = threadIdx.x;
  int col = t * 2;
  float s0[4], t0[4], s1[4], t1[4], aw[4];
  #pragma unroll
  for (int r = 0; r < 4; r++){
    float cnt = g_cntf[r];
    float mean0 = g_stats[3][r][col][0] / cnt;
    float var0  = fmaxf(g_stats[3][r][col][1] / cnt - mean0 * mean0, 0.f);
    s0[r] = gamma[(r * 4 + 3) * HID + col] * rsqrtf(var0 + 1e-5f);
    t0[r] = beta[(r * 4 + 3) * HID + col] - mean0 * s0[r];
    float mean1 = g_stats[3][r][col + 1][0] / cnt;
    float var1  = fmaxf(g_stats[3][r][col + 1][1] / cnt - mean1 * mean1, 0.f);
    s1[r] = gamma[(r * 4 + 3) * HID + col + 1] * rsqrtf(var1 + 1e-5f);
    t1[r] = beta[(r * 4 + 3) * HID + col + 1] - mean1 * s1[r];
    aw[r] = att[r];
  }
  int s = g_noff[n], cnt = g_ncnt[n];
  float a0 = 0.f, a1 = 0.f;
  int k = 0;
  for (; k + 1 < cnt; k += 2){
    u32 p0 = g_nbkt[s + k], p1 = g_nbkt[s + k + 1];
    int r0 = p0 >> 20, r1 = p1 >> 20;
    u32 h0 = *(const u32*)&g_hB16[(size_t)(p0 & 0xFFFFF) * HID + col];
    u32 h1 = *(const u32*)&g_hB16[(size_t)(p1 & 0xFFFFF) * HID + col];
    float2 f0 = __half22float2(*(__half2*)&h0);
    float2 f1 = __half22float2(*(__half2*)&h1);
    a0 += fmaxf(fmaf(f0.x, s0[r0], t0[r0]), 0.f) * aw[r0];
    a1 += fmaxf(fmaf(f0.y, s1[r0], t1[r0]), 0.f) * aw[r0];
    a0 += fmaxf(fmaf(f1.x, s0[r1], t0[r1]), 0.f) * aw[r1];
    a1 += fmaxf(fmaf(f1.y, s1[r1], t1[r1]), 0.f) * aw[r1];
  }
  if (k < cnt){
    u32 p0 = g_nbkt[s + k];
    int r0 = p0 >> 20;
    u32 h0 = *(const u32*)&g_hB16[(size_t)(p0 & 0xFFFFF) * HID + col];
    float2 f0 = __half22float2(*(__half2*)&h0);
    a0 += fmaxf(fmaf(f0.x, s0[r0], t0[r0]), 0.f) * aw[r0];
    a1 += fmaxf(fmaf(f0.y, s1[r0], t1[r0]), 0.f) * aw[r0];
  }
  *(float2*)&out[(size_t)n * HID + col] = make_float2(a0, a1);
}

// ---------------- launch ----------------
extern "C" void kernel_launch(void* const* d_in, const int* in_sizes, int n_in,
                              void* d_out, int out_size){
  const float* nf    = (const float*)d_in[0];
  const float* geo   = (const float*)d_in[1];
  const int*   ei    = (const int*)d_in[2];
  const int*   eij   = (const int*)d_in[3];
  const int*   ejk   = (const int*)d_in[4];
  const int*   nei   = (const int*)d_in[5];
  const float* att   = (const float*)d_in[6];
  const float* W0    = (const float*)d_in[7];
  const float* b0    = (const float*)d_in[8];
  const float* W     = (const float*)d_in[9];
  const float* b     = (const float*)d_in[10];
  const float* gamma = (const float*)d_in[11];
  const float* beta  = (const float*)d_in[12];
  float* out = (float*)d_out;

  cudaFuncSetAttribute(k_gemm0,    cudaFuncAttributeMaxDynamicSharedMemorySize, G0_SMEM);
  cudaFuncSetAttribute(k_gemml<1>, cudaFuncAttributeMaxDynamicSharedMemorySize, L_SMEM);
  cudaFuncSetAttribute(k_gemml<2>, cudaFuncAttributeMaxDynamicSharedMemorySize, L_SMEM);
  cudaFuncSetAttribute(k_gemml<3>, cudaFuncAttributeMaxDynamicSharedMemorySize, L_SMEM);

  k_setup<<<SETUP_GRID, 256>>>(eij, ejk, nei, ei, W0, W, nf, geo);  // L1
  k_offsets2<<<1, 1024>>>();                                         // L2
  k_permprep<<<E_ / 256, 256>>>(ei);                                 // L3
  k_gemm0<<<G0GRID, 512, G0_SMEM>>>(ei, b0);                         // L4 <- ncu window
  k_gemml<1><<<LGRID, 256, L_SMEM>>>(b, gamma, beta);                // L5
  k_gemml<2><<<LGRID, 256, L_SMEM>>>(b, gamma, beta);                // L6
  k_gemml<3><<<LGRID, 256, L_SMEM>>>(b, gamma, beta);                // L7
  k_out<<<N_, 64>>>(att, gamma, beta, out);                          // L8
}